// round 1
// baseline (speedup 1.0000x reference)
#include <cuda_runtime.h>
#include <cuda_bf16.h>
#include <math.h>

// ----------------------------------------------------------------------------
// DiT block: adaLN -> self-attn -> cross-attn -> MLP (GELU tanh)
// B=4, N=1024, D=1024, H=16, HD=64, TD=768, TL=77
// Round 0 baseline: fp32 SGEMM (128x128x8) + flash-style attention.
// ----------------------------------------------------------------------------

#define Bx 4
#define Nx 1024
#define Dx 1024
#define Hx 16
#define HDx 64
#define TDx 768
#define TLx 77
#define ROWS (Bx * Nx)       // 4096
#define CTXROWS (Bx * TLx)   // 308

// scratch (device globals; no runtime allocation allowed)
__device__ float g_mod[Bx * 6 * Dx];        // 24576
__device__ float g_h[ROWS * Dx];            // ln+modulate output (reused 3x)
__device__ float g_qkv[ROWS * 3 * Dx];      // 12.6M
__device__ float g_attn[ROWS * Dx];
__device__ float g_x1[ROWS * Dx];
__device__ float g_x2[ROWS * Dx];
__device__ float g_ctx[CTXROWS * Dx];
__device__ float g_q2[ROWS * Dx];
__device__ float g_k2[CTXROWS * Dx];
__device__ float g_v2[CTXROWS * Dx];
__device__ float g_hidden[ROWS * 4 * Dx];   // 16.8M

// ----------------------------------------------------------------------------
// adaLN modulation: mod = silu(c) @ W_ada + b_ada   ([4,1024]x[1024,6144])
// grid (24, 4), block 256
// ----------------------------------------------------------------------------
__global__ void ada_mod_kernel(const float* __restrict__ c,
                               const float* __restrict__ Wada,
                               const float* __restrict__ bada,
                               float* __restrict__ mod) {
    __shared__ float sc[Dx];
    int b = blockIdx.y;
    for (int i = threadIdx.x; i < Dx; i += 256) {
        float v = c[b * Dx + i];
        sc[i] = v / (1.f + __expf(-v));
    }
    __syncthreads();
    int n = blockIdx.x * 256 + threadIdx.x;
    float acc = 0.f;
    for (int k = 0; k < Dx; k++)
        acc += sc[k] * Wada[(size_t)k * (6 * Dx) + n];
    mod[b * 6 * Dx + n] = acc + bada[n];
}

// ----------------------------------------------------------------------------
// LayerNorm + modulate: out = ln(x) * (1 + scale) + shift
// one block per row (4096 blocks), 256 threads, 4 elems each
// chunk = index of shift chunk in mod (scale = chunk+1)
// ----------------------------------------------------------------------------
__global__ void ln_mod_kernel(const float* __restrict__ x,
                              const float* __restrict__ mod,
                              float* __restrict__ out, int chunk) {
    int row = blockIdx.x;
    int b = row >> 10;
    int tid = threadIdx.x;
    const float* xr = x + (size_t)row * Dx;
    float4 v = *(const float4*)(xr + tid * 4);
    float s = v.x + v.y + v.z + v.w;
    float ss = v.x * v.x + v.y * v.y + v.z * v.z + v.w * v.w;
    #pragma unroll
    for (int off = 16; off; off >>= 1) {
        s  += __shfl_xor_sync(0xffffffffu, s, off);
        ss += __shfl_xor_sync(0xffffffffu, ss, off);
    }
    __shared__ float rs[8], rss[8];
    int wid = tid >> 5, lane = tid & 31;
    if (!lane) { rs[wid] = s; rss[wid] = ss; }
    __syncthreads();
    s = 0.f; ss = 0.f;
    #pragma unroll
    for (int w = 0; w < 8; w++) { s += rs[w]; ss += rss[w]; }
    float mean = s * (1.f / Dx);
    float var = ss * (1.f / Dx) - mean * mean;
    float inv = rsqrtf(var + 1e-6f);
    const float* sh = mod + (size_t)b * 6 * Dx + (size_t)chunk * Dx;
    const float* scl = sh + Dx;
    int d = tid * 4;
    float4 o;
    o.x = (v.x - mean) * inv * (1.f + scl[d + 0]) + sh[d + 0];
    o.y = (v.y - mean) * inv * (1.f + scl[d + 1]) + sh[d + 1];
    o.z = (v.z - mean) * inv * (1.f + scl[d + 2]) + sh[d + 2];
    o.w = (v.w - mean) * inv * (1.f + scl[d + 3]) + sh[d + 3];
    *(float4*)(out + (size_t)row * Dx + d) = o;
}

// ----------------------------------------------------------------------------
// SGEMM: C[M,N] = A[M,K] @ W[K,N] (+bias) (+residual) (+GELU)
// 128x128 tile, BK=8, 256 threads, 8x8 per thread.
// Requires N % 128 == 0, K % 8 == 0. M arbitrary (row-guarded).
// ----------------------------------------------------------------------------
#define ACT_NONE 0
#define ACT_GELU 1

__device__ __forceinline__ float gelu_tanh(float x) {
    float x3 = x * x * x;
    return 0.5f * x * (1.f + tanhf(0.7978845608028654f * (x + 0.044715f * x3)));
}

__global__ __launch_bounds__(256, 2)
void sgemm_kernel(const float* __restrict__ A, const float* __restrict__ W,
                  const float* __restrict__ bias, const float* __restrict__ res,
                  float* __restrict__ C, int M, int N, int K, int act) {
    __shared__ float As[8][128];   // transposed: As[k][m]
    __shared__ float Bs[8][128];
    int tid = threadIdx.x;
    int row0 = blockIdx.y * 128, col0 = blockIdx.x * 128;
    int arow = tid >> 1, ak = (tid & 1) * 4;        // A: 128 rows x 8 k (float4)
    int brow = tid >> 5, bcol = (tid & 31) * 4;     // B: 8 k x 128 cols (float4)
    int tx = tid & 15, ty = tid >> 4;

    float acc[8][8];
    #pragma unroll
    for (int i = 0; i < 8; i++)
        #pragma unroll
        for (int j = 0; j < 8; j++) acc[i][j] = 0.f;

    for (int k0 = 0; k0 < K; k0 += 8) {
        float4 av = make_float4(0.f, 0.f, 0.f, 0.f);
        if (row0 + arow < M)
            av = *(const float4*)(A + (size_t)(row0 + arow) * K + k0 + ak);
        As[ak + 0][arow] = av.x;
        As[ak + 1][arow] = av.y;
        As[ak + 2][arow] = av.z;
        As[ak + 3][arow] = av.w;
        float4 bv = *(const float4*)(W + (size_t)(k0 + brow) * N + col0 + bcol);
        *(float4*)&Bs[brow][bcol] = bv;
        __syncthreads();
        #pragma unroll
        for (int kk = 0; kk < 8; kk++) {
            float4 a0 = *(float4*)&As[kk][ty * 8];
            float4 a1 = *(float4*)&As[kk][ty * 8 + 4];
            float4 b0 = *(float4*)&Bs[kk][tx * 8];
            float4 b1 = *(float4*)&Bs[kk][tx * 8 + 4];
            float a[8] = {a0.x, a0.y, a0.z, a0.w, a1.x, a1.y, a1.z, a1.w};
            float bb[8] = {b0.x, b0.y, b0.z, b0.w, b1.x, b1.y, b1.z, b1.w};
            #pragma unroll
            for (int i = 0; i < 8; i++)
                #pragma unroll
                for (int j = 0; j < 8; j++)
                    acc[i][j] += a[i] * bb[j];
        }
        __syncthreads();
    }

    #pragma unroll
    for (int i = 0; i < 8; i++) {
        int r = row0 + ty * 8 + i;
        if (r >= M) continue;
        #pragma unroll
        for (int j = 0; j < 8; j += 4) {
            int cg = col0 + tx * 8 + j;
            float4 v;
            float* pv = &v.x;
            #pragma unroll
            for (int e = 0; e < 4; e++) {
                float t = acc[i][j + e];
                if (bias) t += bias[cg + e];
                if (act == ACT_GELU) t = gelu_tanh(t);
                if (res) t += res[(size_t)r * N + cg + e];
                pv[e] = t;
            }
            *(float4*)(C + (size_t)r * N + cg) = v;
        }
    }
}

// ----------------------------------------------------------------------------
// Flash-style attention: 64x64 Q/K tiles, online softmax.
// grid (Lq/64, H, B), block 256 (16x16 threads, 4x4 per thread).
// Q/K/V pointers pre-offset to their sections; strides in floats.
// Output layout [B*Lq, D] with head h at cols h*64 (i.e. already merged).
// Dynamic smem: sQ 64*64 + sKV 64*65 + sS 64*64 = 49408 bytes.
// ----------------------------------------------------------------------------
__global__ __launch_bounds__(256, 2)
void attn_kernel(const float* __restrict__ Q, int qStride,
                 const float* __restrict__ K, const float* __restrict__ V,
                 int kStride, float* __restrict__ O, int Lq, int Lk) {
    extern __shared__ float sm[];
    float* sQ  = sm;                 // [64][64]
    float* sKV = sm + 64 * 64;       // [64][65]
    float* sS  = sm + 64 * 64 + 64 * 65; // [64][64]
    int tid = threadIdx.x;
    int tx = tid & 15, ty = tid >> 4;
    int qt = blockIdx.x, h = blockIdx.y, b = blockIdx.z;
    const float scale = 0.125f;  // 1/sqrt(64)

    const float* Qbase = Q + (size_t)(b * Lq + qt * 64) * qStride + h * 64;
    for (int i = tid; i < 64 * 16; i += 256) {
        int r = i >> 4, c4 = (i & 15) * 4;
        float4 v = *(const float4*)(Qbase + (size_t)r * qStride + c4);
        v.x *= scale; v.y *= scale; v.z *= scale; v.w *= scale;
        *(float4*)&sQ[r * 64 + c4] = v;
    }

    float m[4], l[4], o[4][4];
    #pragma unroll
    for (int i = 0; i < 4; i++) {
        m[i] = -1e30f; l[i] = 0.f;
        #pragma unroll
        for (int j = 0; j < 4; j++) o[i][j] = 0.f;
    }

    const float* Kbase = K + (size_t)(b * Lk) * kStride + h * 64;
    const float* Vbase = V + (size_t)(b * Lk) * kStride + h * 64;
    int nkt = (Lk + 63) >> 6;

    for (int kt = 0; kt < nkt; kt++) {
        // load K tile (zero-fill OOB rows)
        for (int i = tid; i < 64 * 16; i += 256) {
            int r = i >> 4, c4 = (i & 15) * 4;
            int jg = kt * 64 + r;
            float4 v = make_float4(0.f, 0.f, 0.f, 0.f);
            if (jg < Lk) v = *(const float4*)(Kbase + (size_t)jg * kStride + c4);
            float* p = &sKV[r * 65 + c4];
            p[0] = v.x; p[1] = v.y; p[2] = v.z; p[3] = v.w;
        }
        __syncthreads();

        float s[4][4];
        #pragma unroll
        for (int i = 0; i < 4; i++)
            #pragma unroll
            for (int j = 0; j < 4; j++) s[i][j] = 0.f;
        #pragma unroll 8
        for (int d = 0; d < 64; d++) {
            float qv[4], kv[4];
            #pragma unroll
            for (int i = 0; i < 4; i++) qv[i] = sQ[(ty * 4 + i) * 64 + d];
            #pragma unroll
            for (int j = 0; j < 4; j++) kv[j] = sKV[(tx * 4 + j) * 65 + d];
            #pragma unroll
            for (int i = 0; i < 4; i++)
                #pragma unroll
                for (int j = 0; j < 4; j++) s[i][j] += qv[i] * kv[j];
        }
        // mask out-of-range keys
        #pragma unroll
        for (int j = 0; j < 4; j++) {
            if (kt * 64 + tx * 4 + j >= Lk) {
                #pragma unroll
                for (int i = 0; i < 4; i++) s[i][j] = -1e30f;
            }
        }
        // online softmax (row reductions over 16 tx lanes)
        #pragma unroll
        for (int i = 0; i < 4; i++) {
            float rm = fmaxf(fmaxf(s[i][0], s[i][1]), fmaxf(s[i][2], s[i][3]));
            #pragma unroll
            for (int off = 8; off; off >>= 1)
                rm = fmaxf(rm, __shfl_xor_sync(0xffffffffu, rm, off));
            float mn = fmaxf(m[i], rm);
            float rs = 0.f;
            #pragma unroll
            for (int j = 0; j < 4; j++) {
                s[i][j] = __expf(s[i][j] - mn);
                rs += s[i][j];
            }
            #pragma unroll
            for (int off = 8; off; off >>= 1)
                rs += __shfl_xor_sync(0xffffffffu, rs, off);
            float alpha = __expf(m[i] - mn);
            l[i] = l[i] * alpha + rs;
            m[i] = mn;
            #pragma unroll
            for (int j = 0; j < 4; j++) o[i][j] *= alpha;
        }
        __syncthreads();  // done reading K tile; safe to overwrite sKV

        // stage P and load V tile
        #pragma unroll
        for (int i = 0; i < 4; i++)
            #pragma unroll
            for (int j = 0; j < 4; j++)
                sS[(ty * 4 + i) * 64 + tx * 4 + j] = s[i][j];
        for (int i = tid; i < 64 * 16; i += 256) {
            int r = i >> 4, c4 = (i & 15) * 4;
            int jg = kt * 64 + r;
            float4 v = make_float4(0.f, 0.f, 0.f, 0.f);
            if (jg < Lk) v = *(const float4*)(Vbase + (size_t)jg * kStride + c4);
            float* p = &sKV[r * 65 + c4];
            p[0] = v.x; p[1] = v.y; p[2] = v.z; p[3] = v.w;
        }
        __syncthreads();

        // O += P @ V
        #pragma unroll 8
        for (int jj = 0; jj < 64; jj++) {
            float pv[4], vv[4];
            #pragma unroll
            for (int i = 0; i < 4; i++) pv[i] = sS[(ty * 4 + i) * 64 + jj];
            #pragma unroll
            for (int j = 0; j < 4; j++) vv[j] = sKV[jj * 65 + tx * 4 + j];
            #pragma unroll
            for (int i = 0; i < 4; i++)
                #pragma unroll
                for (int j = 0; j < 4; j++) o[i][j] += pv[i] * vv[j];
        }
        __syncthreads();
    }

    float* Obase = O + (size_t)(b * Lq + qt * 64) * Dx + h * 64;
    #pragma unroll
    for (int i = 0; i < 4; i++) {
        float inv = 1.f / l[i];
        #pragma unroll
        for (int j = 0; j < 4; j++)
            Obase[(size_t)(ty * 4 + i) * Dx + tx * 4 + j] = o[i][j] * inv;
    }
}

// ----------------------------------------------------------------------------
// launch
// ----------------------------------------------------------------------------
static inline float* sym(const void* s) {
    void* p = nullptr;
    cudaGetSymbolAddress(&p, s);
    return (float*)p;
}

extern "C" void kernel_launch(void* const* d_in, const int* in_sizes, int n_in,
                              void* d_out, int out_size) {
    const float* x     = (const float*)d_in[0];
    const float* c     = (const float*)d_in[1];
    const float* text  = (const float*)d_in[2];
    const float* W_ada = (const float*)d_in[3];
    const float* b_ada = (const float*)d_in[4];
    const float* W_qkv = (const float*)d_in[5];
    const float* b_qkv = (const float*)d_in[6];
    const float* W_proj= (const float*)d_in[7];
    const float* b_proj= (const float*)d_in[8];
    const float* W_ctx = (const float*)d_in[9];
    const float* b_ctx = (const float*)d_in[10];
    const float* W_q   = (const float*)d_in[11];
    const float* W_k   = (const float*)d_in[12];
    const float* W_v   = (const float*)d_in[13];
    const float* W_out = (const float*)d_in[14];
    const float* b_out = (const float*)d_in[15];
    const float* W_fc1 = (const float*)d_in[16];
    const float* b_fc1 = (const float*)d_in[17];
    const float* W_fc2 = (const float*)d_in[18];
    const float* b_fc2 = (const float*)d_in[19];
    float* out = (float*)d_out;

    float* mod   = sym(g_mod);
    float* h     = sym(g_h);
    float* qkv   = sym(g_qkv);
    float* attn  = sym(g_attn);
    float* x1    = sym(g_x1);
    float* x2    = sym(g_x2);
    float* ctx   = sym(g_ctx);
    float* q2    = sym(g_q2);
    float* k2    = sym(g_k2);
    float* v2    = sym(g_v2);
    float* hid   = sym(g_hidden);

    const int ATTN_SMEM = (64 * 64 + 64 * 65 + 64 * 64) * 4;  // 49408
    cudaFuncSetAttribute(attn_kernel, cudaFuncAttributeMaxDynamicSharedMemorySize,
                         ATTN_SMEM);

    // adaLN modulation
    ada_mod_kernel<<<dim3(24, 4), 256>>>(c, W_ada, b_ada, mod);

    // --- self attention ---
    ln_mod_kernel<<<ROWS, 256>>>(x, mod, h, 0);
    sgemm_kernel<<<dim3(3 * Dx / 128, ROWS / 128), 256>>>(
        h, W_qkv, b_qkv, nullptr, qkv, ROWS, 3 * Dx, Dx, ACT_NONE);
    attn_kernel<<<dim3(Nx / 64, Hx, Bx), 256, ATTN_SMEM>>>(
        qkv, 3 * Dx, qkv + Dx, qkv + 2 * Dx, 3 * Dx, attn, Nx, Nx);
    sgemm_kernel<<<dim3(Dx / 128, ROWS / 128), 256>>>(
        attn, W_proj, b_proj, x, x1, ROWS, Dx, Dx, ACT_NONE);

    // --- cross attention ---
    ln_mod_kernel<<<ROWS, 256>>>(x1, mod, h, 2);
    sgemm_kernel<<<dim3(Dx / 128, (CTXROWS + 127) / 128), 256>>>(
        text, W_ctx, b_ctx, nullptr, ctx, CTXROWS, Dx, TDx, ACT_NONE);
    sgemm_kernel<<<dim3(Dx / 128, ROWS / 128), 256>>>(
        h, W_q, nullptr, nullptr, q2, ROWS, Dx, Dx, ACT_NONE);
    sgemm_kernel<<<dim3(Dx / 128, (CTXROWS + 127) / 128), 256>>>(
        ctx, W_k, nullptr, nullptr, k2, CTXROWS, Dx, Dx, ACT_NONE);
    sgemm_kernel<<<dim3(Dx / 128, (CTXROWS + 127) / 128), 256>>>(
        ctx, W_v, nullptr, nullptr, v2, CTXROWS, Dx, Dx, ACT_NONE);
    attn_kernel<<<dim3(Nx / 64, Hx, Bx), 256, ATTN_SMEM>>>(
        q2, Dx, k2, v2, Dx, attn, Nx, TLx);
    sgemm_kernel<<<dim3(Dx / 128, ROWS / 128), 256>>>(
        attn, W_out, b_out, x1, x2, ROWS, Dx, Dx, ACT_NONE);

    // --- MLP ---
    ln_mod_kernel<<<ROWS, 256>>>(x2, mod, h, 4);
    sgemm_kernel<<<dim3(4 * Dx / 128, ROWS / 128), 256>>>(
        h, W_fc1, b_fc1, nullptr, hid, ROWS, 4 * Dx, Dx, ACT_GELU);
    sgemm_kernel<<<dim3(Dx / 128, ROWS / 128), 256>>>(
        hid, W_fc2, b_fc2, x2, out, ROWS, Dx, 4 * Dx, ACT_NONE);
}

// round 4
// speedup vs baseline: 1.6868x; 1.6868x over previous
#include <cuda_runtime.h>
#include <cuda_bf16.h>
#include <cstdint>
#include <math.h>

// ----------------------------------------------------------------------------
// DiT block: adaLN -> self-attn -> cross-attn -> MLP (GELU tanh)
// B=4, N=1024, D=1024, H=16, HD=64, TD=768, TL=77
// Round 4 (= Round 3 resubmit after infra failure):
// mma.sync tf32 tensor-core GEMMs (sm_100-safe), fp32 flash attention.
// ----------------------------------------------------------------------------

#define Bx 4
#define Nx 1024
#define Dx 1024
#define Hx 16
#define HDx 64
#define TDx 768
#define TLx 77
#define ROWS (Bx * Nx)       // 4096
#define CTXROWS (Bx * TLx)   // 308

// scratch (device globals; no runtime allocation allowed)
__device__ float g_mod[Bx * 6 * Dx];
__device__ float g_h[ROWS * Dx];
__device__ float g_qkv[ROWS * 3 * Dx];
__device__ float g_attn[ROWS * Dx];
__device__ float g_x1[ROWS * Dx];
__device__ float g_x2[ROWS * Dx];
__device__ float g_ctx[CTXROWS * Dx];
__device__ float g_q2[ROWS * Dx];
__device__ float g_k2[CTXROWS * Dx];
__device__ float g_v2[CTXROWS * Dx];
__device__ float g_hidden[ROWS * 4 * Dx];

// transposed (K-major [N,K]) tf32-rounded weights
__device__ float g_Wqkv_t[3 * Dx * Dx];
__device__ float g_Wproj_t[Dx * Dx];
__device__ float g_Wctx_t[Dx * TDx];
__device__ float g_Wq_t[Dx * Dx];
__device__ float g_Wk_t[Dx * Dx];
__device__ float g_Wv_t[Dx * Dx];
__device__ float g_Wout_t[Dx * Dx];
__device__ float g_Wfc1_t[4 * Dx * Dx];
__device__ float g_Wfc2_t[4 * Dx * Dx];

// ----------------------------------------------------------------------------
// helpers
// ----------------------------------------------------------------------------
__device__ __forceinline__ float tf32_rna(float x) {
    uint32_t u;
    asm("cvt.rna.tf32.f32 %0, %1;" : "=r"(u) : "f"(x));
    return __uint_as_float(u);
}

__device__ __forceinline__ void mma_tf32(float& c0, float& c1, float& c2, float& c3,
                                         uint32_t a0, uint32_t a1, uint32_t a2, uint32_t a3,
                                         uint32_t b0, uint32_t b1) {
    asm volatile(
        "mma.sync.aligned.m16n8k8.row.col.f32.tf32.tf32.f32 "
        "{%0,%1,%2,%3}, {%4,%5,%6,%7}, {%8,%9}, {%0,%1,%2,%3};"
        : "+f"(c0), "+f"(c1), "+f"(c2), "+f"(c3)
        : "r"(a0), "r"(a1), "r"(a2), "r"(a3), "r"(b0), "r"(b1));
}

// ----------------------------------------------------------------------------
// weight transpose: in[K,N] row-major -> out[N,K] row-major, tf32-rounded.
// grid (N/32, K/32), block (32, 8)
// ----------------------------------------------------------------------------
__global__ void transpose_rna_kernel(const float* __restrict__ in,
                                     float* __restrict__ out, int K, int N) {
    __shared__ float t[32][33];
    int n0 = blockIdx.x * 32, k0 = blockIdx.y * 32;
    int tx = threadIdx.x, ty = threadIdx.y;
    #pragma unroll
    for (int i = 0; i < 32; i += 8)
        t[ty + i][tx] = tf32_rna(in[(size_t)(k0 + ty + i) * N + n0 + tx]);
    __syncthreads();
    #pragma unroll
    for (int i = 0; i < 32; i += 8)
        out[(size_t)(n0 + ty + i) * K + k0 + tx] = t[tx][ty + i];
}

// ----------------------------------------------------------------------------
// adaLN modulation: mod = silu(c) @ W_ada + b_ada
// ----------------------------------------------------------------------------
__global__ void ada_mod_kernel(const float* __restrict__ c,
                               const float* __restrict__ Wada,
                               const float* __restrict__ bada,
                               float* __restrict__ mod) {
    __shared__ float sc[Dx];
    int b = blockIdx.y;
    for (int i = threadIdx.x; i < Dx; i += 256) {
        float v = c[b * Dx + i];
        sc[i] = v / (1.f + __expf(-v));
    }
    __syncthreads();
    int n = blockIdx.x * 256 + threadIdx.x;
    float acc = 0.f;
    for (int k = 0; k < Dx; k++)
        acc += sc[k] * Wada[(size_t)k * (6 * Dx) + n];
    mod[b * 6 * Dx + n] = acc + bada[n];
}

// ----------------------------------------------------------------------------
// LayerNorm + modulate
// ----------------------------------------------------------------------------
__global__ void ln_mod_kernel(const float* __restrict__ x,
                              const float* __restrict__ mod,
                              float* __restrict__ out, int chunk) {
    int row = blockIdx.x;
    int b = row >> 10;
    int tid = threadIdx.x;
    const float* xr = x + (size_t)row * Dx;
    float4 v = *(const float4*)(xr + tid * 4);
    float s = v.x + v.y + v.z + v.w;
    float ss = v.x * v.x + v.y * v.y + v.z * v.z + v.w * v.w;
    #pragma unroll
    for (int off = 16; off; off >>= 1) {
        s  += __shfl_xor_sync(0xffffffffu, s, off);
        ss += __shfl_xor_sync(0xffffffffu, ss, off);
    }
    __shared__ float rs[8], rss[8];
    int wid = tid >> 5, lane = tid & 31;
    if (!lane) { rs[wid] = s; rss[wid] = ss; }
    __syncthreads();
    s = 0.f; ss = 0.f;
    #pragma unroll
    for (int w = 0; w < 8; w++) { s += rs[w]; ss += rss[w]; }
    float mean = s * (1.f / Dx);
    float var = ss * (1.f / Dx) - mean * mean;
    float inv = rsqrtf(var + 1e-6f);
    const float* sh = mod + (size_t)b * 6 * Dx + (size_t)chunk * Dx;
    const float* scl = sh + Dx;
    int d = tid * 4;
    float4 o;
    o.x = (v.x - mean) * inv * (1.f + scl[d + 0]) + sh[d + 0];
    o.y = (v.y - mean) * inv * (1.f + scl[d + 1]) + sh[d + 1];
    o.z = (v.z - mean) * inv * (1.f + scl[d + 2]) + sh[d + 2];
    o.w = (v.w - mean) * inv * (1.f + scl[d + 3]) + sh[d + 3];
    *(float4*)(out + (size_t)row * Dx + d) = o;
}

// ----------------------------------------------------------------------------
// tf32 mma.sync GEMM: C[M,N] = A[M,K] @ BT[N,K]^T (+bias)(+GELU)(+res)
// 128x128 tile, BK=32, 512 threads (16 warps, 4x4), warp tile 32x32.
// Fragment-permuted smem staging:
//   A frag (fm 0..7, ks 0..3): 16x8 tf32, per-lane 4 floats contiguous (lds.128)
//     addr = ((ks*8+fm)*32 + lane)*16B
//   B frag (fn 0..15, ks 0..3): 8x8, per-lane 2 floats contiguous (lds.64)
//     addr = ((ks*16+fn)*32 + lane)*8B
// Each buffer: A 16KB + B 16KB. Double-buffered: 64KB dynamic smem.
// ----------------------------------------------------------------------------
#define ACT_NONE 0
#define ACT_GELU 1
#define GEMM_SMEM 65536

__device__ __forceinline__ float gelu_tanh(float x) {
    float x3 = x * x * x;
    return 0.5f * x * (1.f + tanhf(0.7978845608028654f * (x + 0.044715f * x3)));
}

__global__ __launch_bounds__(512, 1)
void tf32_mma_gemm(const float* __restrict__ A, const float* __restrict__ BT,
                   const float* __restrict__ bias, const float* __restrict__ res,
                   float* __restrict__ C, int M, int N, int K, int act) {
    extern __shared__ char smem[];
    char* sA[2] = { smem,         smem + 16384 };
    char* sB[2] = { smem + 32768, smem + 49152 };

    int tid = threadIdx.x;
    int lane = tid & 31, wid = tid >> 5;
    int wm = wid >> 2, wn = wid & 3;       // 4x4 warp grid
    int row0 = blockIdx.y * 128, col0 = blockIdx.x * 128;

    // --- staging slot assignment: 1024 float4 slots per tile, 2 per thread ---
    int sidx[2] = { tid, tid + 512 };
    int rA[2], qA[2], offA[2];
    int nB[2], qB[2], offB[2];
    bool vA[2];
    const float* gA[2];
    const float* gB[2];
    #pragma unroll
    for (int i = 0; i < 2; i++) {
        int s = sidx[i];
        rA[i] = s >> 3; qA[i] = s & 7;
        int fm = rA[i] >> 4, rin = rA[i] & 15, ks = qA[i] >> 1;
        offA[i] = ((ks * 8 + fm) * 32 + (rin & 7) * 4) * 16
                  + ((rin >> 3) + 2 * (qA[i] & 1)) * 4;
        vA[i] = (row0 + rA[i]) < M;
        gA[i] = A + (size_t)(row0 + rA[i]) * K + qA[i] * 4;

        nB[i] = s >> 3; qB[i] = s & 7;
        int fn = nB[i] >> 3, ksb = qB[i] >> 1;
        offB[i] = ((ksb * 16 + fn) * 32 + (nB[i] & 7) * 4) * 8 + (qB[i] & 1) * 4;
        gB[i] = BT + (size_t)(col0 + nB[i]) * K + qB[i] * 4;
    }

    float acc[2][4][4];
    #pragma unroll
    for (int im = 0; im < 2; im++)
        #pragma unroll
        for (int jn = 0; jn < 4; jn++)
            #pragma unroll
            for (int e = 0; e < 4; e++) acc[im][jn][e] = 0.f;

    int K32 = K >> 5;

    // preload stage 0
    float4 ra[2], rb[2];
    #pragma unroll
    for (int i = 0; i < 2; i++) {
        ra[i] = vA[i] ? *(const float4*)gA[i] : make_float4(0.f, 0.f, 0.f, 0.f);
        rb[i] = *(const float4*)gB[i];
    }
    #pragma unroll
    for (int i = 0; i < 2; i++) {
        float av[4] = { ra[i].x, ra[i].y, ra[i].z, ra[i].w };
        float bv[4] = { rb[i].x, rb[i].y, rb[i].z, rb[i].w };
        #pragma unroll
        for (int e = 0; e < 4; e++) {
            *(float*)(sA[0] + offA[i] + e * 16) = tf32_rna(av[e]);
            *(float*)(sB[0] + offB[i] + e * 8)  = bv[e];
        }
    }
    __syncthreads();

    for (int s = 0; s < K32; s++) {
        int cur = s & 1;
        // prefetch next tile to registers
        if (s + 1 < K32) {
            #pragma unroll
            for (int i = 0; i < 2; i++) {
                const float* pa = gA[i] + (size_t)(s + 1) * 32;
                const float* pb = gB[i] + (size_t)(s + 1) * 32;
                ra[i] = vA[i] ? *(const float4*)pa : make_float4(0.f, 0.f, 0.f, 0.f);
                rb[i] = *(const float4*)pb;
            }
        }

        // mma over current buffer (4 k-steps of 8)
        #pragma unroll
        for (int ks = 0; ks < 4; ks++) {
            uint4 afr[2];
            uint2 bfr[4];
            #pragma unroll
            for (int im = 0; im < 2; im++) {
                int fm = wm * 2 + im;
                afr[im] = *(const uint4*)(sA[cur] + ((ks * 8 + fm) * 32 + lane) * 16);
            }
            #pragma unroll
            for (int jn = 0; jn < 4; jn++) {
                int fn = wn * 4 + jn;
                bfr[jn] = *(const uint2*)(sB[cur] + ((ks * 16 + fn) * 32 + lane) * 8);
            }
            #pragma unroll
            for (int im = 0; im < 2; im++)
                #pragma unroll
                for (int jn = 0; jn < 4; jn++)
                    mma_tf32(acc[im][jn][0], acc[im][jn][1],
                             acc[im][jn][2], acc[im][jn][3],
                             afr[im].x, afr[im].y, afr[im].z, afr[im].w,
                             bfr[jn].x, bfr[jn].y);
        }

        // store next tile
        if (s + 1 < K32) {
            int nxt = 1 - cur;
            #pragma unroll
            for (int i = 0; i < 2; i++) {
                float av[4] = { ra[i].x, ra[i].y, ra[i].z, ra[i].w };
                float bv[4] = { rb[i].x, rb[i].y, rb[i].z, rb[i].w };
                #pragma unroll
                for (int e = 0; e < 4; e++) {
                    *(float*)(sA[nxt] + offA[i] + e * 16) = tf32_rna(av[e]);
                    *(float*)(sB[nxt] + offB[i] + e * 8)  = bv[e];
                }
            }
        }
        __syncthreads();
    }

    // --- epilogue ---
    int gr = lane >> 2, gc = (lane & 3) * 2;
    #pragma unroll
    for (int im = 0; im < 2; im++) {
        #pragma unroll
        for (int half = 0; half < 2; half++) {
            int rg = row0 + wm * 32 + im * 16 + gr + half * 8;
            if (rg >= M) continue;
            #pragma unroll
            for (int jn = 0; jn < 4; jn++) {
                int cg = col0 + wn * 32 + jn * 8 + gc;
                float t0 = acc[im][jn][half * 2 + 0];
                float t1 = acc[im][jn][half * 2 + 1];
                if (bias) { t0 += bias[cg]; t1 += bias[cg + 1]; }
                if (act == ACT_GELU) { t0 = gelu_tanh(t0); t1 = gelu_tanh(t1); }
                if (res) {
                    t0 += res[(size_t)rg * N + cg];
                    t1 += res[(size_t)rg * N + cg + 1];
                }
                *(float2*)(C + (size_t)rg * N + cg) = make_float2(t0, t1);
            }
        }
    }
}

// ----------------------------------------------------------------------------
// Flash-style attention (unchanged)
// ----------------------------------------------------------------------------
__global__ __launch_bounds__(256, 2)
void attn_kernel(const float* __restrict__ Q, int qStride,
                 const float* __restrict__ K, const float* __restrict__ V,
                 int kStride, float* __restrict__ O, int Lq, int Lk) {
    extern __shared__ float sm[];
    float* sQ  = sm;
    float* sKV = sm + 64 * 64;
    float* sS  = sm + 64 * 64 + 64 * 65;
    int tid = threadIdx.x;
    int tx = tid & 15, ty = tid >> 4;
    int qt = blockIdx.x, h = blockIdx.y, b = blockIdx.z;
    const float scale = 0.125f;

    const float* Qbase = Q + (size_t)(b * Lq + qt * 64) * qStride + h * 64;
    for (int i = tid; i < 64 * 16; i += 256) {
        int r = i >> 4, c4 = (i & 15) * 4;
        float4 v = *(const float4*)(Qbase + (size_t)r * qStride + c4);
        v.x *= scale; v.y *= scale; v.z *= scale; v.w *= scale;
        *(float4*)&sQ[r * 64 + c4] = v;
    }

    float m[4], l[4], o[4][4];
    #pragma unroll
    for (int i = 0; i < 4; i++) {
        m[i] = -1e30f; l[i] = 0.f;
        #pragma unroll
        for (int j = 0; j < 4; j++) o[i][j] = 0.f;
    }

    const float* Kbase = K + (size_t)(b * Lk) * kStride + h * 64;
    const float* Vbase = V + (size_t)(b * Lk) * kStride + h * 64;
    int nkt = (Lk + 63) >> 6;

    for (int kt = 0; kt < nkt; kt++) {
        for (int i = tid; i < 64 * 16; i += 256) {
            int r = i >> 4, c4 = (i & 15) * 4;
            int jg = kt * 64 + r;
            float4 v = make_float4(0.f, 0.f, 0.f, 0.f);
            if (jg < Lk) v = *(const float4*)(Kbase + (size_t)jg * kStride + c4);
            float* p = &sKV[r * 65 + c4];
            p[0] = v.x; p[1] = v.y; p[2] = v.z; p[3] = v.w;
        }
        __syncthreads();

        float s[4][4];
        #pragma unroll
        for (int i = 0; i < 4; i++)
            #pragma unroll
            for (int j = 0; j < 4; j++) s[i][j] = 0.f;
        #pragma unroll 8
        for (int d = 0; d < 64; d++) {
            float qv[4], kv[4];
            #pragma unroll
            for (int i = 0; i < 4; i++) qv[i] = sQ[(ty * 4 + i) * 64 + d];
            #pragma unroll
            for (int j = 0; j < 4; j++) kv[j] = sKV[(tx * 4 + j) * 65 + d];
            #pragma unroll
            for (int i = 0; i < 4; i++)
                #pragma unroll
                for (int j = 0; j < 4; j++) s[i][j] += qv[i] * kv[j];
        }
        #pragma unroll
        for (int j = 0; j < 4; j++) {
            if (kt * 64 + tx * 4 + j >= Lk) {
                #pragma unroll
                for (int i = 0; i < 4; i++) s[i][j] = -1e30f;
            }
        }
        #pragma unroll
        for (int i = 0; i < 4; i++) {
            float rm = fmaxf(fmaxf(s[i][0], s[i][1]), fmaxf(s[i][2], s[i][3]));
            #pragma unroll
            for (int off = 8; off; off >>= 1)
                rm = fmaxf(rm, __shfl_xor_sync(0xffffffffu, rm, off));
            float mn = fmaxf(m[i], rm);
            float rs2 = 0.f;
            #pragma unroll
            for (int j = 0; j < 4; j++) {
                s[i][j] = __expf(s[i][j] - mn);
                rs2 += s[i][j];
            }
            #pragma unroll
            for (int off = 8; off; off >>= 1)
                rs2 += __shfl_xor_sync(0xffffffffu, rs2, off);
            float alpha = __expf(m[i] - mn);
            l[i] = l[i] * alpha + rs2;
            m[i] = mn;
            #pragma unroll
            for (int j = 0; j < 4; j++) o[i][j] *= alpha;
        }
        __syncthreads();

        #pragma unroll
        for (int i = 0; i < 4; i++)
            #pragma unroll
            for (int j = 0; j < 4; j++)
                sS[(ty * 4 + i) * 64 + tx * 4 + j] = s[i][j];
        for (int i = tid; i < 64 * 16; i += 256) {
            int r = i >> 4, c4 = (i & 15) * 4;
            int jg = kt * 64 + r;
            float4 v = make_float4(0.f, 0.f, 0.f, 0.f);
            if (jg < Lk) v = *(const float4*)(Vbase + (size_t)jg * kStride + c4);
            float* p = &sKV[r * 65 + c4];
            p[0] = v.x; p[1] = v.y; p[2] = v.z; p[3] = v.w;
        }
        __syncthreads();

        #pragma unroll 8
        for (int jj = 0; jj < 64; jj++) {
            float pv[4], vv[4];
            #pragma unroll
            for (int i = 0; i < 4; i++) pv[i] = sS[(ty * 4 + i) * 64 + jj];
            #pragma unroll
            for (int j = 0; j < 4; j++) vv[j] = sKV[jj * 65 + tx * 4 + j];
            #pragma unroll
            for (int i = 0; i < 4; i++)
                #pragma unroll
                for (int j = 0; j < 4; j++) o[i][j] += pv[i] * vv[j];
        }
        __syncthreads();
    }

    float* Obase = O + (size_t)(b * Lq + qt * 64) * Dx + h * 64;
    #pragma unroll
    for (int i = 0; i < 4; i++) {
        float inv = 1.f / l[i];
        #pragma unroll
        for (int j = 0; j < 4; j++)
            Obase[(size_t)(ty * 4 + i) * Dx + tx * 4 + j] = o[i][j] * inv;
    }
}

// ----------------------------------------------------------------------------
// launch
// ----------------------------------------------------------------------------
static inline float* sym(const void* s) {
    void* p = nullptr;
    cudaGetSymbolAddress(&p, s);
    return (float*)p;
}

static inline void gemm(const float* A, const float* BT, const float* bias,
                        const float* res, float* C, int M, int N, int K, int act) {
    dim3 grid(N / 128, (M + 127) / 128);
    tf32_mma_gemm<<<grid, 512, GEMM_SMEM>>>(A, BT, bias, res, C, M, N, K, act);
}

extern "C" void kernel_launch(void* const* d_in, const int* in_sizes, int n_in,
                              void* d_out, int out_size) {
    const float* x     = (const float*)d_in[0];
    const float* c     = (const float*)d_in[1];
    const float* text  = (const float*)d_in[2];
    const float* W_ada = (const float*)d_in[3];
    const float* b_ada = (const float*)d_in[4];
    const float* W_qkv = (const float*)d_in[5];
    const float* b_qkv = (const float*)d_in[6];
    const float* W_proj= (const float*)d_in[7];
    const float* b_proj= (const float*)d_in[8];
    const float* W_ctx = (const float*)d_in[9];
    const float* b_ctx = (const float*)d_in[10];
    const float* W_q   = (const float*)d_in[11];
    const float* W_k   = (const float*)d_in[12];
    const float* W_v   = (const float*)d_in[13];
    const float* W_out = (const float*)d_in[14];
    const float* b_out = (const float*)d_in[15];
    const float* W_fc1 = (const float*)d_in[16];
    const float* b_fc1 = (const float*)d_in[17];
    const float* W_fc2 = (const float*)d_in[18];
    const float* b_fc2 = (const float*)d_in[19];
    float* out = (float*)d_out;

    float* mod   = sym(g_mod);
    float* h     = sym(g_h);
    float* qkv   = sym(g_qkv);
    float* attn  = sym(g_attn);
    float* x1    = sym(g_x1);
    float* x2    = sym(g_x2);
    float* ctx   = sym(g_ctx);
    float* q2    = sym(g_q2);
    float* k2    = sym(g_k2);
    float* v2    = sym(g_v2);
    float* hid   = sym(g_hidden);

    float* Wqkv_t = sym(g_Wqkv_t);
    float* Wproj_t= sym(g_Wproj_t);
    float* Wctx_t = sym(g_Wctx_t);
    float* Wq_t   = sym(g_Wq_t);
    float* Wk_t   = sym(g_Wk_t);
    float* Wv_t   = sym(g_Wv_t);
    float* Wout_t = sym(g_Wout_t);
    float* Wfc1_t = sym(g_Wfc1_t);
    float* Wfc2_t = sym(g_Wfc2_t);

    const int ATTN_SMEM = (64 * 64 + 64 * 65 + 64 * 64) * 4;
    cudaFuncSetAttribute(attn_kernel, cudaFuncAttributeMaxDynamicSharedMemorySize,
                         ATTN_SMEM);
    cudaFuncSetAttribute(tf32_mma_gemm, cudaFuncAttributeMaxDynamicSharedMemorySize,
                         GEMM_SMEM);

    // --- weight transposes (K-major, tf32-rounded) ---
    dim3 tb(32, 8);
    transpose_rna_kernel<<<dim3(3 * Dx / 32, Dx / 32), tb>>>(W_qkv, Wqkv_t, Dx, 3 * Dx);
    transpose_rna_kernel<<<dim3(Dx / 32, Dx / 32), tb>>>(W_proj, Wproj_t, Dx, Dx);
    transpose_rna_kernel<<<dim3(Dx / 32, TDx / 32), tb>>>(W_ctx, Wctx_t, TDx, Dx);
    transpose_rna_kernel<<<dim3(Dx / 32, Dx / 32), tb>>>(W_q, Wq_t, Dx, Dx);
    transpose_rna_kernel<<<dim3(Dx / 32, Dx / 32), tb>>>(W_k, Wk_t, Dx, Dx);
    transpose_rna_kernel<<<dim3(Dx / 32, Dx / 32), tb>>>(W_v, Wv_t, Dx, Dx);
    transpose_rna_kernel<<<dim3(Dx / 32, Dx / 32), tb>>>(W_out, Wout_t, Dx, Dx);
    transpose_rna_kernel<<<dim3(4 * Dx / 32, Dx / 32), tb>>>(W_fc1, Wfc1_t, Dx, 4 * Dx);
    transpose_rna_kernel<<<dim3(Dx / 32, 4 * Dx / 32), tb>>>(W_fc2, Wfc2_t, 4 * Dx, Dx);

    // adaLN modulation
    ada_mod_kernel<<<dim3(24, 4), 256>>>(c, W_ada, b_ada, mod);

    // --- self attention ---
    ln_mod_kernel<<<ROWS, 256>>>(x, mod, h, 0);
    gemm(h, Wqkv_t, b_qkv, nullptr, qkv, ROWS, 3 * Dx, Dx, ACT_NONE);
    attn_kernel<<<dim3(Nx / 64, Hx, Bx), 256, ATTN_SMEM>>>(
        qkv, 3 * Dx, qkv + Dx, qkv + 2 * Dx, 3 * Dx, attn, Nx, Nx);
    gemm(attn, Wproj_t, b_proj, x, x1, ROWS, Dx, Dx, ACT_NONE);

    // --- cross attention ---
    ln_mod_kernel<<<ROWS, 256>>>(x1, mod, h, 2);
    gemm(text, Wctx_t, b_ctx, nullptr, ctx, CTXROWS, Dx, TDx, ACT_NONE);
    gemm(h, Wq_t, nullptr, nullptr, q2, ROWS, Dx, Dx, ACT_NONE);
    gemm(ctx, Wk_t, nullptr, nullptr, k2, CTXROWS, Dx, Dx, ACT_NONE);
    gemm(ctx, Wv_t, nullptr, nullptr, v2, CTXROWS, Dx, Dx, ACT_NONE);
    attn_kernel<<<dim3(Nx / 64, Hx, Bx), 256, ATTN_SMEM>>>(
        q2, Dx, k2, v2, Dx, attn, Nx, TLx);
    gemm(attn, Wout_t, b_out, x1, x2, ROWS, Dx, Dx, ACT_NONE);

    // --- MLP ---
    ln_mod_kernel<<<ROWS, 256>>>(x2, mod, h, 4);
    gemm(h, Wfc1_t, b_fc1, nullptr, hid, ROWS, 4 * Dx, Dx, ACT_GELU);
    gemm(hid, Wfc2_t, b_fc2, x2, out, ROWS, Dx, 4 * Dx, ACT_NONE);
}

// round 5
// speedup vs baseline: 1.9740x; 1.1703x over previous
#include <cuda_runtime.h>
#include <cuda_bf16.h>
#include <cstdint>
#include <math.h>

// ----------------------------------------------------------------------------
// DiT block: adaLN -> self-attn -> cross-attn -> MLP (GELU tanh)
// Round 5: tf32 mma.sync GEMMs + tf32 mma.sync flash attention.
// ----------------------------------------------------------------------------

#define Bx 4
#define Nx 1024
#define Dx 1024
#define Hx 16
#define HDx 64
#define TDx 768
#define TLx 77
#define ROWS (Bx * Nx)       // 4096
#define CTXROWS (Bx * TLx)   // 308

// scratch (device globals; no runtime allocation allowed)
__device__ float g_mod[Bx * 6 * Dx];
__device__ float g_h[ROWS * Dx];
__device__ float g_qkv[ROWS * 3 * Dx];
__device__ float g_attn[ROWS * Dx];
__device__ float g_x1[ROWS * Dx];
__device__ float g_x2[ROWS * Dx];
__device__ float g_ctx[CTXROWS * Dx];
__device__ float g_q2[ROWS * Dx];
__device__ float g_k2v2[CTXROWS * 2 * Dx];
__device__ float g_hidden[ROWS * 4 * Dx];

// transposed (K-major [N,K]) tf32-rounded weights
__device__ float g_Wqkv_t[3 * Dx * Dx];
__device__ float g_Wproj_t[Dx * Dx];
__device__ float g_Wctx_t[Dx * TDx];
__device__ float g_Wq_t[Dx * Dx];
__device__ float g_Wkv_t[2 * Dx * Dx];   // [Wk ; Wv] stacked in N
__device__ float g_Wout_t[Dx * Dx];
__device__ float g_Wfc1_t[4 * Dx * Dx];
__device__ float g_Wfc2_t[4 * Dx * Dx];

// ----------------------------------------------------------------------------
// helpers
// ----------------------------------------------------------------------------
__device__ __forceinline__ float tf32_rna(float x) {
    uint32_t u;
    asm("cvt.rna.tf32.f32 %0, %1;" : "=r"(u) : "f"(x));
    return __uint_as_float(u);
}
__device__ __forceinline__ uint32_t tf32_bits(float x) {
    uint32_t u;
    asm("cvt.rna.tf32.f32 %0, %1;" : "=r"(u) : "f"(x));
    return u;
}

__device__ __forceinline__ void mma_tf32(float& c0, float& c1, float& c2, float& c3,
                                         uint32_t a0, uint32_t a1, uint32_t a2, uint32_t a3,
                                         uint32_t b0, uint32_t b1) {
    asm volatile(
        "mma.sync.aligned.m16n8k8.row.col.f32.tf32.tf32.f32 "
        "{%0,%1,%2,%3}, {%4,%5,%6,%7}, {%8,%9}, {%0,%1,%2,%3};"
        : "+f"(c0), "+f"(c1), "+f"(c2), "+f"(c3)
        : "r"(a0), "r"(a1), "r"(a2), "r"(a3), "r"(b0), "r"(b1));
}

// ----------------------------------------------------------------------------
// weight transpose: in[K,N] row-major -> out[N,K] row-major, tf32-rounded.
// ----------------------------------------------------------------------------
__global__ void transpose_rna_kernel(const float* __restrict__ in,
                                     float* __restrict__ out, int K, int N) {
    __shared__ float t[32][33];
    int n0 = blockIdx.x * 32, k0 = blockIdx.y * 32;
    int tx = threadIdx.x, ty = threadIdx.y;
    #pragma unroll
    for (int i = 0; i < 32; i += 8)
        t[ty + i][tx] = tf32_rna(in[(size_t)(k0 + ty + i) * N + n0 + tx]);
    __syncthreads();
    #pragma unroll
    for (int i = 0; i < 32; i += 8)
        out[(size_t)(n0 + ty + i) * K + k0 + tx] = t[tx][ty + i];
}

// ----------------------------------------------------------------------------
// adaLN modulation: mod = silu(c) @ W_ada + b_ada
// ----------------------------------------------------------------------------
__global__ void ada_mod_kernel(const float* __restrict__ c,
                               const float* __restrict__ Wada,
                               const float* __restrict__ bada,
                               float* __restrict__ mod) {
    __shared__ float sc[Dx];
    int b = blockIdx.y;
    for (int i = threadIdx.x; i < Dx; i += 256) {
        float v = c[b * Dx + i];
        sc[i] = v / (1.f + __expf(-v));
    }
    __syncthreads();
    int n = blockIdx.x * 256 + threadIdx.x;
    float acc = 0.f;
    for (int k = 0; k < Dx; k++)
        acc += sc[k] * Wada[(size_t)k * (6 * Dx) + n];
    mod[b * 6 * Dx + n] = acc + bada[n];
}

// ----------------------------------------------------------------------------
// LayerNorm + modulate
// ----------------------------------------------------------------------------
__global__ void ln_mod_kernel(const float* __restrict__ x,
                              const float* __restrict__ mod,
                              float* __restrict__ out, int chunk) {
    int row = blockIdx.x;
    int b = row >> 10;
    int tid = threadIdx.x;
    const float* xr = x + (size_t)row * Dx;
    float4 v = *(const float4*)(xr + tid * 4);
    float s = v.x + v.y + v.z + v.w;
    float ss = v.x * v.x + v.y * v.y + v.z * v.z + v.w * v.w;
    #pragma unroll
    for (int off = 16; off; off >>= 1) {
        s  += __shfl_xor_sync(0xffffffffu, s, off);
        ss += __shfl_xor_sync(0xffffffffu, ss, off);
    }
    __shared__ float rs[8], rss[8];
    int wid = tid >> 5, lane = tid & 31;
    if (!lane) { rs[wid] = s; rss[wid] = ss; }
    __syncthreads();
    s = 0.f; ss = 0.f;
    #pragma unroll
    for (int w = 0; w < 8; w++) { s += rs[w]; ss += rss[w]; }
    float mean = s * (1.f / Dx);
    float var = ss * (1.f / Dx) - mean * mean;
    float inv = rsqrtf(var + 1e-6f);
    const float* sh = mod + (size_t)b * 6 * Dx + (size_t)chunk * Dx;
    const float* scl = sh + Dx;
    int d = tid * 4;
    float4 o;
    o.x = (v.x - mean) * inv * (1.f + scl[d + 0]) + sh[d + 0];
    o.y = (v.y - mean) * inv * (1.f + scl[d + 1]) + sh[d + 1];
    o.z = (v.z - mean) * inv * (1.f + scl[d + 2]) + sh[d + 2];
    o.w = (v.w - mean) * inv * (1.f + scl[d + 3]) + sh[d + 3];
    *(float4*)(out + (size_t)row * Dx + d) = o;
}

// ----------------------------------------------------------------------------
// tf32 mma.sync GEMM (unchanged from round 4 — proven)
// ----------------------------------------------------------------------------
#define ACT_NONE 0
#define ACT_GELU 1
#define GEMM_SMEM 65536

__device__ __forceinline__ float gelu_tanh(float x) {
    float x3 = x * x * x;
    return 0.5f * x * (1.f + tanhf(0.7978845608028654f * (x + 0.044715f * x3)));
}

__global__ __launch_bounds__(512, 1)
void tf32_mma_gemm(const float* __restrict__ A, const float* __restrict__ BT,
                   const float* __restrict__ bias, const float* __restrict__ res,
                   float* __restrict__ C, int M, int N, int K, int act) {
    extern __shared__ char smem[];
    char* sA[2] = { smem,         smem + 16384 };
    char* sB[2] = { smem + 32768, smem + 49152 };

    int tid = threadIdx.x;
    int lane = tid & 31, wid = tid >> 5;
    int wm = wid >> 2, wn = wid & 3;
    int row0 = blockIdx.y * 128, col0 = blockIdx.x * 128;

    int sidx[2] = { tid, tid + 512 };
    int rA[2], qA[2], offA[2];
    int nB[2], qB[2], offB[2];
    bool vA[2];
    const float* gA[2];
    const float* gB[2];
    #pragma unroll
    for (int i = 0; i < 2; i++) {
        int s = sidx[i];
        rA[i] = s >> 3; qA[i] = s & 7;
        int fm = rA[i] >> 4, rin = rA[i] & 15, ks = qA[i] >> 1;
        offA[i] = ((ks * 8 + fm) * 32 + (rin & 7) * 4) * 16
                  + ((rin >> 3) + 2 * (qA[i] & 1)) * 4;
        vA[i] = (row0 + rA[i]) < M;
        gA[i] = A + (size_t)(row0 + rA[i]) * K + qA[i] * 4;

        nB[i] = s >> 3; qB[i] = s & 7;
        int fn = nB[i] >> 3, ksb = qB[i] >> 1;
        offB[i] = ((ksb * 16 + fn) * 32 + (nB[i] & 7) * 4) * 8 + (qB[i] & 1) * 4;
        gB[i] = BT + (size_t)(col0 + nB[i]) * K + qB[i] * 4;
    }

    float acc[2][4][4];
    #pragma unroll
    for (int im = 0; im < 2; im++)
        #pragma unroll
        for (int jn = 0; jn < 4; jn++)
            #pragma unroll
            for (int e = 0; e < 4; e++) acc[im][jn][e] = 0.f;

    int K32 = K >> 5;

    float4 ra[2], rb[2];
    #pragma unroll
    for (int i = 0; i < 2; i++) {
        ra[i] = vA[i] ? *(const float4*)gA[i] : make_float4(0.f, 0.f, 0.f, 0.f);
        rb[i] = *(const float4*)gB[i];
    }
    #pragma unroll
    for (int i = 0; i < 2; i++) {
        float av[4] = { ra[i].x, ra[i].y, ra[i].z, ra[i].w };
        float bv[4] = { rb[i].x, rb[i].y, rb[i].z, rb[i].w };
        #pragma unroll
        for (int e = 0; e < 4; e++) {
            *(float*)(sA[0] + offA[i] + e * 16) = tf32_rna(av[e]);
            *(float*)(sB[0] + offB[i] + e * 8)  = bv[e];
        }
    }
    __syncthreads();

    for (int s = 0; s < K32; s++) {
        int cur = s & 1;
        if (s + 1 < K32) {
            #pragma unroll
            for (int i = 0; i < 2; i++) {
                const float* pa = gA[i] + (size_t)(s + 1) * 32;
                const float* pb = gB[i] + (size_t)(s + 1) * 32;
                ra[i] = vA[i] ? *(const float4*)pa : make_float4(0.f, 0.f, 0.f, 0.f);
                rb[i] = *(const float4*)pb;
            }
        }

        #pragma unroll
        for (int ks = 0; ks < 4; ks++) {
            uint4 afr[2];
            uint2 bfr[4];
            #pragma unroll
            for (int im = 0; im < 2; im++) {
                int fm = wm * 2 + im;
                afr[im] = *(const uint4*)(sA[cur] + ((ks * 8 + fm) * 32 + lane) * 16);
            }
            #pragma unroll
            for (int jn = 0; jn < 4; jn++) {
                int fn = wn * 4 + jn;
                bfr[jn] = *(const uint2*)(sB[cur] + ((ks * 16 + fn) * 32 + lane) * 8);
            }
            #pragma unroll
            for (int im = 0; im < 2; im++)
                #pragma unroll
                for (int jn = 0; jn < 4; jn++)
                    mma_tf32(acc[im][jn][0], acc[im][jn][1],
                             acc[im][jn][2], acc[im][jn][3],
                             afr[im].x, afr[im].y, afr[im].z, afr[im].w,
                             bfr[jn].x, bfr[jn].y);
        }

        if (s + 1 < K32) {
            int nxt = 1 - cur;
            #pragma unroll
            for (int i = 0; i < 2; i++) {
                float av[4] = { ra[i].x, ra[i].y, ra[i].z, ra[i].w };
                float bv[4] = { rb[i].x, rb[i].y, rb[i].z, rb[i].w };
                #pragma unroll
                for (int e = 0; e < 4; e++) {
                    *(float*)(sA[nxt] + offA[i] + e * 16) = tf32_rna(av[e]);
                    *(float*)(sB[nxt] + offB[i] + e * 8)  = bv[e];
                }
            }
        }
        __syncthreads();
    }

    int gr = lane >> 2, gc = (lane & 3) * 2;
    #pragma unroll
    for (int im = 0; im < 2; im++) {
        #pragma unroll
        for (int half = 0; half < 2; half++) {
            int rg = row0 + wm * 32 + im * 16 + gr + half * 8;
            if (rg >= M) continue;
            #pragma unroll
            for (int jn = 0; jn < 4; jn++) {
                int cg = col0 + wn * 32 + jn * 8 + gc;
                float t0 = acc[im][jn][half * 2 + 0];
                float t1 = acc[im][jn][half * 2 + 1];
                if (bias) { t0 += bias[cg]; t1 += bias[cg + 1]; }
                if (act == ACT_GELU) { t0 = gelu_tanh(t0); t1 = gelu_tanh(t1); }
                if (res) {
                    t0 += res[(size_t)rg * N + cg];
                    t1 += res[(size_t)rg * N + cg + 1];
                }
                *(float2*)(C + (size_t)rg * N + cg) = make_float2(t0, t1);
            }
        }
    }
}

// ----------------------------------------------------------------------------
// tf32 mma.sync flash attention.
// 64 q-rows per block, 4 warps (each m16), HD=64, K tiles of 64.
// smem: sK (B-frag layout, 16KB), sV (B-frag layout, 16KB), sQP [64][68] fp32.
// Fragment layouts match the GEMM's proven conventions:
//   A (m16k8): a0=A[gr][lc], a1=A[gr+8][lc], a2=A[gr][lc+4], a3=A[gr+8][lc+4]
//   B (k8n8):  b0=BT[n=fn*8+gr][k=ks*8+lc], b1=same n, k+4
//   C (m16n8): c0,c1=row gr cols 2lc,2lc+1; c2,c3=row gr+8
// ----------------------------------------------------------------------------
#define ATTN_SMEM (16384 + 16384 + 64 * 68 * 4)

__global__ __launch_bounds__(128, 2)
void attn_mma_kernel(const float* __restrict__ Q, int qStride,
                     const float* __restrict__ K, const float* __restrict__ V,
                     int kStride, float* __restrict__ O, int Lq, int Lk) {
    extern __shared__ char sm[];
    char* sK = sm;
    char* sV = sm + 16384;
    float* sQP = (float*)(sm + 32768);   // [64][68], Q then reused for P

    int tid = threadIdx.x, lane = tid & 31, w = tid >> 5;
    int gr = lane >> 2, lc = lane & 3;
    int qt = blockIdx.x, h = blockIdx.y, b = blockIdx.z;
    int wr = w * 16;
    const float scale = 0.125f;   // 1/sqrt(64)

    // load Q tile -> sQP (scaled fp32)
    const float* Qbase = Q + (size_t)(b * Lq + qt * 64) * qStride + h * 64;
    for (int i = tid; i < 1024; i += 128) {
        int r = i >> 4, c4 = (i & 15) * 4;
        float4 v = *(const float4*)(Qbase + (size_t)r * qStride + c4);
        float* p = &sQP[r * 68 + c4];
        p[0] = v.x * scale; p[1] = v.y * scale; p[2] = v.z * scale; p[3] = v.w * scale;
    }
    __syncthreads();

    // build Q A-fragments (registers, reused for all K tiles)
    uint32_t qf[8][4];
    #pragma unroll
    for (int ks = 0; ks < 8; ks++) {
        qf[ks][0] = tf32_bits(sQP[(wr + gr)     * 68 + ks * 8 + lc]);
        qf[ks][1] = tf32_bits(sQP[(wr + gr + 8) * 68 + ks * 8 + lc]);
        qf[ks][2] = tf32_bits(sQP[(wr + gr)     * 68 + ks * 8 + lc + 4]);
        qf[ks][3] = tf32_bits(sQP[(wr + gr + 8) * 68 + ks * 8 + lc + 4]);
    }
    __syncwarp();

    float oacc[8][4];
    #pragma unroll
    for (int fn = 0; fn < 8; fn++)
        #pragma unroll
        for (int e = 0; e < 4; e++) oacc[fn][e] = 0.f;
    float mrow[2] = { -1e30f, -1e30f };
    float lrow[2] = { 0.f, 0.f };

    const float* Kbase = K + (size_t)(b * Lk) * kStride + h * 64;
    const float* Vbase = V + (size_t)(b * Lk) * kStride + h * 64;
    int nkt = (Lk + 63) >> 6;

    for (int kt = 0; kt < nkt; kt++) {
        // stage K and V tiles into B-fragment layout (tf32)
        for (int i = tid; i < 1024; i += 128) {
            int r = i >> 4, d0 = (i & 15) * 4;
            int jg = kt * 64 + r;
            float4 kv = make_float4(0.f, 0.f, 0.f, 0.f);
            float4 vv = make_float4(0.f, 0.f, 0.f, 0.f);
            if (jg < Lk) {
                kv = *(const float4*)(Kbase + (size_t)jg * kStride + d0);
                vv = *(const float4*)(Vbase + (size_t)jg * kStride + d0);
            }
            float ka[4] = { kv.x, kv.y, kv.z, kv.w };
            float va[4] = { vv.x, vv.y, vv.z, vv.w };
            #pragma unroll
            for (int e = 0; e < 4; e++) {
                int d = d0 + e;
                // K: n=key(r), k=dim(d)
                *(uint32_t*)(sK + (((d >> 3) * 8 + (r >> 3)) * 32
                             + (r & 7) * 4 + (d & 3)) * 8 + ((d >> 2) & 1) * 4)
                    = tf32_bits(ka[e]);
                // V: k=key(r), n=dim(d)
                *(uint32_t*)(sV + (((r >> 3) * 8 + (d >> 3)) * 32
                             + (d & 7) * 4 + (r & 3)) * 8 + ((r >> 2) & 1) * 4)
                    = tf32_bits(va[e]);
            }
        }
        __syncthreads();

        // S = Q @ K^T
        float sacc[8][4];
        #pragma unroll
        for (int fn = 0; fn < 8; fn++)
            #pragma unroll
            for (int e = 0; e < 4; e++) sacc[fn][e] = 0.f;
        #pragma unroll
        for (int ks = 0; ks < 8; ks++) {
            #pragma unroll
            for (int fn = 0; fn < 8; fn++) {
                uint2 bb = *(const uint2*)(sK + ((ks * 8 + fn) * 32 + lane) * 8);
                mma_tf32(sacc[fn][0], sacc[fn][1], sacc[fn][2], sacc[fn][3],
                         qf[ks][0], qf[ks][1], qf[ks][2], qf[ks][3], bb.x, bb.y);
            }
        }

        // mask out-of-range keys
        if (kt * 64 + 64 > Lk) {
            #pragma unroll
            for (int fn = 0; fn < 8; fn++) {
                int key0 = kt * 64 + fn * 8 + 2 * lc;
                if (key0 >= Lk)     { sacc[fn][0] = -1e30f; sacc[fn][2] = -1e30f; }
                if (key0 + 1 >= Lk) { sacc[fn][1] = -1e30f; sacc[fn][3] = -1e30f; }
            }
        }

        // online softmax (rows gr, gr+8)
        #pragma unroll
        for (int hr = 0; hr < 2; hr++) {
            float rm = -1e30f;
            #pragma unroll
            for (int fn = 0; fn < 8; fn++)
                rm = fmaxf(rm, fmaxf(sacc[fn][hr * 2], sacc[fn][hr * 2 + 1]));
            rm = fmaxf(rm, __shfl_xor_sync(0xffffffffu, rm, 1));
            rm = fmaxf(rm, __shfl_xor_sync(0xffffffffu, rm, 2));
            float mn = fmaxf(mrow[hr], rm);
            float rs = 0.f;
            #pragma unroll
            for (int fn = 0; fn < 8; fn++) {
                float p0 = __expf(sacc[fn][hr * 2]     - mn);
                float p1 = __expf(sacc[fn][hr * 2 + 1] - mn);
                sacc[fn][hr * 2] = p0; sacc[fn][hr * 2 + 1] = p1;
                rs += p0 + p1;
            }
            rs += __shfl_xor_sync(0xffffffffu, rs, 1);
            rs += __shfl_xor_sync(0xffffffffu, rs, 2);
            float alpha = __expf(mrow[hr] - mn);
            lrow[hr] = lrow[hr] * alpha + rs;
            mrow[hr] = mn;
            #pragma unroll
            for (int fn = 0; fn < 8; fn++) {
                oacc[fn][hr * 2]     *= alpha;
                oacc[fn][hr * 2 + 1] *= alpha;
            }
        }

        // stage P into this warp's private rows of sQP (tf32-rounded fp32)
        #pragma unroll
        for (int fn = 0; fn < 8; fn++) {
            int col = fn * 8 + 2 * lc;
            sQP[(wr + gr)     * 68 + col]     = tf32_rna(sacc[fn][0]);
            sQP[(wr + gr)     * 68 + col + 1] = tf32_rna(sacc[fn][1]);
            sQP[(wr + gr + 8) * 68 + col]     = tf32_rna(sacc[fn][2]);
            sQP[(wr + gr + 8) * 68 + col + 1] = tf32_rna(sacc[fn][3]);
        }
        __syncwarp();

        // O += P @ V
        #pragma unroll
        for (int kg = 0; kg < 8; kg++) {
            uint32_t pa0 = __float_as_uint(sQP[(wr + gr)     * 68 + kg * 8 + lc]);
            uint32_t pa1 = __float_as_uint(sQP[(wr + gr + 8) * 68 + kg * 8 + lc]);
            uint32_t pa2 = __float_as_uint(sQP[(wr + gr)     * 68 + kg * 8 + lc + 4]);
            uint32_t pa3 = __float_as_uint(sQP[(wr + gr + 8) * 68 + kg * 8 + lc + 4]);
            #pragma unroll
            for (int fn = 0; fn < 8; fn++) {
                uint2 bb = *(const uint2*)(sV + ((kg * 8 + fn) * 32 + lane) * 8);
                mma_tf32(oacc[fn][0], oacc[fn][1], oacc[fn][2], oacc[fn][3],
                         pa0, pa1, pa2, pa3, bb.x, bb.y);
            }
        }
        __syncthreads();   // sK/sV (and per-warp sQP) safe to overwrite next tile
    }

    // epilogue
    float* Obase = O + (size_t)(b * Lq + qt * 64) * Dx + h * 64;
    #pragma unroll
    for (int hr = 0; hr < 2; hr++) {
        float inv = 1.f / lrow[hr];
        int row = wr + gr + hr * 8;
        #pragma unroll
        for (int fn = 0; fn < 8; fn++) {
            float2 o2 = make_float2(oacc[fn][hr * 2] * inv,
                                    oacc[fn][hr * 2 + 1] * inv);
            *(float2*)(Obase + (size_t)row * Dx + fn * 8 + 2 * lc) = o2;
        }
    }
}

// ----------------------------------------------------------------------------
// launch
// ----------------------------------------------------------------------------
static inline float* sym(const void* s) {
    void* p = nullptr;
    cudaGetSymbolAddress(&p, s);
    return (float*)p;
}

static inline void gemm(const float* A, const float* BT, const float* bias,
                        const float* res, float* C, int M, int N, int K, int act) {
    dim3 grid(N / 128, (M + 127) / 128);
    tf32_mma_gemm<<<grid, 512, GEMM_SMEM>>>(A, BT, bias, res, C, M, N, K, act);
}

extern "C" void kernel_launch(void* const* d_in, const int* in_sizes, int n_in,
                              void* d_out, int out_size) {
    const float* x     = (const float*)d_in[0];
    const float* c     = (const float*)d_in[1];
    const float* text  = (const float*)d_in[2];
    const float* W_ada = (const float*)d_in[3];
    const float* b_ada = (const float*)d_in[4];
    const float* W_qkv = (const float*)d_in[5];
    const float* b_qkv = (const float*)d_in[6];
    const float* W_proj= (const float*)d_in[7];
    const float* b_proj= (const float*)d_in[8];
    const float* W_ctx = (const float*)d_in[9];
    const float* b_ctx = (const float*)d_in[10];
    const float* W_q   = (const float*)d_in[11];
    const float* W_k   = (const float*)d_in[12];
    const float* W_v   = (const float*)d_in[13];
    const float* W_out = (const float*)d_in[14];
    const float* b_out = (const float*)d_in[15];
    const float* W_fc1 = (const float*)d_in[16];
    const float* b_fc1 = (const float*)d_in[17];
    const float* W_fc2 = (const float*)d_in[18];
    const float* b_fc2 = (const float*)d_in[19];
    float* out = (float*)d_out;

    float* mod   = sym(g_mod);
    float* h     = sym(g_h);
    float* qkv   = sym(g_qkv);
    float* attn  = sym(g_attn);
    float* x1    = sym(g_x1);
    float* x2    = sym(g_x2);
    float* ctx   = sym(g_ctx);
    float* q2    = sym(g_q2);
    float* k2v2  = sym(g_k2v2);
    float* hid   = sym(g_hidden);

    float* Wqkv_t = sym(g_Wqkv_t);
    float* Wproj_t= sym(g_Wproj_t);
    float* Wctx_t = sym(g_Wctx_t);
    float* Wq_t   = sym(g_Wq_t);
    float* Wkv_t  = sym(g_Wkv_t);
    float* Wout_t = sym(g_Wout_t);
    float* Wfc1_t = sym(g_Wfc1_t);
    float* Wfc2_t = sym(g_Wfc2_t);

    cudaFuncSetAttribute(attn_mma_kernel, cudaFuncAttributeMaxDynamicSharedMemorySize,
                         ATTN_SMEM);
    cudaFuncSetAttribute(tf32_mma_gemm, cudaFuncAttributeMaxDynamicSharedMemorySize,
                         GEMM_SMEM);

    dim3 tb(32, 8);
    // launches 0-5 ordered so ncu (-s 5) profiles the self-attention kernel
    transpose_rna_kernel<<<dim3(3 * Dx / 32, Dx / 32), tb>>>(W_qkv, Wqkv_t, Dx, 3 * Dx); // 0
    ada_mod_kernel<<<dim3(24, 4), 256>>>(c, W_ada, b_ada, mod);                          // 1
    ln_mod_kernel<<<ROWS, 256>>>(x, mod, h, 0);                                          // 2
    transpose_rna_kernel<<<dim3(Dx / 32, Dx / 32), tb>>>(W_proj, Wproj_t, Dx, Dx);       // 3
    gemm(h, Wqkv_t, b_qkv, nullptr, qkv, ROWS, 3 * Dx, Dx, ACT_NONE);                    // 4
    attn_mma_kernel<<<dim3(Nx / 64, Hx, Bx), 128, ATTN_SMEM>>>(                          // 5
        qkv, 3 * Dx, qkv + Dx, qkv + 2 * Dx, 3 * Dx, attn, Nx, Nx);
    gemm(attn, Wproj_t, b_proj, x, x1, ROWS, Dx, Dx, ACT_NONE);

    // remaining weight transposes
    transpose_rna_kernel<<<dim3(Dx / 32, TDx / 32), tb>>>(W_ctx, Wctx_t, TDx, Dx);
    transpose_rna_kernel<<<dim3(Dx / 32, Dx / 32), tb>>>(W_q, Wq_t, Dx, Dx);
    transpose_rna_kernel<<<dim3(Dx / 32, Dx / 32), tb>>>(W_k, Wkv_t, Dx, Dx);
    transpose_rna_kernel<<<dim3(Dx / 32, Dx / 32), tb>>>(W_v, Wkv_t + Dx * Dx, Dx, Dx);
    transpose_rna_kernel<<<dim3(Dx / 32, Dx / 32), tb>>>(W_out, Wout_t, Dx, Dx);
    transpose_rna_kernel<<<dim3(4 * Dx / 32, Dx / 32), tb>>>(W_fc1, Wfc1_t, Dx, 4 * Dx);
    transpose_rna_kernel<<<dim3(Dx / 32, 4 * Dx / 32), tb>>>(W_fc2, Wfc2_t, 4 * Dx, Dx);

    // --- cross attention ---
    ln_mod_kernel<<<ROWS, 256>>>(x1, mod, h, 2);
    gemm(text, Wctx_t, b_ctx, nullptr, ctx, CTXROWS, Dx, TDx, ACT_NONE);
    gemm(h, Wq_t, nullptr, nullptr, q2, ROWS, Dx, Dx, ACT_NONE);
    gemm(ctx, Wkv_t, nullptr, nullptr, k2v2, CTXROWS, 2 * Dx, Dx, ACT_NONE);
    attn_mma_kernel<<<dim3(Nx / 64, Hx, Bx), 128, ATTN_SMEM>>>(
        q2, Dx, k2v2, k2v2 + Dx, 2 * Dx, attn, Nx, TLx);
    gemm(attn, Wout_t, b_out, x1, x2, ROWS, Dx, Dx, ACT_NONE);

    // --- MLP ---
    ln_mod_kernel<<<ROWS, 256>>>(x2, mod, h, 4);
    gemm(h, Wfc1_t, b_fc1, nullptr, hid, ROWS, 4 * Dx, Dx, ACT_GELU);
    gemm(hid, Wfc2_t, b_fc2, x2, out, ROWS, Dx, 4 * Dx, ACT_NONE);
}

// round 7
// speedup vs baseline: 2.0973x; 1.0625x over previous
#include <cuda_runtime.h>
#include <cuda_bf16.h>
#include <cstdint>
#include <math.h>

// ----------------------------------------------------------------------------
// DiT block: adaLN -> self-attn -> cross-attn -> MLP (GELU tanh)
// Round 7 (= Round 6 resubmit after infra failure):
// cp.async 4-stage tf32 GEMM (plane-separated fragment layout),
// tf32 mma flash attention.
// ----------------------------------------------------------------------------

#define Bx 4
#define Nx 1024
#define Dx 1024
#define Hx 16
#define HDx 64
#define TDx 768
#define TLx 77
#define ROWS (Bx * Nx)       // 4096
#define CTXROWS (Bx * TLx)   // 308

// scratch (device globals; no runtime allocation allowed)
__device__ float g_mod[Bx * 6 * Dx];
__device__ float g_h[ROWS * Dx];
__device__ float g_qkv[ROWS * 3 * Dx];
__device__ float g_attn[ROWS * Dx];
__device__ float g_x1[ROWS * Dx];
__device__ float g_x2[ROWS * Dx];
__device__ float g_ctx[CTXROWS * Dx];
__device__ float g_q2[ROWS * Dx];
__device__ float g_k2v2[CTXROWS * 2 * Dx];
__device__ float g_hidden[ROWS * 4 * Dx];

// transposed (K-major [N,K]) tf32-rounded weights
__device__ float g_Wqkv_t[3 * Dx * Dx];
__device__ float g_Wproj_t[Dx * Dx];
__device__ float g_Wctx_t[Dx * TDx];
__device__ float g_Wq_t[Dx * Dx];
__device__ float g_Wkv_t[2 * Dx * Dx];   // [Wk ; Wv] stacked in N
__device__ float g_Wout_t[Dx * Dx];
__device__ float g_Wfc1_t[4 * Dx * Dx];
__device__ float g_Wfc2_t[4 * Dx * Dx];

// ----------------------------------------------------------------------------
// helpers
// ----------------------------------------------------------------------------
__device__ __forceinline__ uint32_t smem_u32(const void* p) {
    uint32_t a;
    asm("{ .reg .u64 t; cvta.to.shared.u64 t, %1; cvt.u32.u64 %0, t; }"
        : "=r"(a) : "l"(p));
    return a;
}
__device__ __forceinline__ float tf32_rna(float x) {
    uint32_t u;
    asm("cvt.rna.tf32.f32 %0, %1;" : "=r"(u) : "f"(x));
    return __uint_as_float(u);
}
__device__ __forceinline__ uint32_t tf32_bits(float x) {
    uint32_t u;
    asm("cvt.rna.tf32.f32 %0, %1;" : "=r"(u) : "f"(x));
    return u;
}
__device__ __forceinline__ void cp_async16(uint32_t saddr, const void* gaddr, int szbytes) {
    asm volatile("cp.async.cg.shared.global [%0], [%1], 16, %2;"
                 :: "r"(saddr), "l"(gaddr), "r"(szbytes) : "memory");
}
#define CP_COMMIT() asm volatile("cp.async.commit_group;" ::: "memory")
#define CP_WAIT(n)  asm volatile("cp.async.wait_group %0;" :: "n"(n) : "memory")

__device__ __forceinline__ void mma_tf32(float& c0, float& c1, float& c2, float& c3,
                                         uint32_t a0, uint32_t a1, uint32_t a2, uint32_t a3,
                                         uint32_t b0, uint32_t b1) {
    asm volatile(
        "mma.sync.aligned.m16n8k8.row.col.f32.tf32.tf32.f32 "
        "{%0,%1,%2,%3}, {%4,%5,%6,%7}, {%8,%9}, {%0,%1,%2,%3};"
        : "+f"(c0), "+f"(c1), "+f"(c2), "+f"(c3)
        : "r"(a0), "r"(a1), "r"(a2), "r"(a3), "r"(b0), "r"(b1));
}

// ----------------------------------------------------------------------------
// weight transpose: in[K,N] row-major -> out[N,K] row-major, tf32-rounded.
// ----------------------------------------------------------------------------
__global__ void transpose_rna_kernel(const float* __restrict__ in,
                                     float* __restrict__ out, int K, int N) {
    __shared__ float t[32][33];
    int n0 = blockIdx.x * 32, k0 = blockIdx.y * 32;
    int tx = threadIdx.x, ty = threadIdx.y;
    #pragma unroll
    for (int i = 0; i < 32; i += 8)
        t[ty + i][tx] = tf32_rna(in[(size_t)(k0 + ty + i) * N + n0 + tx]);
    __syncthreads();
    #pragma unroll
    for (int i = 0; i < 32; i += 8)
        out[(size_t)(n0 + ty + i) * K + k0 + tx] = t[tx][ty + i];
}

// ----------------------------------------------------------------------------
// adaLN modulation: mod = silu(c) @ W_ada + b_ada
// ----------------------------------------------------------------------------
__global__ void ada_mod_kernel(const float* __restrict__ c,
                               const float* __restrict__ Wada,
                               const float* __restrict__ bada,
                               float* __restrict__ mod) {
    __shared__ float sc[Dx];
    int b = blockIdx.y;
    for (int i = threadIdx.x; i < Dx; i += 256) {
        float v = c[b * Dx + i];
        sc[i] = v / (1.f + __expf(-v));
    }
    __syncthreads();
    int n = blockIdx.x * 256 + threadIdx.x;
    float acc = 0.f;
    for (int k = 0; k < Dx; k++)
        acc += sc[k] * Wada[(size_t)k * (6 * Dx) + n];
    mod[b * 6 * Dx + n] = acc + bada[n];
}

// ----------------------------------------------------------------------------
// LayerNorm + modulate
// ----------------------------------------------------------------------------
__global__ void ln_mod_kernel(const float* __restrict__ x,
                              const float* __restrict__ mod,
                              float* __restrict__ out, int chunk) {
    int row = blockIdx.x;
    int b = row >> 10;
    int tid = threadIdx.x;
    const float* xr = x + (size_t)row * Dx;
    float4 v = *(const float4*)(xr + tid * 4);
    float s = v.x + v.y + v.z + v.w;
    float ss = v.x * v.x + v.y * v.y + v.z * v.z + v.w * v.w;
    #pragma unroll
    for (int off = 16; off; off >>= 1) {
        s  += __shfl_xor_sync(0xffffffffu, s, off);
        ss += __shfl_xor_sync(0xffffffffu, ss, off);
    }
    __shared__ float rs[8], rss[8];
    int wid = tid >> 5, lane = tid & 31;
    if (!lane) { rs[wid] = s; rss[wid] = ss; }
    __syncthreads();
    s = 0.f; ss = 0.f;
    #pragma unroll
    for (int w = 0; w < 8; w++) { s += rs[w]; ss += rss[w]; }
    float mean = s * (1.f / Dx);
    float var = ss * (1.f / Dx) - mean * mean;
    float inv = rsqrtf(var + 1e-6f);
    const float* sh = mod + (size_t)b * 6 * Dx + (size_t)chunk * Dx;
    const float* scl = sh + Dx;
    int d = tid * 4;
    float4 o;
    o.x = (v.x - mean) * inv * (1.f + scl[d + 0]) + sh[d + 0];
    o.y = (v.y - mean) * inv * (1.f + scl[d + 1]) + sh[d + 1];
    o.z = (v.z - mean) * inv * (1.f + scl[d + 2]) + sh[d + 2];
    o.w = (v.w - mean) * inv * (1.f + scl[d + 3]) + sh[d + 3];
    *(float4*)(out + (size_t)row * Dx + d) = o;
}

// ----------------------------------------------------------------------------
// tf32 mma.sync GEMM with cp.async 4-stage pipeline.
// C[M,N] = A[M,K] @ BT[N,K]^T (+bias)(+GELU)(+res)
// 128x128 tile, BK=32, 512 threads (16 warps, 4x4), warp tile 32x32.
// Plane-separated fragment smem layout (per stage: A 16KB + B 16KB):
//   A, per (ks, fm): 4 planes (a0..a3) x 128B; word for lane L at
//       plane*128 + ((gr + ks + 4*khi) & 7)*16 + lc*4   (gr=L>>2, lc=L&3)
//   B, per (ks, fn): 2 planes (b0,b1) x 128B, same swizzle.
// Every 16B global segment (one row, 4 consecutive k) maps to one contiguous
// 16B smem segment -> cp.async.cg 16B, conflict-free stores and lds.32 reads.
// A is fed as raw fp32 (HW tf32 truncation); BT is pre-rounded (rna).
// ----------------------------------------------------------------------------
#define ACT_NONE 0
#define ACT_GELU 1
#define STAGES 4
#define GEMM_SMEM (STAGES * 32768)   // 128KB

__device__ __forceinline__ float gelu_tanh(float x) {
    float x3 = x * x * x;
    return 0.5f * x * (1.f + tanhf(0.7978845608028654f * (x + 0.044715f * x3)));
}

__global__ __launch_bounds__(512, 1)
void tf32_mma_gemm(const float* __restrict__ A, const float* __restrict__ BT,
                   const float* __restrict__ bias, const float* __restrict__ res,
                   float* __restrict__ C, int M, int N, int K, int act) {
    extern __shared__ char smem[];
    uint32_t sbase = smem_u32(smem);
    int tid = threadIdx.x, lane = tid & 31, wid = tid >> 5;
    int wm = wid >> 2, wn = wid & 3;
    int row0 = blockIdx.y * 128, col0 = blockIdx.x * 128;
    int gr = lane >> 2, lc = lane & 3;

    // producer: 2 A-chunks + 2 B-chunks (16B each) per thread per stage
    uint32_t offA[2], offB[2];
    const float* gAq[2];
    const float* gBq[2];
    int szA[2];
    #pragma unroll
    for (int i = 0; i < 2; i++) {
        int cch = tid + i * 512;
        int m = cch >> 3, q = cch & 7;
        int ks = q >> 1, qo = q & 1;
        int ai = ((m >> 3) & 1) + 2 * qo;
        int fm = m >> 4, gm = m & 7;
        offA[i] = (uint32_t)(((ks * 8 + fm) * 4 + ai) * 128
                             + (((gm + ks + 4 * qo) & 7) << 4));
        szA[i] = (row0 + m) < M ? 16 : 0;
        gAq[i] = A + (size_t)(row0 + m) * K + q * 4;
        int fn = m >> 3, gn = m & 7;
        offB[i] = (uint32_t)(((ks * 16 + fn) * 2 + qo) * 128
                             + (((gn + ks + 4 * qo) & 7) << 4));
        gBq[i] = BT + (size_t)(col0 + m) * K + q * 4;
    }

    float acc[2][4][4];
    #pragma unroll
    for (int im = 0; im < 2; im++)
        #pragma unroll
        for (int jn = 0; jn < 4; jn++)
            #pragma unroll
            for (int e = 0; e < 4; e++) acc[im][jn][e] = 0.f;

    int K32 = K >> 5;   // always >= 24 here

    // prologue: fill STAGES-1 stages
    #pragma unroll
    for (int s = 0; s < STAGES - 1; s++) {
        uint32_t sa = sbase + (uint32_t)(s * 32768);
        #pragma unroll
        for (int i = 0; i < 2; i++) {
            cp_async16(sa + offA[i], gAq[i] + (size_t)s * 32, szA[i]);
            cp_async16(sa + 16384u + offB[i], gBq[i] + (size_t)s * 32, 16);
        }
        CP_COMMIT();
    }

    for (int s = 0; s < K32; s++) {
        CP_WAIT(STAGES - 2);
        __syncthreads();
        uint32_t stoff = (uint32_t)((s % STAGES) * 32768);
        const char* sa = smem + stoff;
        const char* sb = smem + stoff + 16384;

        #pragma unroll
        for (int ks = 0; ks < 4; ks++) {
            uint32_t olo = (uint32_t)((((gr + ks) & 7) << 4) + (lc << 2));
            uint32_t ohi = (uint32_t)((((gr + ks + 4) & 7) << 4) + (lc << 2));
            uint32_t afr[2][4];
            #pragma unroll
            for (int im = 0; im < 2; im++) {
                const char* pb = sa + ((ks * 8 + wm * 2 + im) * 4) * 128;
                afr[im][0] = *(const uint32_t*)(pb + 0 * 128 + olo);
                afr[im][1] = *(const uint32_t*)(pb + 1 * 128 + olo);
                afr[im][2] = *(const uint32_t*)(pb + 2 * 128 + ohi);
                afr[im][3] = *(const uint32_t*)(pb + 3 * 128 + ohi);
            }
            uint32_t bfr[4][2];
            #pragma unroll
            for (int jn = 0; jn < 4; jn++) {
                const char* pb = sb + ((ks * 16 + wn * 4 + jn) * 2) * 128;
                bfr[jn][0] = *(const uint32_t*)(pb + olo);
                bfr[jn][1] = *(const uint32_t*)(pb + 128 + ohi);
            }
            #pragma unroll
            for (int im = 0; im < 2; im++)
                #pragma unroll
                for (int jn = 0; jn < 4; jn++)
                    mma_tf32(acc[im][jn][0], acc[im][jn][1],
                             acc[im][jn][2], acc[im][jn][3],
                             afr[im][0], afr[im][1], afr[im][2], afr[im][3],
                             bfr[jn][0], bfr[jn][1]);
        }

        // issue stage s+STAGES-1 (always commit to keep group accounting)
        int sn = s + STAGES - 1;
        if (sn < K32) {
            uint32_t sa2 = sbase + (uint32_t)((sn % STAGES) * 32768);
            #pragma unroll
            for (int i = 0; i < 2; i++) {
                cp_async16(sa2 + offA[i], gAq[i] + (size_t)sn * 32, szA[i]);
                cp_async16(sa2 + 16384u + offB[i], gBq[i] + (size_t)sn * 32, 16);
            }
        }
        CP_COMMIT();
    }

    // --- epilogue (C layout: rows gr/gr+8, cols 2lc within each m16n8) ---
    int egr = lane >> 2, egc = (lane & 3) * 2;
    #pragma unroll
    for (int im = 0; im < 2; im++) {
        #pragma unroll
        for (int half = 0; half < 2; half++) {
            int rg = row0 + wm * 32 + im * 16 + egr + half * 8;
            if (rg >= M) continue;
            #pragma unroll
            for (int jn = 0; jn < 4; jn++) {
                int cg = col0 + wn * 32 + jn * 8 + egc;
                float t0 = acc[im][jn][half * 2 + 0];
                float t1 = acc[im][jn][half * 2 + 1];
                if (bias) { t0 += bias[cg]; t1 += bias[cg + 1]; }
                if (act == ACT_GELU) { t0 = gelu_tanh(t0); t1 = gelu_tanh(t1); }
                if (res) {
                    t0 += res[(size_t)rg * N + cg];
                    t1 += res[(size_t)rg * N + cg + 1];
                }
                *(float2*)(C + (size_t)rg * N + cg) = make_float2(t0, t1);
            }
        }
    }
}

// ----------------------------------------------------------------------------
// tf32 mma.sync flash attention (proven in round 5)
// ----------------------------------------------------------------------------
#define ATTN_SMEM (16384 + 16384 + 64 * 68 * 4)

__global__ __launch_bounds__(128, 2)
void attn_mma_kernel(const float* __restrict__ Q, int qStride,
                     const float* __restrict__ K, const float* __restrict__ V,
                     int kStride, float* __restrict__ O, int Lq, int Lk) {
    extern __shared__ char sm[];
    char* sK = sm;
    char* sV = sm + 16384;
    float* sQP = (float*)(sm + 32768);   // [64][68]

    int tid = threadIdx.x, lane = tid & 31, w = tid >> 5;
    int gr = lane >> 2, lc = lane & 3;
    int qt = blockIdx.x, h = blockIdx.y, b = blockIdx.z;
    int wr = w * 16;
    const float scale = 0.125f;

    const float* Qbase = Q + (size_t)(b * Lq + qt * 64) * qStride + h * 64;
    for (int i = tid; i < 1024; i += 128) {
        int r = i >> 4, c4 = (i & 15) * 4;
        float4 v = *(const float4*)(Qbase + (size_t)r * qStride + c4);
        float* p = &sQP[r * 68 + c4];
        p[0] = v.x * scale; p[1] = v.y * scale; p[2] = v.z * scale; p[3] = v.w * scale;
    }
    __syncthreads();

    uint32_t qf[8][4];
    #pragma unroll
    for (int ks = 0; ks < 8; ks++) {
        qf[ks][0] = tf32_bits(sQP[(wr + gr)     * 68 + ks * 8 + lc]);
        qf[ks][1] = tf32_bits(sQP[(wr + gr + 8) * 68 + ks * 8 + lc]);
        qf[ks][2] = tf32_bits(sQP[(wr + gr)     * 68 + ks * 8 + lc + 4]);
        qf[ks][3] = tf32_bits(sQP[(wr + gr + 8) * 68 + ks * 8 + lc + 4]);
    }
    __syncwarp();

    float oacc[8][4];
    #pragma unroll
    for (int fn = 0; fn < 8; fn++)
        #pragma unroll
        for (int e = 0; e < 4; e++) oacc[fn][e] = 0.f;
    float mrow[2] = { -1e30f, -1e30f };
    float lrow[2] = { 0.f, 0.f };

    const float* Kbase = K + (size_t)(b * Lk) * kStride + h * 64;
    const float* Vbase = V + (size_t)(b * Lk) * kStride + h * 64;
    int nkt = (Lk + 63) >> 6;

    for (int kt = 0; kt < nkt; kt++) {
        for (int i = tid; i < 1024; i += 128) {
            int r = i >> 4, d0 = (i & 15) * 4;
            int jg = kt * 64 + r;
            float4 kv = make_float4(0.f, 0.f, 0.f, 0.f);
            float4 vv = make_float4(0.f, 0.f, 0.f, 0.f);
            if (jg < Lk) {
                kv = *(const float4*)(Kbase + (size_t)jg * kStride + d0);
                vv = *(const float4*)(Vbase + (size_t)jg * kStride + d0);
            }
            float ka[4] = { kv.x, kv.y, kv.z, kv.w };
            float va[4] = { vv.x, vv.y, vv.z, vv.w };
            #pragma unroll
            for (int e = 0; e < 4; e++) {
                int d = d0 + e;
                *(uint32_t*)(sK + (((d >> 3) * 8 + (r >> 3)) * 32
                             + (r & 7) * 4 + (d & 3)) * 8 + ((d >> 2) & 1) * 4)
                    = tf32_bits(ka[e]);
                *(uint32_t*)(sV + (((r >> 3) * 8 + (d >> 3)) * 32
                             + (d & 7) * 4 + (r & 3)) * 8 + ((r >> 2) & 1) * 4)
                    = tf32_bits(va[e]);
            }
        }
        __syncthreads();

        float sacc[8][4];
        #pragma unroll
        for (int fn = 0; fn < 8; fn++)
            #pragma unroll
            for (int e = 0; e < 4; e++) sacc[fn][e] = 0.f;
        #pragma unroll
        for (int ks = 0; ks < 8; ks++) {
            #pragma unroll
            for (int fn = 0; fn < 8; fn++) {
                uint2 bb = *(const uint2*)(sK + ((ks * 8 + fn) * 32 + lane) * 8);
                mma_tf32(sacc[fn][0], sacc[fn][1], sacc[fn][2], sacc[fn][3],
                         qf[ks][0], qf[ks][1], qf[ks][2], qf[ks][3], bb.x, bb.y);
            }
        }

        if (kt * 64 + 64 > Lk) {
            #pragma unroll
            for (int fn = 0; fn < 8; fn++) {
                int key0 = kt * 64 + fn * 8 + 2 * lc;
                if (key0 >= Lk)     { sacc[fn][0] = -1e30f; sacc[fn][2] = -1e30f; }
                if (key0 + 1 >= Lk) { sacc[fn][1] = -1e30f; sacc[fn][3] = -1e30f; }
            }
        }

        #pragma unroll
        for (int hr = 0; hr < 2; hr++) {
            float rm = -1e30f;
            #pragma unroll
            for (int fn = 0; fn < 8; fn++)
                rm = fmaxf(rm, fmaxf(sacc[fn][hr * 2], sacc[fn][hr * 2 + 1]));
            rm = fmaxf(rm, __shfl_xor_sync(0xffffffffu, rm, 1));
            rm = fmaxf(rm, __shfl_xor_sync(0xffffffffu, rm, 2));
            float mn = fmaxf(mrow[hr], rm);
            float rs = 0.f;
            #pragma unroll
            for (int fn = 0; fn < 8; fn++) {
                float p0 = __expf(sacc[fn][hr * 2]     - mn);
                float p1 = __expf(sacc[fn][hr * 2 + 1] - mn);
                sacc[fn][hr * 2] = p0; sacc[fn][hr * 2 + 1] = p1;
                rs += p0 + p1;
            }
            rs += __shfl_xor_sync(0xffffffffu, rs, 1);
            rs += __shfl_xor_sync(0xffffffffu, rs, 2);
            float alpha = __expf(mrow[hr] - mn);
            lrow[hr] = lrow[hr] * alpha + rs;
            mrow[hr] = mn;
            #pragma unroll
            for (int fn = 0; fn < 8; fn++) {
                oacc[fn][hr * 2]     *= alpha;
                oacc[fn][hr * 2 + 1] *= alpha;
            }
        }

        #pragma unroll
        for (int fn = 0; fn < 8; fn++) {
            int col = fn * 8 + 2 * lc;
            sQP[(wr + gr)     * 68 + col]     = tf32_rna(sacc[fn][0]);
            sQP[(wr + gr)     * 68 + col + 1] = tf32_rna(sacc[fn][1]);
            sQP[(wr + gr + 8) * 68 + col]     = tf32_rna(sacc[fn][2]);
            sQP[(wr + gr + 8) * 68 + col + 1] = tf32_rna(sacc[fn][3]);
        }
        __syncwarp();

        #pragma unroll
        for (int kg = 0; kg < 8; kg++) {
            uint32_t pa0 = __float_as_uint(sQP[(wr + gr)     * 68 + kg * 8 + lc]);
            uint32_t pa1 = __float_as_uint(sQP[(wr + gr + 8) * 68 + kg * 8 + lc]);
            uint32_t pa2 = __float_as_uint(sQP[(wr + gr)     * 68 + kg * 8 + lc + 4]);
            uint32_t pa3 = __float_as_uint(sQP[(wr + gr + 8) * 68 + kg * 8 + lc + 4]);
            #pragma unroll
            for (int fn = 0; fn < 8; fn++) {
                uint2 bb = *(const uint2*)(sV + ((kg * 8 + fn) * 32 + lane) * 8);
                mma_tf32(oacc[fn][0], oacc[fn][1], oacc[fn][2], oacc[fn][3],
                         pa0, pa1, pa2, pa3, bb.x, bb.y);
            }
        }
        __syncthreads();
    }

    float* Obase = O + (size_t)(b * Lq + qt * 64) * Dx + h * 64;
    #pragma unroll
    for (int hr = 0; hr < 2; hr++) {
        float inv = 1.f / lrow[hr];
        int row = wr + gr + hr * 8;
        #pragma unroll
        for (int fn = 0; fn < 8; fn++) {
            float2 o2 = make_float2(oacc[fn][hr * 2] * inv,
                                    oacc[fn][hr * 2 + 1] * inv);
            *(float2*)(Obase + (size_t)row * Dx + fn * 8 + 2 * lc) = o2;
        }
    }
}

// ----------------------------------------------------------------------------
// launch
// ----------------------------------------------------------------------------
static inline float* sym(const void* s) {
    void* p = nullptr;
    cudaGetSymbolAddress(&p, s);
    return (float*)p;
}

static inline void gemm(const float* A, const float* BT, const float* bias,
                        const float* res, float* C, int M, int N, int K, int act) {
    dim3 grid(N / 128, (M + 127) / 128);
    tf32_mma_gemm<<<grid, 512, GEMM_SMEM>>>(A, BT, bias, res, C, M, N, K, act);
}

extern "C" void kernel_launch(void* const* d_in, const int* in_sizes, int n_in,
                              void* d_out, int out_size) {
    const float* x     = (const float*)d_in[0];
    const float* c     = (const float*)d_in[1];
    const float* text  = (const float*)d_in[2];
    const float* W_ada = (const float*)d_in[3];
    const float* b_ada = (const float*)d_in[4];
    const float* W_qkv = (const float*)d_in[5];
    const float* b_qkv = (const float*)d_in[6];
    const float* W_proj= (const float*)d_in[7];
    const float* b_proj= (const float*)d_in[8];
    const float* W_ctx = (const float*)d_in[9];
    const float* b_ctx = (const float*)d_in[10];
    const float* W_q   = (const float*)d_in[11];
    const float* W_k   = (const float*)d_in[12];
    const float* W_v   = (const float*)d_in[13];
    const float* W_out = (const float*)d_in[14];
    const float* b_out = (const float*)d_in[15];
    const float* W_fc1 = (const float*)d_in[16];
    const float* b_fc1 = (const float*)d_in[17];
    const float* W_fc2 = (const float*)d_in[18];
    const float* b_fc2 = (const float*)d_in[19];
    float* out = (float*)d_out;

    float* mod   = sym(g_mod);
    float* h     = sym(g_h);
    float* qkv   = sym(g_qkv);
    float* attn  = sym(g_attn);
    float* x1    = sym(g_x1);
    float* x2    = sym(g_x2);
    float* ctx   = sym(g_ctx);
    float* q2    = sym(g_q2);
    float* k2v2  = sym(g_k2v2);
    float* hid   = sym(g_hidden);

    float* Wqkv_t = sym(g_Wqkv_t);
    float* Wproj_t= sym(g_Wproj_t);
    float* Wctx_t = sym(g_Wctx_t);
    float* Wq_t   = sym(g_Wq_t);
    float* Wkv_t  = sym(g_Wkv_t);
    float* Wout_t = sym(g_Wout_t);
    float* Wfc1_t = sym(g_Wfc1_t);
    float* Wfc2_t = sym(g_Wfc2_t);

    cudaFuncSetAttribute(attn_mma_kernel, cudaFuncAttributeMaxDynamicSharedMemorySize,
                         ATTN_SMEM);
    cudaFuncSetAttribute(tf32_mma_gemm, cudaFuncAttributeMaxDynamicSharedMemorySize,
                         GEMM_SMEM);

    dim3 tb(32, 8);
    // launches 0-5 ordered so ncu (-s 5 -c 1) profiles the qkv GEMM
    transpose_rna_kernel<<<dim3(3 * Dx / 32, Dx / 32), tb>>>(W_qkv, Wqkv_t, Dx, 3 * Dx); // 0
    ada_mod_kernel<<<dim3(24, 4), 256>>>(c, W_ada, b_ada, mod);                          // 1
    ln_mod_kernel<<<ROWS, 256>>>(x, mod, h, 0);                                          // 2
    transpose_rna_kernel<<<dim3(Dx / 32, Dx / 32), tb>>>(W_proj, Wproj_t, Dx, Dx);       // 3
    transpose_rna_kernel<<<dim3(4 * Dx / 32, Dx / 32), tb>>>(W_fc1, Wfc1_t, Dx, 4 * Dx); // 4
    gemm(h, Wqkv_t, b_qkv, nullptr, qkv, ROWS, 3 * Dx, Dx, ACT_NONE);                    // 5
    attn_mma_kernel<<<dim3(Nx / 64, Hx, Bx), 128, ATTN_SMEM>>>(
        qkv, 3 * Dx, qkv + Dx, qkv + 2 * Dx, 3 * Dx, attn, Nx, Nx);
    gemm(attn, Wproj_t, b_proj, x, x1, ROWS, Dx, Dx, ACT_NONE);

    // remaining weight transposes
    transpose_rna_kernel<<<dim3(Dx / 32, TDx / 32), tb>>>(W_ctx, Wctx_t, TDx, Dx);
    transpose_rna_kernel<<<dim3(Dx / 32, Dx / 32), tb>>>(W_q, Wq_t, Dx, Dx);
    transpose_rna_kernel<<<dim3(Dx / 32, Dx / 32), tb>>>(W_k, Wkv_t, Dx, Dx);
    transpose_rna_kernel<<<dim3(Dx / 32, Dx / 32), tb>>>(W_v, Wkv_t + Dx * Dx, Dx, Dx);
    transpose_rna_kernel<<<dim3(Dx / 32, Dx / 32), tb>>>(W_out, Wout_t, Dx, Dx);
    transpose_rna_kernel<<<dim3(Dx / 32, 4 * Dx / 32), tb>>>(W_fc2, Wfc2_t, 4 * Dx, Dx);

    // --- cross attention ---
    ln_mod_kernel<<<ROWS, 256>>>(x1, mod, h, 2);
    gemm(text, Wctx_t, b_ctx, nullptr, ctx, CTXROWS, Dx, TDx, ACT_NONE);
    gemm(h, Wq_t, nullptr, nullptr, q2, ROWS, Dx, Dx, ACT_NONE);
    gemm(ctx, Wkv_t, nullptr, nullptr, k2v2, CTXROWS, 2 * Dx, Dx, ACT_NONE);
    attn_mma_kernel<<<dim3(Nx / 64, Hx, Bx), 128, ATTN_SMEM>>>(
        q2, Dx, k2v2, k2v2 + Dx, 2 * Dx, attn, Nx, TLx);
    gemm(attn, Wout_t, b_out, x1, x2, ROWS, Dx, Dx, ACT_NONE);

    // --- MLP ---
    ln_mod_kernel<<<ROWS, 256>>>(x2, mod, h, 4);
    gemm(h, Wfc1_t, b_fc1, nullptr, hid, ROWS, 4 * Dx, Dx, ACT_GELU);
    gemm(hid, Wfc2_t, b_fc2, x2, out, ROWS, Dx, 4 * Dx, ACT_NONE);
}

// round 8
// speedup vs baseline: 4.6662x; 2.2248x over previous
#include <cuda_runtime.h>
#include <cuda_fp16.h>
#include <cstdint>
#include <math.h>

// ----------------------------------------------------------------------------
// DiT block: adaLN -> self-attn -> cross-attn -> MLP (GELU tanh)
// Round 8: fp16 ldmatrix/mma.m16n8k16 GEMMs (cp.async 3-stage), tf32 mma attn.
// ----------------------------------------------------------------------------

#define Bx 4
#define Nx 1024
#define Dx 1024
#define Hx 16
#define HDx 64
#define TDx 768
#define TLx 77
#define ROWS (Bx * Nx)       // 4096
#define CTXROWS (Bx * TLx)   // 308

// fp32 scratch
__device__ float g_mod[Bx * 6 * Dx];
__device__ float g_qkv[ROWS * 3 * Dx];
__device__ float g_x1[ROWS * Dx];
__device__ float g_x2[ROWS * Dx];
__device__ float g_q2[ROWS * Dx];
__device__ float g_k2v2[CTXROWS * 2 * Dx];
// half scratch (GEMM A-operands)
__device__ __half g_h[ROWS * Dx];
__device__ __half g_attn_h[ROWS * Dx];
__device__ __half g_ctx_h[CTXROWS * Dx];
__device__ __half g_text_h[CTXROWS * TDx];
__device__ __half g_hid_h[ROWS * 4 * Dx];
// transposed (K-major [N,K]) fp16 weights
__device__ __half g_Wqkv_t[3 * Dx * Dx];
__device__ __half g_Wproj_t[Dx * Dx];
__device__ __half g_Wctx_t[Dx * TDx];
__device__ __half g_Wq_t[Dx * Dx];
__device__ __half g_Wkv_t[2 * Dx * Dx];
__device__ __half g_Wout_t[Dx * Dx];
__device__ __half g_Wfc1_t[4 * Dx * Dx];
__device__ __half g_Wfc2_t[4 * Dx * Dx];

// ----------------------------------------------------------------------------
// helpers
// ----------------------------------------------------------------------------
__device__ __forceinline__ uint32_t smem_u32(const void* p) {
    uint32_t a;
    asm("{ .reg .u64 t; cvta.to.shared.u64 t, %1; cvt.u32.u64 %0, t; }"
        : "=r"(a) : "l"(p));
    return a;
}
__device__ __forceinline__ float tf32_rna(float x) {
    uint32_t u;
    asm("cvt.rna.tf32.f32 %0, %1;" : "=r"(u) : "f"(x));
    return __uint_as_float(u);
}
__device__ __forceinline__ uint32_t tf32_bits(float x) {
    uint32_t u;
    asm("cvt.rna.tf32.f32 %0, %1;" : "=r"(u) : "f"(x));
    return u;
}
__device__ __forceinline__ void cp_async16(uint32_t saddr, const void* gaddr, int szbytes) {
    asm volatile("cp.async.cg.shared.global [%0], [%1], 16, %2;"
                 :: "r"(saddr), "l"(gaddr), "r"(szbytes) : "memory");
}
#define CP_COMMIT() asm volatile("cp.async.commit_group;" ::: "memory")
#define CP_WAIT(n)  asm volatile("cp.async.wait_group %0;" :: "n"(n) : "memory")

#define LDMATRIX_X4(r0, r1, r2, r3, addr) \
    asm volatile("ldmatrix.sync.aligned.m8n8.x4.shared.b16 {%0,%1,%2,%3}, [%4];" \
                 : "=r"(r0), "=r"(r1), "=r"(r2), "=r"(r3) : "r"(addr))

__device__ __forceinline__ void mma_f16(float& c0, float& c1, float& c2, float& c3,
                                        uint32_t a0, uint32_t a1, uint32_t a2, uint32_t a3,
                                        uint32_t b0, uint32_t b1) {
    asm volatile(
        "mma.sync.aligned.m16n8k16.row.col.f32.f16.f16.f32 "
        "{%0,%1,%2,%3}, {%4,%5,%6,%7}, {%8,%9}, {%0,%1,%2,%3};"
        : "+f"(c0), "+f"(c1), "+f"(c2), "+f"(c3)
        : "r"(a0), "r"(a1), "r"(a2), "r"(a3), "r"(b0), "r"(b1));
}

__device__ __forceinline__ void mma_tf32(float& c0, float& c1, float& c2, float& c3,
                                         uint32_t a0, uint32_t a1, uint32_t a2, uint32_t a3,
                                         uint32_t b0, uint32_t b1) {
    asm volatile(
        "mma.sync.aligned.m16n8k8.row.col.f32.tf32.tf32.f32 "
        "{%0,%1,%2,%3}, {%4,%5,%6,%7}, {%8,%9}, {%0,%1,%2,%3};"
        : "+f"(c0), "+f"(c1), "+f"(c2), "+f"(c3)
        : "r"(a0), "r"(a1), "r"(a2), "r"(a3), "r"(b0), "r"(b1));
}

// ----------------------------------------------------------------------------
// weight transpose: in[K,N] fp32 -> out[N,K] fp16 (rne)
// ----------------------------------------------------------------------------
__global__ void transpose_h_kernel(const float* __restrict__ in,
                                   __half* __restrict__ out, int K, int N) {
    __shared__ float t[32][33];
    int n0 = blockIdx.x * 32, k0 = blockIdx.y * 32;
    int tx = threadIdx.x, ty = threadIdx.y;
    #pragma unroll
    for (int i = 0; i < 32; i += 8)
        t[ty + i][tx] = in[(size_t)(k0 + ty + i) * N + n0 + tx];
    __syncthreads();
    #pragma unroll
    for (int i = 0; i < 32; i += 8)
        out[(size_t)(n0 + ty + i) * K + k0 + tx] = __float2half(t[tx][ty + i]);
}

// fp32 -> fp16 elementwise
__global__ void f2h_kernel(const float* __restrict__ in, __half* __restrict__ out, int n) {
    int i = blockIdx.x * 256 + threadIdx.x;
    if (i < n) out[i] = __float2half(in[i]);
}

// ----------------------------------------------------------------------------
// adaLN modulation: mod = silu(c) @ W_ada + b_ada
// ----------------------------------------------------------------------------
__global__ void ada_mod_kernel(const float* __restrict__ c,
                               const float* __restrict__ Wada,
                               const float* __restrict__ bada,
                               float* __restrict__ mod) {
    __shared__ float sc[Dx];
    int b = blockIdx.y;
    for (int i = threadIdx.x; i < Dx; i += 256) {
        float v = c[b * Dx + i];
        sc[i] = v / (1.f + __expf(-v));
    }
    __syncthreads();
    int n = blockIdx.x * 256 + threadIdx.x;
    float acc = 0.f;
    for (int k = 0; k < Dx; k++)
        acc += sc[k] * Wada[(size_t)k * (6 * Dx) + n];
    mod[b * 6 * Dx + n] = acc + bada[n];
}

// ----------------------------------------------------------------------------
// LayerNorm + modulate -> fp16 output
// ----------------------------------------------------------------------------
__global__ void ln_mod_kernel(const float* __restrict__ x,
                              const float* __restrict__ mod,
                              __half* __restrict__ out, int chunk) {
    int row = blockIdx.x;
    int b = row >> 10;
    int tid = threadIdx.x;
    const float* xr = x + (size_t)row * Dx;
    float4 v = *(const float4*)(xr + tid * 4);
    float s = v.x + v.y + v.z + v.w;
    float ss = v.x * v.x + v.y * v.y + v.z * v.z + v.w * v.w;
    #pragma unroll
    for (int off = 16; off; off >>= 1) {
        s  += __shfl_xor_sync(0xffffffffu, s, off);
        ss += __shfl_xor_sync(0xffffffffu, ss, off);
    }
    __shared__ float rs[8], rss[8];
    int wid = tid >> 5, lane = tid & 31;
    if (!lane) { rs[wid] = s; rss[wid] = ss; }
    __syncthreads();
    s = 0.f; ss = 0.f;
    #pragma unroll
    for (int w = 0; w < 8; w++) { s += rs[w]; ss += rss[w]; }
    float mean = s * (1.f / Dx);
    float var = ss * (1.f / Dx) - mean * mean;
    float inv = rsqrtf(var + 1e-6f);
    const float* sh = mod + (size_t)b * 6 * Dx + (size_t)chunk * Dx;
    const float* scl = sh + Dx;
    int d = tid * 4;
    float o0 = (v.x - mean) * inv * (1.f + scl[d + 0]) + sh[d + 0];
    float o1 = (v.y - mean) * inv * (1.f + scl[d + 1]) + sh[d + 1];
    float o2 = (v.z - mean) * inv * (1.f + scl[d + 2]) + sh[d + 2];
    float o3 = (v.w - mean) * inv * (1.f + scl[d + 3]) + sh[d + 3];
    __half2* op = (__half2*)(out + (size_t)row * Dx + d);
    op[0] = __floats2half2_rn(o0, o1);
    op[1] = __floats2half2_rn(o2, o3);
}

// ----------------------------------------------------------------------------
// fp16 mma.sync GEMM with cp.async 3-stage pipeline + ldmatrix.
// C[M,N] = A[M,K] @ BT[N,K]^T (+bias)(+GELU)(+res), fp32 accum.
// 128x128 tile, BK=64 (128B half rows), 512 threads, warp tile 32x32.
// smem/stage: A 16KB + B 16KB, XOR swizzle: addr(r,c8)=r*128 + ((c8^(r&7))<<4).
// Output: fp32 (Cf) or fp16 (Ch).
// ----------------------------------------------------------------------------
#define ACT_NONE 0
#define ACT_GELU 1
#define STAGES 3
#define GEMM_SMEM (STAGES * 32768)   // 96KB

__device__ __forceinline__ float gelu_tanh(float x) {
    float x3 = x * x * x;
    return 0.5f * x * (1.f + tanhf(0.7978845608028654f * (x + 0.044715f * x3)));
}

__global__ __launch_bounds__(512, 1)
void h_mma_gemm(const __half* __restrict__ A, const __half* __restrict__ BT,
                const float* __restrict__ bias, const float* __restrict__ res,
                float* __restrict__ Cf, __half* __restrict__ Ch,
                int M, int N, int K, int act) {
    extern __shared__ char smem[];
    uint32_t sbase = smem_u32(smem);
    int tid = threadIdx.x, lane = tid & 31, wid = tid >> 5;
    int wm = wid >> 2, wn = wid & 3;
    int row0 = blockIdx.y * 128, col0 = blockIdx.x * 128;

    // producer: 2 A-chunks + 2 B-chunks (16B = 8 halves) per thread per stage
    uint32_t offAB[2];
    const __half* gA[2];
    const __half* gB[2];
    int szA[2];
    #pragma unroll
    for (int i = 0; i < 2; i++) {
        int idx = tid + i * 512;         // 0..1023
        int r = idx >> 3, c8 = idx & 7;
        offAB[i] = (uint32_t)(r * 128 + ((c8 ^ (r & 7)) << 4));
        szA[i] = (row0 + r) < M ? 16 : 0;
        gA[i] = A + (size_t)(row0 + r) * K + c8 * 8;
        gB[i] = BT + (size_t)(col0 + r) * K + c8 * 8;
    }

    float acc[2][4][4];
    #pragma unroll
    for (int im = 0; im < 2; im++)
        #pragma unroll
        for (int jn = 0; jn < 4; jn++)
            #pragma unroll
            for (int e = 0; e < 4; e++) acc[im][jn][e] = 0.f;

    int K64 = K >> 6;

    // prologue
    #pragma unroll
    for (int s = 0; s < STAGES - 1; s++) {
        uint32_t sa = sbase + (uint32_t)(s * 32768);
        #pragma unroll
        for (int i = 0; i < 2; i++) {
            cp_async16(sa + offAB[i], gA[i] + (size_t)s * 64, szA[i]);
            cp_async16(sa + 16384u + offAB[i], gB[i] + (size_t)s * 64, 16);
        }
        CP_COMMIT();
    }

    // ldmatrix lane addressing (within a 16x16 quad of 8x8 matrices)
    int lrA = (lane & 7) | (lane & 8);          // A: row within 16
    int lkA8 = (lane >> 4) << 3;                // A: +8 k for lanes 16-31
    int lrB = (lane & 7) | ((lane & 16) >> 1);  // B: n within 16
    int lkB8 = lane & 8;                        // B: +8 k for lanes 8-15/24-31

    for (int s = 0; s < K64; s++) {
        CP_WAIT(STAGES - 2);
        __syncthreads();
        uint32_t sa = sbase + (uint32_t)((s % STAGES) * 32768);
        uint32_t sb = sa + 16384u;

        #pragma unroll
        for (int kg = 0; kg < 4; kg++) {
            int lkA = kg * 16 + lkA8;
            int lkB = kg * 16 + lkB8;
            uint32_t areg[2][4];
            #pragma unroll
            for (int im = 0; im < 2; im++) {
                int r = wm * 32 + im * 16 + lrA;
                uint32_t addr = sa + (uint32_t)(r * 128 + (((lkA >> 3) ^ (r & 7)) << 4));
                LDMATRIX_X4(areg[im][0], areg[im][1], areg[im][2], areg[im][3], addr);
            }
            uint32_t breg[2][4];
            #pragma unroll
            for (int p = 0; p < 2; p++) {
                int r = wn * 32 + p * 16 + lrB;
                uint32_t addr = sb + (uint32_t)(r * 128 + (((lkB >> 3) ^ (r & 7)) << 4));
                LDMATRIX_X4(breg[p][0], breg[p][1], breg[p][2], breg[p][3], addr);
            }
            #pragma unroll
            for (int im = 0; im < 2; im++)
                #pragma unroll
                for (int jn = 0; jn < 4; jn++) {
                    int p = jn >> 1, q = (jn & 1) * 2;
                    mma_f16(acc[im][jn][0], acc[im][jn][1],
                            acc[im][jn][2], acc[im][jn][3],
                            areg[im][0], areg[im][1], areg[im][2], areg[im][3],
                            breg[p][q], breg[p][q + 1]);
                }
        }

        int sn = s + STAGES - 1;
        if (sn < K64) {
            uint32_t sa2 = sbase + (uint32_t)((sn % STAGES) * 32768);
            #pragma unroll
            for (int i = 0; i < 2; i++) {
                cp_async16(sa2 + offAB[i], gA[i] + (size_t)sn * 64, szA[i]);
                cp_async16(sa2 + 16384u + offAB[i], gB[i] + (size_t)sn * 64, 16);
            }
        }
        CP_COMMIT();
    }

    // epilogue (m16n8 C layout: rows gr/gr+8, cols 2lc/2lc+1)
    int egr = lane >> 2, egc = (lane & 3) * 2;
    #pragma unroll
    for (int im = 0; im < 2; im++) {
        #pragma unroll
        for (int half = 0; half < 2; half++) {
            int rg = row0 + wm * 32 + im * 16 + egr + half * 8;
            if (rg >= M) continue;
            #pragma unroll
            for (int jn = 0; jn < 4; jn++) {
                int cg = col0 + wn * 32 + jn * 8 + egc;
                float t0 = acc[im][jn][half * 2 + 0];
                float t1 = acc[im][jn][half * 2 + 1];
                if (bias) { t0 += bias[cg]; t1 += bias[cg + 1]; }
                if (act == ACT_GELU) { t0 = gelu_tanh(t0); t1 = gelu_tanh(t1); }
                if (res) {
                    t0 += res[(size_t)rg * N + cg];
                    t1 += res[(size_t)rg * N + cg + 1];
                }
                if (Ch) {
                    *(__half2*)(Ch + (size_t)rg * N + cg) = __floats2half2_rn(t0, t1);
                } else {
                    *(float2*)(Cf + (size_t)rg * N + cg) = make_float2(t0, t1);
                }
            }
        }
    }
}

// ----------------------------------------------------------------------------
// tf32 mma.sync flash attention (proven; output now fp16)
// ----------------------------------------------------------------------------
#define ATTN_SMEM (16384 + 16384 + 64 * 68 * 4)

__global__ __launch_bounds__(128, 2)
void attn_mma_kernel(const float* __restrict__ Q, int qStride,
                     const float* __restrict__ K, const float* __restrict__ V,
                     int kStride, __half* __restrict__ O, int Lq, int Lk) {
    extern __shared__ char sm[];
    char* sK = sm;
    char* sV = sm + 16384;
    float* sQP = (float*)(sm + 32768);   // [64][68]

    int tid = threadIdx.x, lane = tid & 31, w = tid >> 5;
    int gr = lane >> 2, lc = lane & 3;
    int qt = blockIdx.x, h = blockIdx.y, b = blockIdx.z;
    int wr = w * 16;
    const float scale = 0.125f;

    const float* Qbase = Q + (size_t)(b * Lq + qt * 64) * qStride + h * 64;
    for (int i = tid; i < 1024; i += 128) {
        int r = i >> 4, c4 = (i & 15) * 4;
        float4 v = *(const float4*)(Qbase + (size_t)r * qStride + c4);
        float* p = &sQP[r * 68 + c4];
        p[0] = v.x * scale; p[1] = v.y * scale; p[2] = v.z * scale; p[3] = v.w * scale;
    }
    __syncthreads();

    uint32_t qf[8][4];
    #pragma unroll
    for (int ks = 0; ks < 8; ks++) {
        qf[ks][0] = tf32_bits(sQP[(wr + gr)     * 68 + ks * 8 + lc]);
        qf[ks][1] = tf32_bits(sQP[(wr + gr + 8) * 68 + ks * 8 + lc]);
        qf[ks][2] = tf32_bits(sQP[(wr + gr)     * 68 + ks * 8 + lc + 4]);
        qf[ks][3] = tf32_bits(sQP[(wr + gr + 8) * 68 + ks * 8 + lc + 4]);
    }
    __syncwarp();

    float oacc[8][4];
    #pragma unroll
    for (int fn = 0; fn < 8; fn++)
        #pragma unroll
        for (int e = 0; e < 4; e++) oacc[fn][e] = 0.f;
    float mrow[2] = { -1e30f, -1e30f };
    float lrow[2] = { 0.f, 0.f };

    const float* Kbase = K + (size_t)(b * Lk) * kStride + h * 64;
    const float* Vbase = V + (size_t)(b * Lk) * kStride + h * 64;
    int nkt = (Lk + 63) >> 6;

    for (int kt = 0; kt < nkt; kt++) {
        for (int i = tid; i < 1024; i += 128) {
            int r = i >> 4, d0 = (i & 15) * 4;
            int jg = kt * 64 + r;
            float4 kv = make_float4(0.f, 0.f, 0.f, 0.f);
            float4 vv = make_float4(0.f, 0.f, 0.f, 0.f);
            if (jg < Lk) {
                kv = *(const float4*)(Kbase + (size_t)jg * kStride + d0);
                vv = *(const float4*)(Vbase + (size_t)jg * kStride + d0);
            }
            float ka[4] = { kv.x, kv.y, kv.z, kv.w };
            float va[4] = { vv.x, vv.y, vv.z, vv.w };
            #pragma unroll
            for (int e = 0; e < 4; e++) {
                int d = d0 + e;
                *(uint32_t*)(sK + (((d >> 3) * 8 + (r >> 3)) * 32
                             + (r & 7) * 4 + (d & 3)) * 8 + ((d >> 2) & 1) * 4)
                    = tf32_bits(ka[e]);
                *(uint32_t*)(sV + (((r >> 3) * 8 + (d >> 3)) * 32
                             + (d & 7) * 4 + (r & 3)) * 8 + ((r >> 2) & 1) * 4)
                    = tf32_bits(va[e]);
            }
        }
        __syncthreads();

        float sacc[8][4];
        #pragma unroll
        for (int fn = 0; fn < 8; fn++)
            #pragma unroll
            for (int e = 0; e < 4; e++) sacc[fn][e] = 0.f;
        #pragma unroll
        for (int ks = 0; ks < 8; ks++) {
            #pragma unroll
            for (int fn = 0; fn < 8; fn++) {
                uint2 bb = *(const uint2*)(sK + ((ks * 8 + fn) * 32 + lane) * 8);
                mma_tf32(sacc[fn][0], sacc[fn][1], sacc[fn][2], sacc[fn][3],
                         qf[ks][0], qf[ks][1], qf[ks][2], qf[ks][3], bb.x, bb.y);
            }
        }

        if (kt * 64 + 64 > Lk) {
            #pragma unroll
            for (int fn = 0; fn < 8; fn++) {
                int key0 = kt * 64 + fn * 8 + 2 * lc;
                if (key0 >= Lk)     { sacc[fn][0] = -1e30f; sacc[fn][2] = -1e30f; }
                if (key0 + 1 >= Lk) { sacc[fn][1] = -1e30f; sacc[fn][3] = -1e30f; }
            }
        }

        #pragma unroll
        for (int hr = 0; hr < 2; hr++) {
            float rm = -1e30f;
            #pragma unroll
            for (int fn = 0; fn < 8; fn++)
                rm = fmaxf(rm, fmaxf(sacc[fn][hr * 2], sacc[fn][hr * 2 + 1]));
            rm = fmaxf(rm, __shfl_xor_sync(0xffffffffu, rm, 1));
            rm = fmaxf(rm, __shfl_xor_sync(0xffffffffu, rm, 2));
            float mn = fmaxf(mrow[hr], rm);
            float rsum = 0.f;
            #pragma unroll
            for (int fn = 0; fn < 8; fn++) {
                float p0 = __expf(sacc[fn][hr * 2]     - mn);
                float p1 = __expf(sacc[fn][hr * 2 + 1] - mn);
                sacc[fn][hr * 2] = p0; sacc[fn][hr * 2 + 1] = p1;
                rsum += p0 + p1;
            }
            rsum += __shfl_xor_sync(0xffffffffu, rsum, 1);
            rsum += __shfl_xor_sync(0xffffffffu, rsum, 2);
            float alpha = __expf(mrow[hr] - mn);
            lrow[hr] = lrow[hr] * alpha + rsum;
            mrow[hr] = mn;
            #pragma unroll
            for (int fn = 0; fn < 8; fn++) {
                oacc[fn][hr * 2]     *= alpha;
                oacc[fn][hr * 2 + 1] *= alpha;
            }
        }

        #pragma unroll
        for (int fn = 0; fn < 8; fn++) {
            int col = fn * 8 + 2 * lc;
            sQP[(wr + gr)     * 68 + col]     = tf32_rna(sacc[fn][0]);
            sQP[(wr + gr)     * 68 + col + 1] = tf32_rna(sacc[fn][1]);
            sQP[(wr + gr + 8) * 68 + col]     = tf32_rna(sacc[fn][2]);
            sQP[(wr + gr + 8) * 68 + col + 1] = tf32_rna(sacc[fn][3]);
        }
        __syncwarp();

        #pragma unroll
        for (int kg = 0; kg < 8; kg++) {
            uint32_t pa0 = __float_as_uint(sQP[(wr + gr)     * 68 + kg * 8 + lc]);
            uint32_t pa1 = __float_as_uint(sQP[(wr + gr + 8) * 68 + kg * 8 + lc]);
            uint32_t pa2 = __float_as_uint(sQP[(wr + gr)     * 68 + kg * 8 + lc + 4]);
            uint32_t pa3 = __float_as_uint(sQP[(wr + gr + 8) * 68 + kg * 8 + lc + 4]);
            #pragma unroll
            for (int fn = 0; fn < 8; fn++) {
                uint2 bb = *(const uint2*)(sV + ((kg * 8 + fn) * 32 + lane) * 8);
                mma_tf32(oacc[fn][0], oacc[fn][1], oacc[fn][2], oacc[fn][3],
                         pa0, pa1, pa2, pa3, bb.x, bb.y);
            }
        }
        __syncthreads();
    }

    __half* Obase = O + (size_t)(b * Lq + qt * 64) * Dx + h * 64;
    #pragma unroll
    for (int hr = 0; hr < 2; hr++) {
        float inv = 1.f / lrow[hr];
        int row = wr + gr + hr * 8;
        #pragma unroll
        for (int fn = 0; fn < 8; fn++) {
            *(__half2*)(Obase + (size_t)row * Dx + fn * 8 + 2 * lc) =
                __floats2half2_rn(oacc[fn][hr * 2] * inv, oacc[fn][hr * 2 + 1] * inv);
        }
    }
}

// ----------------------------------------------------------------------------
// launch
// ----------------------------------------------------------------------------
template <typename T>
static inline T* sym(const void* s) {
    void* p = nullptr;
    cudaGetSymbolAddress(&p, s);
    return (T*)p;
}

static inline void hgemm(const __half* A, const __half* BT, const float* bias,
                         const float* res, float* Cf, __half* Ch,
                         int M, int N, int K, int act) {
    dim3 grid(N / 128, (M + 127) / 128);
    h_mma_gemm<<<grid, 512, GEMM_SMEM>>>(A, BT, bias, res, Cf, Ch, M, N, K, act);
}

extern "C" void kernel_launch(void* const* d_in, const int* in_sizes, int n_in,
                              void* d_out, int out_size) {
    const float* x     = (const float*)d_in[0];
    const float* c     = (const float*)d_in[1];
    const float* text  = (const float*)d_in[2];
    const float* W_ada = (const float*)d_in[3];
    const float* b_ada = (const float*)d_in[4];
    const float* W_qkv = (const float*)d_in[5];
    const float* b_qkv = (const float*)d_in[6];
    const float* W_proj= (const float*)d_in[7];
    const float* b_proj= (const float*)d_in[8];
    const float* W_ctx = (const float*)d_in[9];
    const float* b_ctx = (const float*)d_in[10];
    const float* W_q   = (const float*)d_in[11];
    const float* W_k   = (const float*)d_in[12];
    const float* W_v   = (const float*)d_in[13];
    const float* W_out = (const float*)d_in[14];
    const float* b_out = (const float*)d_in[15];
    const float* W_fc1 = (const float*)d_in[16];
    const float* b_fc1 = (const float*)d_in[17];
    const float* W_fc2 = (const float*)d_in[18];
    const float* b_fc2 = (const float*)d_in[19];
    float* out = (float*)d_out;

    float*  mod   = sym<float>(g_mod);
    float*  qkv   = sym<float>(g_qkv);
    float*  x1    = sym<float>(g_x1);
    float*  x2    = sym<float>(g_x2);
    float*  q2    = sym<float>(g_q2);
    float*  k2v2  = sym<float>(g_k2v2);
    __half* h     = sym<__half>(g_h);
    __half* attnh = sym<__half>(g_attn_h);
    __half* ctxh  = sym<__half>(g_ctx_h);
    __half* texth = sym<__half>(g_text_h);
    __half* hidh  = sym<__half>(g_hid_h);

    __half* Wqkv_t = sym<__half>(g_Wqkv_t);
    __half* Wproj_t= sym<__half>(g_Wproj_t);
    __half* Wctx_t = sym<__half>(g_Wctx_t);
    __half* Wq_t   = sym<__half>(g_Wq_t);
    __half* Wkv_t  = sym<__half>(g_Wkv_t);
    __half* Wout_t = sym<__half>(g_Wout_t);
    __half* Wfc1_t = sym<__half>(g_Wfc1_t);
    __half* Wfc2_t = sym<__half>(g_Wfc2_t);

    cudaFuncSetAttribute(attn_mma_kernel, cudaFuncAttributeMaxDynamicSharedMemorySize,
                         ATTN_SMEM);
    cudaFuncSetAttribute(h_mma_gemm, cudaFuncAttributeMaxDynamicSharedMemorySize,
                         GEMM_SMEM);

    dim3 tb(32, 8);
    // launches 0-5 ordered so ncu (-s 5 -c 1) profiles the qkv GEMM
    transpose_h_kernel<<<dim3(3 * Dx / 32, Dx / 32), tb>>>(W_qkv, Wqkv_t, Dx, 3 * Dx); // 0
    ada_mod_kernel<<<dim3(24, 4), 256>>>(c, W_ada, b_ada, mod);                        // 1
    ln_mod_kernel<<<ROWS, 256>>>(x, mod, h, 0);                                        // 2
    transpose_h_kernel<<<dim3(Dx / 32, Dx / 32), tb>>>(W_proj, Wproj_t, Dx, Dx);       // 3
    transpose_h_kernel<<<dim3(4 * Dx / 32, Dx / 32), tb>>>(W_fc1, Wfc1_t, Dx, 4 * Dx); // 4
    hgemm(h, Wqkv_t, b_qkv, nullptr, qkv, nullptr, ROWS, 3 * Dx, Dx, ACT_NONE);        // 5
    attn_mma_kernel<<<dim3(Nx / 64, Hx, Bx), 128, ATTN_SMEM>>>(
        qkv, 3 * Dx, qkv + Dx, qkv + 2 * Dx, 3 * Dx, attnh, Nx, Nx);
    hgemm(attnh, Wproj_t, b_proj, x, x1, nullptr, ROWS, Dx, Dx, ACT_NONE);

    // remaining weight transposes + text conversion
    transpose_h_kernel<<<dim3(Dx / 32, TDx / 32), tb>>>(W_ctx, Wctx_t, TDx, Dx);
    transpose_h_kernel<<<dim3(Dx / 32, Dx / 32), tb>>>(W_q, Wq_t, Dx, Dx);
    transpose_h_kernel<<<dim3(Dx / 32, Dx / 32), tb>>>(W_k, Wkv_t, Dx, Dx);
    transpose_h_kernel<<<dim3(Dx / 32, Dx / 32), tb>>>(W_v, Wkv_t + Dx * Dx, Dx, Dx);
    transpose_h_kernel<<<dim3(Dx / 32, Dx / 32), tb>>>(W_out, Wout_t, Dx, Dx);
    transpose_h_kernel<<<dim3(Dx / 32, 4 * Dx / 32), tb>>>(W_fc2, Wfc2_t, 4 * Dx, Dx);
    f2h_kernel<<<(CTXROWS * TDx + 255) / 256, 256>>>(text, texth, CTXROWS * TDx);

    // --- cross attention ---
    ln_mod_kernel<<<ROWS, 256>>>(x1, mod, h, 2);
    hgemm(texth, Wctx_t, b_ctx, nullptr, nullptr, ctxh, CTXROWS, Dx, TDx, ACT_NONE);
    hgemm(h, Wq_t, nullptr, nullptr, q2, nullptr, ROWS, Dx, Dx, ACT_NONE);
    hgemm(ctxh, Wkv_t, nullptr, nullptr, k2v2, nullptr, CTXROWS, 2 * Dx, Dx, ACT_NONE);
    attn_mma_kernel<<<dim3(Nx / 64, Hx, Bx), 128, ATTN_SMEM>>>(
        q2, Dx, k2v2, k2v2 + Dx, 2 * Dx, attnh, Nx, TLx);
    hgemm(attnh, Wout_t, b_out, x1, x2, nullptr, ROWS, Dx, Dx, ACT_NONE);

    // --- MLP ---
    ln_mod_kernel<<<ROWS, 256>>>(x2, mod, h, 4);
    hgemm(h, Wfc1_t, b_fc1, nullptr, nullptr, hidh, ROWS, 4 * Dx, Dx, ACT_GELU);
    hgemm(hidh, Wfc2_t, b_fc2, x2, out, nullptr, ROWS, Dx, 4 * Dx, ACT_NONE);
}

// round 9
// speedup vs baseline: 6.6832x; 1.4322x over previous
#include <cuda_runtime.h>
#include <cuda_fp16.h>
#include <cstdint>
#include <math.h>

// ----------------------------------------------------------------------------
// DiT block: adaLN -> self-attn -> cross-attn -> MLP (GELU tanh)
// Round 9: fp16 ldmatrix/mma GEMMs + fp16 ldmatrix/mma flash attention.
// ----------------------------------------------------------------------------

#define Bx 4
#define Nx 1024
#define Dx 1024
#define Hx 16
#define HDx 64
#define TDx 768
#define TLx 77
#define ROWS (Bx * Nx)       // 4096
#define CTXROWS (Bx * TLx)   // 308

// fp32 scratch
__device__ float g_mod[Bx * 6 * Dx];
__device__ float g_x1[ROWS * Dx];
__device__ float g_x2[ROWS * Dx];
// half scratch
__device__ __half g_h[ROWS * Dx];
__device__ __half g_qkv[ROWS * 3 * Dx];
__device__ __half g_attn_h[ROWS * Dx];
__device__ __half g_q2[ROWS * Dx];
__device__ __half g_k2v2[CTXROWS * 2 * Dx];
__device__ __half g_ctx_h[CTXROWS * Dx];
__device__ __half g_text_h[CTXROWS * TDx];
__device__ __half g_hid_h[ROWS * 4 * Dx];
// transposed (K-major [N,K]) fp16 weights
__device__ __half g_Wqkv_t[3 * Dx * Dx];
__device__ __half g_Wproj_t[Dx * Dx];
__device__ __half g_Wctx_t[Dx * TDx];
__device__ __half g_Wq_t[Dx * Dx];
__device__ __half g_Wkv_t[2 * Dx * Dx];
__device__ __half g_Wout_t[Dx * Dx];
__device__ __half g_Wfc1_t[4 * Dx * Dx];
__device__ __half g_Wfc2_t[4 * Dx * Dx];

// ----------------------------------------------------------------------------
// helpers
// ----------------------------------------------------------------------------
__device__ __forceinline__ uint32_t smem_u32(const void* p) {
    uint32_t a;
    asm("{ .reg .u64 t; cvta.to.shared.u64 t, %1; cvt.u32.u64 %0, t; }"
        : "=r"(a) : "l"(p));
    return a;
}
__device__ __forceinline__ void cp_async16(uint32_t saddr, const void* gaddr, int szbytes) {
    asm volatile("cp.async.cg.shared.global [%0], [%1], 16, %2;"
                 :: "r"(saddr), "l"(gaddr), "r"(szbytes) : "memory");
}
#define CP_COMMIT() asm volatile("cp.async.commit_group;" ::: "memory")
#define CP_WAIT(n)  asm volatile("cp.async.wait_group %0;" :: "n"(n) : "memory")

#define LDMATRIX_X4(r0, r1, r2, r3, addr) \
    asm volatile("ldmatrix.sync.aligned.m8n8.x4.shared.b16 {%0,%1,%2,%3}, [%4];" \
                 : "=r"(r0), "=r"(r1), "=r"(r2), "=r"(r3) : "r"(addr))
#define LDMATRIX_X4_T(r0, r1, r2, r3, addr) \
    asm volatile("ldmatrix.sync.aligned.m8n8.x4.trans.shared.b16 {%0,%1,%2,%3}, [%4];" \
                 : "=r"(r0), "=r"(r1), "=r"(r2), "=r"(r3) : "r"(addr))

__device__ __forceinline__ void mma_f16(float& c0, float& c1, float& c2, float& c3,
                                        uint32_t a0, uint32_t a1, uint32_t a2, uint32_t a3,
                                        uint32_t b0, uint32_t b1) {
    asm volatile(
        "mma.sync.aligned.m16n8k16.row.col.f32.f16.f16.f32 "
        "{%0,%1,%2,%3}, {%4,%5,%6,%7}, {%8,%9}, {%0,%1,%2,%3};"
        : "+f"(c0), "+f"(c1), "+f"(c2), "+f"(c3)
        : "r"(a0), "r"(a1), "r"(a2), "r"(a3), "r"(b0), "r"(b1));
}
__device__ __forceinline__ uint32_t pack_h2(float lo, float hi) {
    __half2 h = __floats2half2_rn(lo, hi);
    return *(uint32_t*)&h;
}

// ----------------------------------------------------------------------------
// weight transpose: in[K,N] fp32 -> out[N,K] fp16 (rne)
// ----------------------------------------------------------------------------
__global__ void transpose_h_kernel(const float* __restrict__ in,
                                   __half* __restrict__ out, int K, int N) {
    __shared__ float t[32][33];
    int n0 = blockIdx.x * 32, k0 = blockIdx.y * 32;
    int tx = threadIdx.x, ty = threadIdx.y;
    #pragma unroll
    for (int i = 0; i < 32; i += 8)
        t[ty + i][tx] = in[(size_t)(k0 + ty + i) * N + n0 + tx];
    __syncthreads();
    #pragma unroll
    for (int i = 0; i < 32; i += 8)
        out[(size_t)(n0 + ty + i) * K + k0 + tx] = __float2half(t[tx][ty + i]);
}

__global__ void f2h_kernel(const float* __restrict__ in, __half* __restrict__ out, int n) {
    int i = blockIdx.x * 256 + threadIdx.x;
    if (i < n) out[i] = __float2half(in[i]);
}

// ----------------------------------------------------------------------------
// adaLN modulation
// ----------------------------------------------------------------------------
__global__ void ada_mod_kernel(const float* __restrict__ c,
                               const float* __restrict__ Wada,
                               const float* __restrict__ bada,
                               float* __restrict__ mod) {
    __shared__ float sc[Dx];
    int b = blockIdx.y;
    for (int i = threadIdx.x; i < Dx; i += 256) {
        float v = c[b * Dx + i];
        sc[i] = v / (1.f + __expf(-v));
    }
    __syncthreads();
    int n = blockIdx.x * 256 + threadIdx.x;
    float acc = 0.f;
    for (int k = 0; k < Dx; k++)
        acc += sc[k] * Wada[(size_t)k * (6 * Dx) + n];
    mod[b * 6 * Dx + n] = acc + bada[n];
}

// ----------------------------------------------------------------------------
// LayerNorm + modulate -> fp16
// ----------------------------------------------------------------------------
__global__ void ln_mod_kernel(const float* __restrict__ x,
                              const float* __restrict__ mod,
                              __half* __restrict__ out, int chunk) {
    int row = blockIdx.x;
    int b = row >> 10;
    int tid = threadIdx.x;
    const float* xr = x + (size_t)row * Dx;
    float4 v = *(const float4*)(xr + tid * 4);
    float s = v.x + v.y + v.z + v.w;
    float ss = v.x * v.x + v.y * v.y + v.z * v.z + v.w * v.w;
    #pragma unroll
    for (int off = 16; off; off >>= 1) {
        s  += __shfl_xor_sync(0xffffffffu, s, off);
        ss += __shfl_xor_sync(0xffffffffu, ss, off);
    }
    __shared__ float rs[8], rss[8];
    int wid = tid >> 5, lane = tid & 31;
    if (!lane) { rs[wid] = s; rss[wid] = ss; }
    __syncthreads();
    s = 0.f; ss = 0.f;
    #pragma unroll
    for (int w = 0; w < 8; w++) { s += rs[w]; ss += rss[w]; }
    float mean = s * (1.f / Dx);
    float var = ss * (1.f / Dx) - mean * mean;
    float inv = rsqrtf(var + 1e-6f);
    const float* sh = mod + (size_t)b * 6 * Dx + (size_t)chunk * Dx;
    const float* scl = sh + Dx;
    int d = tid * 4;
    float o0 = (v.x - mean) * inv * (1.f + scl[d + 0]) + sh[d + 0];
    float o1 = (v.y - mean) * inv * (1.f + scl[d + 1]) + sh[d + 1];
    float o2 = (v.z - mean) * inv * (1.f + scl[d + 2]) + sh[d + 2];
    float o3 = (v.w - mean) * inv * (1.f + scl[d + 3]) + sh[d + 3];
    __half2* op = (__half2*)(out + (size_t)row * Dx + d);
    op[0] = __floats2half2_rn(o0, o1);
    op[1] = __floats2half2_rn(o2, o3);
}

// ----------------------------------------------------------------------------
// fp16 mma.sync GEMM (unchanged from round 8 — proven)
// ----------------------------------------------------------------------------
#define ACT_NONE 0
#define ACT_GELU 1
#define STAGES 3
#define GEMM_SMEM (STAGES * 32768)

__device__ __forceinline__ float gelu_tanh(float x) {
    float x3 = x * x * x;
    return 0.5f * x * (1.f + tanhf(0.7978845608028654f * (x + 0.044715f * x3)));
}

__global__ __launch_bounds__(512, 1)
void h_mma_gemm(const __half* __restrict__ A, const __half* __restrict__ BT,
                const float* __restrict__ bias, const float* __restrict__ res,
                float* __restrict__ Cf, __half* __restrict__ Ch,
                int M, int N, int K, int act) {
    extern __shared__ char smem[];
    uint32_t sbase = smem_u32(smem);
    int tid = threadIdx.x, lane = tid & 31, wid = tid >> 5;
    int wm = wid >> 2, wn = wid & 3;
    int row0 = blockIdx.y * 128, col0 = blockIdx.x * 128;

    uint32_t offAB[2];
    const __half* gA[2];
    const __half* gB[2];
    int szA[2];
    #pragma unroll
    for (int i = 0; i < 2; i++) {
        int idx = tid + i * 512;
        int r = idx >> 3, c8 = idx & 7;
        offAB[i] = (uint32_t)(r * 128 + ((c8 ^ (r & 7)) << 4));
        szA[i] = (row0 + r) < M ? 16 : 0;
        gA[i] = A + (size_t)(row0 + r) * K + c8 * 8;
        gB[i] = BT + (size_t)(col0 + r) * K + c8 * 8;
    }

    float acc[2][4][4];
    #pragma unroll
    for (int im = 0; im < 2; im++)
        #pragma unroll
        for (int jn = 0; jn < 4; jn++)
            #pragma unroll
            for (int e = 0; e < 4; e++) acc[im][jn][e] = 0.f;

    int K64 = K >> 6;

    #pragma unroll
    for (int s = 0; s < STAGES - 1; s++) {
        uint32_t sa = sbase + (uint32_t)(s * 32768);
        #pragma unroll
        for (int i = 0; i < 2; i++) {
            cp_async16(sa + offAB[i], gA[i] + (size_t)s * 64, szA[i]);
            cp_async16(sa + 16384u + offAB[i], gB[i] + (size_t)s * 64, 16);
        }
        CP_COMMIT();
    }

    int lrA = (lane & 7) | (lane & 8);
    int lkA8 = (lane >> 4) << 3;
    int lrB = (lane & 7) | ((lane & 16) >> 1);
    int lkB8 = lane & 8;

    for (int s = 0; s < K64; s++) {
        CP_WAIT(STAGES - 2);
        __syncthreads();
        uint32_t sa = sbase + (uint32_t)((s % STAGES) * 32768);
        uint32_t sb = sa + 16384u;

        #pragma unroll
        for (int kg = 0; kg < 4; kg++) {
            int lkA = kg * 16 + lkA8;
            int lkB = kg * 16 + lkB8;
            uint32_t areg[2][4];
            #pragma unroll
            for (int im = 0; im < 2; im++) {
                int r = wm * 32 + im * 16 + lrA;
                uint32_t addr = sa + (uint32_t)(r * 128 + (((lkA >> 3) ^ (r & 7)) << 4));
                LDMATRIX_X4(areg[im][0], areg[im][1], areg[im][2], areg[im][3], addr);
            }
            uint32_t breg[2][4];
            #pragma unroll
            for (int p = 0; p < 2; p++) {
                int r = wn * 32 + p * 16 + lrB;
                uint32_t addr = sb + (uint32_t)(r * 128 + (((lkB >> 3) ^ (r & 7)) << 4));
                LDMATRIX_X4(breg[p][0], breg[p][1], breg[p][2], breg[p][3], addr);
            }
            #pragma unroll
            for (int im = 0; im < 2; im++)
                #pragma unroll
                for (int jn = 0; jn < 4; jn++) {
                    int p = jn >> 1, q = (jn & 1) * 2;
                    mma_f16(acc[im][jn][0], acc[im][jn][1],
                            acc[im][jn][2], acc[im][jn][3],
                            areg[im][0], areg[im][1], areg[im][2], areg[im][3],
                            breg[p][q], breg[p][q + 1]);
                }
        }

        int sn = s + STAGES - 1;
        if (sn < K64) {
            uint32_t sa2 = sbase + (uint32_t)((sn % STAGES) * 32768);
            #pragma unroll
            for (int i = 0; i < 2; i++) {
                cp_async16(sa2 + offAB[i], gA[i] + (size_t)sn * 64, szA[i]);
                cp_async16(sa2 + 16384u + offAB[i], gB[i] + (size_t)sn * 64, 16);
            }
        }
        CP_COMMIT();
    }

    int egr = lane >> 2, egc = (lane & 3) * 2;
    #pragma unroll
    for (int im = 0; im < 2; im++) {
        #pragma unroll
        for (int half = 0; half < 2; half++) {
            int rg = row0 + wm * 32 + im * 16 + egr + half * 8;
            if (rg >= M) continue;
            #pragma unroll
            for (int jn = 0; jn < 4; jn++) {
                int cg = col0 + wn * 32 + jn * 8 + egc;
                float t0 = acc[im][jn][half * 2 + 0];
                float t1 = acc[im][jn][half * 2 + 1];
                if (bias) { t0 += bias[cg]; t1 += bias[cg + 1]; }
                if (act == ACT_GELU) { t0 = gelu_tanh(t0); t1 = gelu_tanh(t1); }
                if (res) {
                    t0 += res[(size_t)rg * N + cg];
                    t1 += res[(size_t)rg * N + cg + 1];
                }
                if (Ch) {
                    *(__half2*)(Ch + (size_t)rg * N + cg) = __floats2half2_rn(t0, t1);
                } else {
                    *(float2*)(Cf + (size_t)rg * N + cg) = make_float2(t0, t1);
                }
            }
        }
    }
}

// ----------------------------------------------------------------------------
// fp16 ldmatrix/mma flash attention.
// 64 q-rows per CTA, 4 warps (each m16), HD=64, K tiles of 64.
// smem: sQ 8KB + sK 8KB + sV 8KB, all 128B rows with XOR swizzle.
// QK^T: A=Q (ldmatrix), B=K rows (non-trans).  P@V: A=P (register repack),
// B=V via ldmatrix.trans (dims become n).  fp32 accum, online softmax.
// ----------------------------------------------------------------------------
#define ATTN_SMEM (3 * 8192)

__global__ __launch_bounds__(128, 3)
void attn_h_kernel(const __half* __restrict__ Q, int qStride,
                   const __half* __restrict__ K, const __half* __restrict__ V,
                   int kStride, __half* __restrict__ O, int Lq, int Lk) {
    extern __shared__ char smc[];
    uint32_t sQ = smem_u32(smc);
    uint32_t sK = sQ + 8192;
    uint32_t sV = sQ + 16384;

    int tid = threadIdx.x, lane = tid & 31, w = tid >> 5;
    int gr = lane >> 2, lc = lane & 3;
    int qt = blockIdx.x, h = blockIdx.y, b = blockIdx.z;
    int wr = w * 16;
    const float scale = 0.125f;   // 1/sqrt(64)

    // ---- load Q tile (cp.async, swizzled) ----
    const __half* Qbase = Q + (size_t)(b * Lq + qt * 64) * qStride + h * 64;
    #pragma unroll
    for (int i = 0; i < 4; i++) {
        int idx = tid + i * 128;           // 0..511
        int r = idx >> 3, c8 = idx & 7;
        cp_async16(sQ + r * 128 + ((c8 ^ (r & 7)) << 4),
                   Qbase + (size_t)r * qStride + c8 * 8, 16);
    }
    CP_COMMIT();
    CP_WAIT(0);
    __syncthreads();

    // ---- Q fragments (registers, reused all tiles) ----
    int lrA = (lane & 7) | (lane & 8);
    int lkA8 = (lane >> 4) << 3;
    uint32_t qf[4][4];
    #pragma unroll
    for (int kg = 0; kg < 4; kg++) {
        int r = wr + lrA;
        int c = kg * 16 + lkA8;
        uint32_t addr = sQ + (uint32_t)(r * 128 + (((c >> 3) ^ (r & 7)) << 4));
        LDMATRIX_X4(qf[kg][0], qf[kg][1], qf[kg][2], qf[kg][3], addr);
    }

    float oacc[8][4];
    #pragma unroll
    for (int fn = 0; fn < 8; fn++)
        #pragma unroll
        for (int e = 0; e < 4; e++) oacc[fn][e] = 0.f;
    float mrow[2] = { -1e30f, -1e30f };
    float lrow[2] = { 0.f, 0.f };

    const __half* Kbase = K + (size_t)(b * Lk) * kStride + h * 64;
    const __half* Vbase = V + (size_t)(b * Lk) * kStride + h * 64;
    int nkt = (Lk + 63) >> 6;

    int lrB = (lane & 7) | ((lane & 16) >> 1);
    int lkB8 = lane & 8;
    int mV = lane >> 3;                  // ldmatrix matrix index 0..3

    for (int kt = 0; kt < nkt; kt++) {
        // ---- stage K and V tiles (cp.async, zero-fill OOB) ----
        #pragma unroll
        for (int i = 0; i < 4; i++) {
            int idx = tid + i * 128;
            int r = idx >> 3, c8 = idx & 7;
            int jg = kt * 64 + r;
            int sz = (jg < Lk) ? 16 : 0;
            uint32_t so = (uint32_t)(r * 128 + ((c8 ^ (r & 7)) << 4));
            cp_async16(sK + so, Kbase + (size_t)jg * kStride + c8 * 8, sz);
            cp_async16(sV + so, Vbase + (size_t)jg * kStride + c8 * 8, sz);
        }
        CP_COMMIT();
        CP_WAIT(0);
        __syncthreads();

        // ---- S = Q @ K^T ----
        float sacc[8][4];
        #pragma unroll
        for (int fn = 0; fn < 8; fn++)
            #pragma unroll
            for (int e = 0; e < 4; e++) sacc[fn][e] = 0.f;
        #pragma unroll
        for (int kg = 0; kg < 4; kg++) {
            #pragma unroll
            for (int pp = 0; pp < 4; pp++) {   // key block of 16
                int r = pp * 16 + lrB;
                int c = kg * 16 + lkB8;
                uint32_t addr = sK + (uint32_t)(r * 128 + (((c >> 3) ^ (r & 7)) << 4));
                uint32_t kb0, kb1, kb2, kb3;
                LDMATRIX_X4(kb0, kb1, kb2, kb3, addr);
                mma_f16(sacc[2 * pp][0], sacc[2 * pp][1], sacc[2 * pp][2], sacc[2 * pp][3],
                        qf[kg][0], qf[kg][1], qf[kg][2], qf[kg][3], kb0, kb1);
                mma_f16(sacc[2 * pp + 1][0], sacc[2 * pp + 1][1],
                        sacc[2 * pp + 1][2], sacc[2 * pp + 1][3],
                        qf[kg][0], qf[kg][1], qf[kg][2], qf[kg][3], kb2, kb3);
            }
        }
        #pragma unroll
        for (int fn = 0; fn < 8; fn++)
            #pragma unroll
            for (int e = 0; e < 4; e++) sacc[fn][e] *= scale;

        // ---- mask out-of-range keys ----
        if (kt * 64 + 64 > Lk) {
            #pragma unroll
            for (int fn = 0; fn < 8; fn++) {
                int key0 = kt * 64 + fn * 8 + 2 * lc;
                if (key0 >= Lk)     { sacc[fn][0] = -1e30f; sacc[fn][2] = -1e30f; }
                if (key0 + 1 >= Lk) { sacc[fn][1] = -1e30f; sacc[fn][3] = -1e30f; }
            }
        }

        // ---- online softmax (rows gr, gr+8) ----
        #pragma unroll
        for (int hr = 0; hr < 2; hr++) {
            float rm = -1e30f;
            #pragma unroll
            for (int fn = 0; fn < 8; fn++)
                rm = fmaxf(rm, fmaxf(sacc[fn][hr * 2], sacc[fn][hr * 2 + 1]));
            rm = fmaxf(rm, __shfl_xor_sync(0xffffffffu, rm, 1));
            rm = fmaxf(rm, __shfl_xor_sync(0xffffffffu, rm, 2));
            float mn = fmaxf(mrow[hr], rm);
            float rsum = 0.f;
            #pragma unroll
            for (int fn = 0; fn < 8; fn++) {
                float p0 = __expf(sacc[fn][hr * 2]     - mn);
                float p1 = __expf(sacc[fn][hr * 2 + 1] - mn);
                sacc[fn][hr * 2] = p0; sacc[fn][hr * 2 + 1] = p1;
                rsum += p0 + p1;
            }
            rsum += __shfl_xor_sync(0xffffffffu, rsum, 1);
            rsum += __shfl_xor_sync(0xffffffffu, rsum, 2);
            float alpha = __expf(mrow[hr] - mn);
            lrow[hr] = lrow[hr] * alpha + rsum;
            mrow[hr] = mn;
            #pragma unroll
            for (int fn = 0; fn < 8; fn++) {
                oacc[fn][hr * 2]     *= alpha;
                oacc[fn][hr * 2 + 1] *= alpha;
            }
        }

        // ---- P fragments (pure register repack; C layout == A layout) ----
        uint32_t pf[4][4];
        #pragma unroll
        for (int kg = 0; kg < 4; kg++) {
            pf[kg][0] = pack_h2(sacc[2 * kg][0],     sacc[2 * kg][1]);
            pf[kg][1] = pack_h2(sacc[2 * kg][2],     sacc[2 * kg][3]);
            pf[kg][2] = pack_h2(sacc[2 * kg + 1][0], sacc[2 * kg + 1][1]);
            pf[kg][3] = pack_h2(sacc[2 * kg + 1][2], sacc[2 * kg + 1][3]);
        }

        // ---- O += P @ V (V via ldmatrix.trans: dims -> n) ----
        #pragma unroll
        for (int kg = 0; kg < 4; kg++) {
            #pragma unroll
            for (int dn = 0; dn < 4; dn++) {   // dim block of 16
                int r = kg * 16 + (mV & 1) * 8 + (lane & 7);
                int c8 = dn * 2 + (mV >> 1);
                uint32_t addr = sV + (uint32_t)(r * 128 + ((c8 ^ (r & 7)) << 4));
                uint32_t vb0, vb1, vb2, vb3;
                LDMATRIX_X4_T(vb0, vb1, vb2, vb3, addr);
                mma_f16(oacc[2 * dn][0], oacc[2 * dn][1],
                        oacc[2 * dn][2], oacc[2 * dn][3],
                        pf[kg][0], pf[kg][1], pf[kg][2], pf[kg][3], vb0, vb1);
                mma_f16(oacc[2 * dn + 1][0], oacc[2 * dn + 1][1],
                        oacc[2 * dn + 1][2], oacc[2 * dn + 1][3],
                        pf[kg][0], pf[kg][1], pf[kg][2], pf[kg][3], vb2, vb3);
            }
        }
        __syncthreads();   // all warps done with sK/sV before next stage
    }

    // ---- epilogue ----
    __half* Obase = O + (size_t)(b * Lq + qt * 64) * Dx + h * 64;
    #pragma unroll
    for (int hr = 0; hr < 2; hr++) {
        float inv = 1.f / lrow[hr];
        int row = wr + gr + hr * 8;
        #pragma unroll
        for (int fn = 0; fn < 8; fn++) {
            *(__half2*)(Obase + (size_t)row * Dx + fn * 8 + 2 * lc) =
                __floats2half2_rn(oacc[fn][hr * 2] * inv, oacc[fn][hr * 2 + 1] * inv);
        }
    }
}

// ----------------------------------------------------------------------------
// launch
// ----------------------------------------------------------------------------
template <typename T>
static inline T* sym(const void* s) {
    void* p = nullptr;
    cudaGetSymbolAddress(&p, s);
    return (T*)p;
}

static inline void hgemm(const __half* A, const __half* BT, const float* bias,
                         const float* res, float* Cf, __half* Ch,
                         int M, int N, int K, int act) {
    dim3 grid(N / 128, (M + 127) / 128);
    h_mma_gemm<<<grid, 512, GEMM_SMEM>>>(A, BT, bias, res, Cf, Ch, M, N, K, act);
}

extern "C" void kernel_launch(void* const* d_in, const int* in_sizes, int n_in,
                              void* d_out, int out_size) {
    const float* x     = (const float*)d_in[0];
    const float* c     = (const float*)d_in[1];
    const float* text  = (const float*)d_in[2];
    const float* W_ada = (const float*)d_in[3];
    const float* b_ada = (const float*)d_in[4];
    const float* W_qkv = (const float*)d_in[5];
    const float* b_qkv = (const float*)d_in[6];
    const float* W_proj= (const float*)d_in[7];
    const float* b_proj= (const float*)d_in[8];
    const float* W_ctx = (const float*)d_in[9];
    const float* b_ctx = (const float*)d_in[10];
    const float* W_q   = (const float*)d_in[11];
    const float* W_k   = (const float*)d_in[12];
    const float* W_v   = (const float*)d_in[13];
    const float* W_out = (const float*)d_in[14];
    const float* b_out = (const float*)d_in[15];
    const float* W_fc1 = (const float*)d_in[16];
    const float* b_fc1 = (const float*)d_in[17];
    const float* W_fc2 = (const float*)d_in[18];
    const float* b_fc2 = (const float*)d_in[19];
    float* out = (float*)d_out;

    float*  mod   = sym<float>(g_mod);
    float*  x1    = sym<float>(g_x1);
    float*  x2    = sym<float>(g_x2);
    __half* h     = sym<__half>(g_h);
    __half* qkvh  = sym<__half>(g_qkv);
    __half* attnh = sym<__half>(g_attn_h);
    __half* q2h   = sym<__half>(g_q2);
    __half* k2v2h = sym<__half>(g_k2v2);
    __half* ctxh  = sym<__half>(g_ctx_h);
    __half* texth = sym<__half>(g_text_h);
    __half* hidh  = sym<__half>(g_hid_h);

    __half* Wqkv_t = sym<__half>(g_Wqkv_t);
    __half* Wproj_t= sym<__half>(g_Wproj_t);
    __half* Wctx_t = sym<__half>(g_Wctx_t);
    __half* Wq_t   = sym<__half>(g_Wq_t);
    __half* Wkv_t  = sym<__half>(g_Wkv_t);
    __half* Wout_t = sym<__half>(g_Wout_t);
    __half* Wfc1_t = sym<__half>(g_Wfc1_t);
    __half* Wfc2_t = sym<__half>(g_Wfc2_t);

    cudaFuncSetAttribute(attn_h_kernel, cudaFuncAttributeMaxDynamicSharedMemorySize,
                         ATTN_SMEM);
    cudaFuncSetAttribute(h_mma_gemm, cudaFuncAttributeMaxDynamicSharedMemorySize,
                         GEMM_SMEM);

    dim3 tb(32, 8);
    // launches 0-5 ordered so ncu (-s 5 -c 1) profiles the qkv GEMM
    transpose_h_kernel<<<dim3(3 * Dx / 32, Dx / 32), tb>>>(W_qkv, Wqkv_t, Dx, 3 * Dx); // 0
    ada_mod_kernel<<<dim3(24, 4), 256>>>(c, W_ada, b_ada, mod);                        // 1
    ln_mod_kernel<<<ROWS, 256>>>(x, mod, h, 0);                                        // 2
    transpose_h_kernel<<<dim3(Dx / 32, Dx / 32), tb>>>(W_proj, Wproj_t, Dx, Dx);       // 3
    transpose_h_kernel<<<dim3(4 * Dx / 32, Dx / 32), tb>>>(W_fc1, Wfc1_t, Dx, 4 * Dx); // 4
    hgemm(h, Wqkv_t, b_qkv, nullptr, nullptr, qkvh, ROWS, 3 * Dx, Dx, ACT_NONE);       // 5
    attn_h_kernel<<<dim3(Nx / 64, Hx, Bx), 128, ATTN_SMEM>>>(
        qkvh, 3 * Dx, qkvh + Dx, qkvh + 2 * Dx, 3 * Dx, attnh, Nx, Nx);
    hgemm(attnh, Wproj_t, b_proj, x, x1, nullptr, ROWS, Dx, Dx, ACT_NONE);

    // remaining weight transposes + text conversion
    transpose_h_kernel<<<dim3(Dx / 32, TDx / 32), tb>>>(W_ctx, Wctx_t, TDx, Dx);
    transpose_h_kernel<<<dim3(Dx / 32, Dx / 32), tb>>>(W_q, Wq_t, Dx, Dx);
    transpose_h_kernel<<<dim3(Dx / 32, Dx / 32), tb>>>(W_k, Wkv_t, Dx, Dx);
    transpose_h_kernel<<<dim3(Dx / 32, Dx / 32), tb>>>(W_v, Wkv_t + Dx * Dx, Dx, Dx);
    transpose_h_kernel<<<dim3(Dx / 32, Dx / 32), tb>>>(W_out, Wout_t, Dx, Dx);
    transpose_h_kernel<<<dim3(Dx / 32, 4 * Dx / 32), tb>>>(W_fc2, Wfc2_t, 4 * Dx, Dx);
    f2h_kernel<<<(CTXROWS * TDx + 255) / 256, 256>>>(text, texth, CTXROWS * TDx);

    // --- cross attention ---
    ln_mod_kernel<<<ROWS, 256>>>(x1, mod, h, 2);
    hgemm(texth, Wctx_t, b_ctx, nullptr, nullptr, ctxh, CTXROWS, Dx, TDx, ACT_NONE);
    hgemm(h, Wq_t, nullptr, nullptr, nullptr, q2h, ROWS, Dx, Dx, ACT_NONE);
    hgemm(ctxh, Wkv_t, nullptr, nullptr, nullptr, k2v2h, CTXROWS, 2 * Dx, Dx, ACT_NONE);
    attn_h_kernel<<<dim3(Nx / 64, Hx, Bx), 128, ATTN_SMEM>>>(
        q2h, Dx, k2v2h, k2v2h + Dx, 2 * Dx, attnh, Nx, TLx);
    hgemm(attnh, Wout_t, b_out, x1, x2, nullptr, ROWS, Dx, Dx, ACT_NONE);

    // --- MLP ---
    ln_mod_kernel<<<ROWS, 256>>>(x2, mod, h, 4);
    hgemm(h, Wfc1_t, b_fc1, nullptr, nullptr, hidh, ROWS, 4 * Dx, Dx, ACT_GELU);
    hgemm(hidh, Wfc2_t, b_fc2, x2, out, nullptr, ROWS, Dx, 4 * Dx, ACT_NONE);
}

// round 10
// speedup vs baseline: 7.2306x; 1.0819x over previous
#include <cuda_runtime.h>
#include <cuda_fp16.h>
#include <cstdint>
#include <math.h>

// ----------------------------------------------------------------------------
// DiT block: adaLN -> self-attn -> cross-attn -> MLP (GELU tanh)
// Round 10: fp16 GEMM rebalanced (256 thr, warp tile 64x32, 2 CTAs/SM),
//           fp16 ldmatrix/mma flash attention.
// ----------------------------------------------------------------------------

#define Bx 4
#define Nx 1024
#define Dx 1024
#define Hx 16
#define HDx 64
#define TDx 768
#define TLx 77
#define ROWS (Bx * Nx)       // 4096
#define CTXROWS (Bx * TLx)   // 308

// fp32 scratch
__device__ float g_mod[Bx * 6 * Dx];
__device__ float g_x1[ROWS * Dx];
__device__ float g_x2[ROWS * Dx];
// half scratch
__device__ __half g_h[ROWS * Dx];
__device__ __half g_qkv[ROWS * 3 * Dx];
__device__ __half g_attn_h[ROWS * Dx];
__device__ __half g_q2[ROWS * Dx];
__device__ __half g_k2v2[CTXROWS * 2 * Dx];
__device__ __half g_ctx_h[CTXROWS * Dx];
__device__ __half g_text_h[CTXROWS * TDx];
__device__ __half g_hid_h[ROWS * 4 * Dx];
// transposed (K-major [N,K]) fp16 weights
__device__ __half g_Wqkv_t[3 * Dx * Dx];
__device__ __half g_Wproj_t[Dx * Dx];
__device__ __half g_Wctx_t[Dx * TDx];
__device__ __half g_Wq_t[Dx * Dx];
__device__ __half g_Wkv_t[2 * Dx * Dx];
__device__ __half g_Wout_t[Dx * Dx];
__device__ __half g_Wfc1_t[4 * Dx * Dx];
__device__ __half g_Wfc2_t[4 * Dx * Dx];

// ----------------------------------------------------------------------------
// helpers
// ----------------------------------------------------------------------------
__device__ __forceinline__ uint32_t smem_u32(const void* p) {
    uint32_t a;
    asm("{ .reg .u64 t; cvta.to.shared.u64 t, %1; cvt.u32.u64 %0, t; }"
        : "=r"(a) : "l"(p));
    return a;
}
__device__ __forceinline__ void cp_async16(uint32_t saddr, const void* gaddr, int szbytes) {
    asm volatile("cp.async.cg.shared.global [%0], [%1], 16, %2;"
                 :: "r"(saddr), "l"(gaddr), "r"(szbytes) : "memory");
}
#define CP_COMMIT() asm volatile("cp.async.commit_group;" ::: "memory")
#define CP_WAIT(n)  asm volatile("cp.async.wait_group %0;" :: "n"(n) : "memory")

#define LDMATRIX_X4(r0, r1, r2, r3, addr) \
    asm volatile("ldmatrix.sync.aligned.m8n8.x4.shared.b16 {%0,%1,%2,%3}, [%4];" \
                 : "=r"(r0), "=r"(r1), "=r"(r2), "=r"(r3) : "r"(addr))
#define LDMATRIX_X4_T(r0, r1, r2, r3, addr) \
    asm volatile("ldmatrix.sync.aligned.m8n8.x4.trans.shared.b16 {%0,%1,%2,%3}, [%4];" \
                 : "=r"(r0), "=r"(r1), "=r"(r2), "=r"(r3) : "r"(addr))

__device__ __forceinline__ void mma_f16(float& c0, float& c1, float& c2, float& c3,
                                        uint32_t a0, uint32_t a1, uint32_t a2, uint32_t a3,
                                        uint32_t b0, uint32_t b1) {
    asm volatile(
        "mma.sync.aligned.m16n8k16.row.col.f32.f16.f16.f32 "
        "{%0,%1,%2,%3}, {%4,%5,%6,%7}, {%8,%9}, {%0,%1,%2,%3};"
        : "+f"(c0), "+f"(c1), "+f"(c2), "+f"(c3)
        : "r"(a0), "r"(a1), "r"(a2), "r"(a3), "r"(b0), "r"(b1));
}
__device__ __forceinline__ uint32_t pack_h2(float lo, float hi) {
    __half2 h = __floats2half2_rn(lo, hi);
    return *(uint32_t*)&h;
}

// ----------------------------------------------------------------------------
// weight transpose: in[K,N] fp32 -> out[N,K] fp16 (rne)
// ----------------------------------------------------------------------------
__global__ void transpose_h_kernel(const float* __restrict__ in,
                                   __half* __restrict__ out, int K, int N) {
    __shared__ float t[32][33];
    int n0 = blockIdx.x * 32, k0 = blockIdx.y * 32;
    int tx = threadIdx.x, ty = threadIdx.y;
    #pragma unroll
    for (int i = 0; i < 32; i += 8)
        t[ty + i][tx] = in[(size_t)(k0 + ty + i) * N + n0 + tx];
    __syncthreads();
    #pragma unroll
    for (int i = 0; i < 32; i += 8)
        out[(size_t)(n0 + ty + i) * K + k0 + tx] = __float2half(t[tx][ty + i]);
}

__global__ void f2h_kernel(const float* __restrict__ in, __half* __restrict__ out, int n) {
    int i = blockIdx.x * 256 + threadIdx.x;
    if (i < n) out[i] = __float2half(in[i]);
}

// ----------------------------------------------------------------------------
// adaLN modulation
// ----------------------------------------------------------------------------
__global__ void ada_mod_kernel(const float* __restrict__ c,
                               const float* __restrict__ Wada,
                               const float* __restrict__ bada,
                               float* __restrict__ mod) {
    __shared__ float sc[Dx];
    int b = blockIdx.y;
    for (int i = threadIdx.x; i < Dx; i += 256) {
        float v = c[b * Dx + i];
        sc[i] = v / (1.f + __expf(-v));
    }
    __syncthreads();
    int n = blockIdx.x * 256 + threadIdx.x;
    float acc = 0.f;
    for (int k = 0; k < Dx; k++)
        acc += sc[k] * Wada[(size_t)k * (6 * Dx) + n];
    mod[b * 6 * Dx + n] = acc + bada[n];
}

// ----------------------------------------------------------------------------
// LayerNorm + modulate -> fp16
// ----------------------------------------------------------------------------
__global__ void ln_mod_kernel(const float* __restrict__ x,
                              const float* __restrict__ mod,
                              __half* __restrict__ out, int chunk) {
    int row = blockIdx.x;
    int b = row >> 10;
    int tid = threadIdx.x;
    const float* xr = x + (size_t)row * Dx;
    float4 v = *(const float4*)(xr + tid * 4);
    float s = v.x + v.y + v.z + v.w;
    float ss = v.x * v.x + v.y * v.y + v.z * v.z + v.w * v.w;
    #pragma unroll
    for (int off = 16; off; off >>= 1) {
        s  += __shfl_xor_sync(0xffffffffu, s, off);
        ss += __shfl_xor_sync(0xffffffffu, ss, off);
    }
    __shared__ float rs[8], rss[8];
    int wid = tid >> 5, lane = tid & 31;
    if (!lane) { rs[wid] = s; rss[wid] = ss; }
    __syncthreads();
    s = 0.f; ss = 0.f;
    #pragma unroll
    for (int w = 0; w < 8; w++) { s += rs[w]; ss += rss[w]; }
    float mean = s * (1.f / Dx);
    float var = ss * (1.f / Dx) - mean * mean;
    float inv = rsqrtf(var + 1e-6f);
    const float* sh = mod + (size_t)b * 6 * Dx + (size_t)chunk * Dx;
    const float* scl = sh + Dx;
    int d = tid * 4;
    float o0 = (v.x - mean) * inv * (1.f + scl[d + 0]) + sh[d + 0];
    float o1 = (v.y - mean) * inv * (1.f + scl[d + 1]) + sh[d + 1];
    float o2 = (v.z - mean) * inv * (1.f + scl[d + 2]) + sh[d + 2];
    float o3 = (v.w - mean) * inv * (1.f + scl[d + 3]) + sh[d + 3];
    __half2* op = (__half2*)(out + (size_t)row * Dx + d);
    op[0] = __floats2half2_rn(o0, o1);
    op[1] = __floats2half2_rn(o2, o3);
}

// ----------------------------------------------------------------------------
// fp16 mma.sync GEMM, cp.async 3-stage.
// 128x128 tile, BK=64, 256 threads (8 warps, 2x4), warp tile 64x32.
// 2 CTAs/SM (regs capped at 128 by launch_bounds; smem 96KB/CTA).
// ----------------------------------------------------------------------------
#define ACT_NONE 0
#define ACT_GELU 1
#define STAGES 3
#define GEMM_SMEM (STAGES * 32768)

__device__ __forceinline__ float gelu_tanh(float x) {
    float x3 = x * x * x;
    return 0.5f * x * (1.f + tanhf(0.7978845608028654f * (x + 0.044715f * x3)));
}

__global__ __launch_bounds__(256, 2)
void h_mma_gemm(const __half* __restrict__ A, const __half* __restrict__ BT,
                const float* __restrict__ bias, const float* __restrict__ res,
                float* __restrict__ Cf, __half* __restrict__ Ch,
                int M, int N, int K, int act) {
    extern __shared__ char smem[];
    uint32_t sbase = smem_u32(smem);
    int tid = threadIdx.x, lane = tid & 31, wid = tid >> 5;
    int wm = wid >> 2, wn = wid & 3;          // 2x4 warp grid, warp tile 64x32
    int row0 = blockIdx.y * 128, col0 = blockIdx.x * 128;

    // producer: 4 A-chunks + 4 B-chunks (16B each) per thread per stage
    uint32_t offAB[4];
    const __half* gA[4];
    const __half* gB[4];
    int szA[4];
    #pragma unroll
    for (int i = 0; i < 4; i++) {
        int idx = tid + i * 256;              // 0..1023
        int r = idx >> 3, c8 = idx & 7;
        offAB[i] = (uint32_t)(r * 128 + ((c8 ^ (r & 7)) << 4));
        szA[i] = (row0 + r) < M ? 16 : 0;
        gA[i] = A + (size_t)(row0 + r) * K + c8 * 8;
        gB[i] = BT + (size_t)(col0 + r) * K + c8 * 8;
    }

    float acc[4][4][4];
    #pragma unroll
    for (int im = 0; im < 4; im++)
        #pragma unroll
        for (int jn = 0; jn < 4; jn++)
            #pragma unroll
            for (int e = 0; e < 4; e++) acc[im][jn][e] = 0.f;

    int K64 = K >> 6;

    #pragma unroll
    for (int s = 0; s < STAGES - 1; s++) {
        uint32_t sa = sbase + (uint32_t)(s * 32768);
        #pragma unroll
        for (int i = 0; i < 4; i++) {
            cp_async16(sa + offAB[i], gA[i] + (size_t)s * 64, szA[i]);
            cp_async16(sa + 16384u + offAB[i], gB[i] + (size_t)s * 64, 16);
        }
        CP_COMMIT();
    }

    int lrA = (lane & 7) | (lane & 8);
    int lkA8 = (lane >> 4) << 3;
    int lrB = (lane & 7) | ((lane & 16) >> 1);
    int lkB8 = lane & 8;

    for (int s = 0; s < K64; s++) {
        CP_WAIT(STAGES - 2);
        __syncthreads();
        uint32_t sa = sbase + (uint32_t)((s % STAGES) * 32768);
        uint32_t sb = sa + 16384u;

        #pragma unroll
        for (int kg = 0; kg < 4; kg++) {
            int lkA = kg * 16 + lkA8;
            int lkB = kg * 16 + lkB8;
            uint32_t areg[4][4];
            #pragma unroll
            for (int im = 0; im < 4; im++) {
                int r = wm * 64 + im * 16 + lrA;
                uint32_t addr = sa + (uint32_t)(r * 128 + (((lkA >> 3) ^ (r & 7)) << 4));
                LDMATRIX_X4(areg[im][0], areg[im][1], areg[im][2], areg[im][3], addr);
            }
            uint32_t breg[2][4];
            #pragma unroll
            for (int p = 0; p < 2; p++) {
                int r = wn * 32 + p * 16 + lrB;
                uint32_t addr = sb + (uint32_t)(r * 128 + (((lkB >> 3) ^ (r & 7)) << 4));
                LDMATRIX_X4(breg[p][0], breg[p][1], breg[p][2], breg[p][3], addr);
            }
            #pragma unroll
            for (int im = 0; im < 4; im++)
                #pragma unroll
                for (int jn = 0; jn < 4; jn++) {
                    int p = jn >> 1, q = (jn & 1) * 2;
                    mma_f16(acc[im][jn][0], acc[im][jn][1],
                            acc[im][jn][2], acc[im][jn][3],
                            areg[im][0], areg[im][1], areg[im][2], areg[im][3],
                            breg[p][q], breg[p][q + 1]);
                }
        }

        int sn = s + STAGES - 1;
        if (sn < K64) {
            uint32_t sa2 = sbase + (uint32_t)((sn % STAGES) * 32768);
            #pragma unroll
            for (int i = 0; i < 4; i++) {
                cp_async16(sa2 + offAB[i], gA[i] + (size_t)sn * 64, szA[i]);
                cp_async16(sa2 + 16384u + offAB[i], gB[i] + (size_t)sn * 64, 16);
            }
        }
        CP_COMMIT();
    }

    int egr = lane >> 2, egc = (lane & 3) * 2;
    #pragma unroll
    for (int im = 0; im < 4; im++) {
        #pragma unroll
        for (int half = 0; half < 2; half++) {
            int rg = row0 + wm * 64 + im * 16 + egr + half * 8;
            if (rg >= M) continue;
            #pragma unroll
            for (int jn = 0; jn < 4; jn++) {
                int cg = col0 + wn * 32 + jn * 8 + egc;
                float t0 = acc[im][jn][half * 2 + 0];
                float t1 = acc[im][jn][half * 2 + 1];
                if (bias) { t0 += bias[cg]; t1 += bias[cg + 1]; }
                if (act == ACT_GELU) { t0 = gelu_tanh(t0); t1 = gelu_tanh(t1); }
                if (res) {
                    t0 += res[(size_t)rg * N + cg];
                    t1 += res[(size_t)rg * N + cg + 1];
                }
                if (Ch) {
                    *(__half2*)(Ch + (size_t)rg * N + cg) = __floats2half2_rn(t0, t1);
                } else {
                    *(float2*)(Cf + (size_t)rg * N + cg) = make_float2(t0, t1);
                }
            }
        }
    }
}

// ----------------------------------------------------------------------------
// fp16 ldmatrix/mma flash attention (unchanged from round 9 — proven)
// ----------------------------------------------------------------------------
#define ATTN_SMEM (3 * 8192)

__global__ __launch_bounds__(128, 3)
void attn_h_kernel(const __half* __restrict__ Q, int qStride,
                   const __half* __restrict__ K, const __half* __restrict__ V,
                   int kStride, __half* __restrict__ O, int Lq, int Lk) {
    extern __shared__ char smc[];
    uint32_t sQ = smem_u32(smc);
    uint32_t sK = sQ + 8192;
    uint32_t sV = sQ + 16384;

    int tid = threadIdx.x, lane = tid & 31, w = tid >> 5;
    int gr = lane >> 2, lc = lane & 3;
    int qt = blockIdx.x, h = blockIdx.y, b = blockIdx.z;
    int wr = w * 16;
    const float scale = 0.125f;

    const __half* Qbase = Q + (size_t)(b * Lq + qt * 64) * qStride + h * 64;
    #pragma unroll
    for (int i = 0; i < 4; i++) {
        int idx = tid + i * 128;
        int r = idx >> 3, c8 = idx & 7;
        cp_async16(sQ + r * 128 + ((c8 ^ (r & 7)) << 4),
                   Qbase + (size_t)r * qStride + c8 * 8, 16);
    }
    CP_COMMIT();
    CP_WAIT(0);
    __syncthreads();

    int lrA = (lane & 7) | (lane & 8);
    int lkA8 = (lane >> 4) << 3;
    uint32_t qf[4][4];
    #pragma unroll
    for (int kg = 0; kg < 4; kg++) {
        int r = wr + lrA;
        int c = kg * 16 + lkA8;
        uint32_t addr = sQ + (uint32_t)(r * 128 + (((c >> 3) ^ (r & 7)) << 4));
        LDMATRIX_X4(qf[kg][0], qf[kg][1], qf[kg][2], qf[kg][3], addr);
    }

    float oacc[8][4];
    #pragma unroll
    for (int fn = 0; fn < 8; fn++)
        #pragma unroll
        for (int e = 0; e < 4; e++) oacc[fn][e] = 0.f;
    float mrow[2] = { -1e30f, -1e30f };
    float lrow[2] = { 0.f, 0.f };

    const __half* Kbase = K + (size_t)(b * Lk) * kStride + h * 64;
    const __half* Vbase = V + (size_t)(b * Lk) * kStride + h * 64;
    int nkt = (Lk + 63) >> 6;

    int lrB = (lane & 7) | ((lane & 16) >> 1);
    int lkB8 = lane & 8;
    int mV = lane >> 3;

    for (int kt = 0; kt < nkt; kt++) {
        #pragma unroll
        for (int i = 0; i < 4; i++) {
            int idx = tid + i * 128;
            int r = idx >> 3, c8 = idx & 7;
            int jg = kt * 64 + r;
            int sz = (jg < Lk) ? 16 : 0;
            uint32_t so = (uint32_t)(r * 128 + ((c8 ^ (r & 7)) << 4));
            cp_async16(sK + so, Kbase + (size_t)jg * kStride + c8 * 8, sz);
            cp_async16(sV + so, Vbase + (size_t)jg * kStride + c8 * 8, sz);
        }
        CP_COMMIT();
        CP_WAIT(0);
        __syncthreads();

        float sacc[8][4];
        #pragma unroll
        for (int fn = 0; fn < 8; fn++)
            #pragma unroll
            for (int e = 0; e < 4; e++) sacc[fn][e] = 0.f;
        #pragma unroll
        for (int kg = 0; kg < 4; kg++) {
            #pragma unroll
            for (int pp = 0; pp < 4; pp++) {
                int r = pp * 16 + lrB;
                int c = kg * 16 + lkB8;
                uint32_t addr = sK + (uint32_t)(r * 128 + (((c >> 3) ^ (r & 7)) << 4));
                uint32_t kb0, kb1, kb2, kb3;
                LDMATRIX_X4(kb0, kb1, kb2, kb3, addr);
                mma_f16(sacc[2 * pp][0], sacc[2 * pp][1], sacc[2 * pp][2], sacc[2 * pp][3],
                        qf[kg][0], qf[kg][1], qf[kg][2], qf[kg][3], kb0, kb1);
                mma_f16(sacc[2 * pp + 1][0], sacc[2 * pp + 1][1],
                        sacc[2 * pp + 1][2], sacc[2 * pp + 1][3],
                        qf[kg][0], qf[kg][1], qf[kg][2], qf[kg][3], kb2, kb3);
            }
        }
        #pragma unroll
        for (int fn = 0; fn < 8; fn++)
            #pragma unroll
            for (int e = 0; e < 4; e++) sacc[fn][e] *= scale;

        if (kt * 64 + 64 > Lk) {
            #pragma unroll
            for (int fn = 0; fn < 8; fn++) {
                int key0 = kt * 64 + fn * 8 + 2 * lc;
                if (key0 >= Lk)     { sacc[fn][0] = -1e30f; sacc[fn][2] = -1e30f; }
                if (key0 + 1 >= Lk) { sacc[fn][1] = -1e30f; sacc[fn][3] = -1e30f; }
            }
        }

        #pragma unroll
        for (int hr = 0; hr < 2; hr++) {
            float rm = -1e30f;
            #pragma unroll
            for (int fn = 0; fn < 8; fn++)
                rm = fmaxf(rm, fmaxf(sacc[fn][hr * 2], sacc[fn][hr * 2 + 1]));
            rm = fmaxf(rm, __shfl_xor_sync(0xffffffffu, rm, 1));
            rm = fmaxf(rm, __shfl_xor_sync(0xffffffffu, rm, 2));
            float mn = fmaxf(mrow[hr], rm);
            float rsum = 0.f;
            #pragma unroll
            for (int fn = 0; fn < 8; fn++) {
                float p0 = __expf(sacc[fn][hr * 2]     - mn);
                float p1 = __expf(sacc[fn][hr * 2 + 1] - mn);
                sacc[fn][hr * 2] = p0; sacc[fn][hr * 2 + 1] = p1;
                rsum += p0 + p1;
            }
            rsum += __shfl_xor_sync(0xffffffffu, rsum, 1);
            rsum += __shfl_xor_sync(0xffffffffu, rsum, 2);
            float alpha = __expf(mrow[hr] - mn);
            lrow[hr] = lrow[hr] * alpha + rsum;
            mrow[hr] = mn;
            #pragma unroll
            for (int fn = 0; fn < 8; fn++) {
                oacc[fn][hr * 2]     *= alpha;
                oacc[fn][hr * 2 + 1] *= alpha;
            }
        }

        uint32_t pf[4][4];
        #pragma unroll
        for (int kg = 0; kg < 4; kg++) {
            pf[kg][0] = pack_h2(sacc[2 * kg][0],     sacc[2 * kg][1]);
            pf[kg][1] = pack_h2(sacc[2 * kg][2],     sacc[2 * kg][3]);
            pf[kg][2] = pack_h2(sacc[2 * kg + 1][0], sacc[2 * kg + 1][1]);
            pf[kg][3] = pack_h2(sacc[2 * kg + 1][2], sacc[2 * kg + 1][3]);
        }

        #pragma unroll
        for (int kg = 0; kg < 4; kg++) {
            #pragma unroll
            for (int dn = 0; dn < 4; dn++) {
                int r = kg * 16 + (mV & 1) * 8 + (lane & 7);
                int c8 = dn * 2 + (mV >> 1);
                uint32_t addr = sV + (uint32_t)(r * 128 + ((c8 ^ (r & 7)) << 4));
                uint32_t vb0, vb1, vb2, vb3;
                LDMATRIX_X4_T(vb0, vb1, vb2, vb3, addr);
                mma_f16(oacc[2 * dn][0], oacc[2 * dn][1],
                        oacc[2 * dn][2], oacc[2 * dn][3],
                        pf[kg][0], pf[kg][1], pf[kg][2], pf[kg][3], vb0, vb1);
                mma_f16(oacc[2 * dn + 1][0], oacc[2 * dn + 1][1],
                        oacc[2 * dn + 1][2], oacc[2 * dn + 1][3],
                        pf[kg][0], pf[kg][1], pf[kg][2], pf[kg][3], vb2, vb3);
            }
        }
        __syncthreads();
    }

    __half* Obase = O + (size_t)(b * Lq + qt * 64) * Dx + h * 64;
    #pragma unroll
    for (int hr = 0; hr < 2; hr++) {
        float inv = 1.f / lrow[hr];
        int row = wr + gr + hr * 8;
        #pragma unroll
        for (int fn = 0; fn < 8; fn++) {
            *(__half2*)(Obase + (size_t)row * Dx + fn * 8 + 2 * lc) =
                __floats2half2_rn(oacc[fn][hr * 2] * inv, oacc[fn][hr * 2 + 1] * inv);
        }
    }
}

// ----------------------------------------------------------------------------
// launch
// ----------------------------------------------------------------------------
template <typename T>
static inline T* sym(const void* s) {
    void* p = nullptr;
    cudaGetSymbolAddress(&p, s);
    return (T*)p;
}

static inline void hgemm(const __half* A, const __half* BT, const float* bias,
                         const float* res, float* Cf, __half* Ch,
                         int M, int N, int K, int act) {
    dim3 grid(N / 128, (M + 127) / 128);
    h_mma_gemm<<<grid, 256, GEMM_SMEM>>>(A, BT, bias, res, Cf, Ch, M, N, K, act);
}

extern "C" void kernel_launch(void* const* d_in, const int* in_sizes, int n_in,
                              void* d_out, int out_size) {
    const float* x     = (const float*)d_in[0];
    const float* c     = (const float*)d_in[1];
    const float* text  = (const float*)d_in[2];
    const float* W_ada = (const float*)d_in[3];
    const float* b_ada = (const float*)d_in[4];
    const float* W_qkv = (const float*)d_in[5];
    const float* b_qkv = (const float*)d_in[6];
    const float* W_proj= (const float*)d_in[7];
    const float* b_proj= (const float*)d_in[8];
    const float* W_ctx = (const float*)d_in[9];
    const float* b_ctx = (const float*)d_in[10];
    const float* W_q   = (const float*)d_in[11];
    const float* W_k   = (const float*)d_in[12];
    const float* W_v   = (const float*)d_in[13];
    const float* W_out = (const float*)d_in[14];
    const float* b_out = (const float*)d_in[15];
    const float* W_fc1 = (const float*)d_in[16];
    const float* b_fc1 = (const float*)d_in[17];
    const float* W_fc2 = (const float*)d_in[18];
    const float* b_fc2 = (const float*)d_in[19];
    float* out = (float*)d_out;

    float*  mod   = sym<float>(g_mod);
    float*  x1    = sym<float>(g_x1);
    float*  x2    = sym<float>(g_x2);
    __half* h     = sym<__half>(g_h);
    __half* qkvh  = sym<__half>(g_qkv);
    __half* attnh = sym<__half>(g_attn_h);
    __half* q2h   = sym<__half>(g_q2);
    __half* k2v2h = sym<__half>(g_k2v2);
    __half* ctxh  = sym<__half>(g_ctx_h);
    __half* texth = sym<__half>(g_text_h);
    __half* hidh  = sym<__half>(g_hid_h);

    __half* Wqkv_t = sym<__half>(g_Wqkv_t);
    __half* Wproj_t= sym<__half>(g_Wproj_t);
    __half* Wctx_t = sym<__half>(g_Wctx_t);
    __half* Wq_t   = sym<__half>(g_Wq_t);
    __half* Wkv_t  = sym<__half>(g_Wkv_t);
    __half* Wout_t = sym<__half>(g_Wout_t);
    __half* Wfc1_t = sym<__half>(g_Wfc1_t);
    __half* Wfc2_t = sym<__half>(g_Wfc2_t);

    cudaFuncSetAttribute(attn_h_kernel, cudaFuncAttributeMaxDynamicSharedMemorySize,
                         ATTN_SMEM);
    cudaFuncSetAttribute(h_mma_gemm, cudaFuncAttributeMaxDynamicSharedMemorySize,
                         GEMM_SMEM);

    dim3 tb(32, 8);
    // launches 0-5 ordered so ncu (-s 5 -c 1) profiles the qkv GEMM
    transpose_h_kernel<<<dim3(3 * Dx / 32, Dx / 32), tb>>>(W_qkv, Wqkv_t, Dx, 3 * Dx); // 0
    ada_mod_kernel<<<dim3(24, 4), 256>>>(c, W_ada, b_ada, mod);                        // 1
    ln_mod_kernel<<<ROWS, 256>>>(x, mod, h, 0);                                        // 2
    transpose_h_kernel<<<dim3(Dx / 32, Dx / 32), tb>>>(W_proj, Wproj_t, Dx, Dx);       // 3
    transpose_h_kernel<<<dim3(4 * Dx / 32, Dx / 32), tb>>>(W_fc1, Wfc1_t, Dx, 4 * Dx); // 4
    hgemm(h, Wqkv_t, b_qkv, nullptr, nullptr, qkvh, ROWS, 3 * Dx, Dx, ACT_NONE);       // 5
    attn_h_kernel<<<dim3(Nx / 64, Hx, Bx), 128, ATTN_SMEM>>>(
        qkvh, 3 * Dx, qkvh + Dx, qkvh + 2 * Dx, 3 * Dx, attnh, Nx, Nx);
    hgemm(attnh, Wproj_t, b_proj, x, x1, nullptr, ROWS, Dx, Dx, ACT_NONE);

    // remaining weight transposes + text conversion
    transpose_h_kernel<<<dim3(Dx / 32, TDx / 32), tb>>>(W_ctx, Wctx_t, TDx, Dx);
    transpose_h_kernel<<<dim3(Dx / 32, Dx / 32), tb>>>(W_q, Wq_t, Dx, Dx);
    transpose_h_kernel<<<dim3(Dx / 32, Dx / 32), tb>>>(W_k, Wkv_t, Dx, Dx);
    transpose_h_kernel<<<dim3(Dx / 32, Dx / 32), tb>>>(W_v, Wkv_t + Dx * Dx, Dx, Dx);
    transpose_h_kernel<<<dim3(Dx / 32, Dx / 32), tb>>>(W_out, Wout_t, Dx, Dx);
    transpose_h_kernel<<<dim3(Dx / 32, 4 * Dx / 32), tb>>>(W_fc2, Wfc2_t, 4 * Dx, Dx);
    f2h_kernel<<<(CTXROWS * TDx + 255) / 256, 256>>>(text, texth, CTXROWS * TDx);

    // --- cross attention ---
    ln_mod_kernel<<<ROWS, 256>>>(x1, mod, h, 2);
    hgemm(texth, Wctx_t, b_ctx, nullptr, nullptr, ctxh, CTXROWS, Dx, TDx, ACT_NONE);
    hgemm(h, Wq_t, nullptr, nullptr, nullptr, q2h, ROWS, Dx, Dx, ACT_NONE);
    hgemm(ctxh, Wkv_t, nullptr, nullptr, nullptr, k2v2h, CTXROWS, 2 * Dx, Dx, ACT_NONE);
    attn_h_kernel<<<dim3(Nx / 64, Hx, Bx), 128, ATTN_SMEM>>>(
        q2h, Dx, k2v2h, k2v2h + Dx, 2 * Dx, attnh, Nx, TLx);
    hgemm(attnh, Wout_t, b_out, x1, x2, nullptr, ROWS, Dx, Dx, ACT_NONE);

    // --- MLP ---
    ln_mod_kernel<<<ROWS, 256>>>(x2, mod, h, 4);
    hgemm(h, Wfc1_t, b_fc1, nullptr, nullptr, hidh, ROWS, 4 * Dx, Dx, ACT_GELU);
    hgemm(hidh, Wfc2_t, b_fc2, x2, out, nullptr, ROWS, Dx, 4 * Dx, ACT_NONE);
}

// round 11
// speedup vs baseline: 7.6291x; 1.0551x over previous
#include <cuda_runtime.h>
#include <cuda_fp16.h>
#include <cstdint>
#include <math.h>

// ----------------------------------------------------------------------------
// DiT block: adaLN -> self-attn -> cross-attn -> MLP (GELU tanh)
// Round 11: templated BM GEMM (64 for small-M), double-buffered attention,
//           batched weight transposes.
// ----------------------------------------------------------------------------

#define Bx 4
#define Nx 1024
#define Dx 1024
#define Hx 16
#define HDx 64
#define TDx 768
#define TLx 77
#define ROWS (Bx * Nx)       // 4096
#define CTXROWS (Bx * TLx)   // 308

// fp32 scratch
__device__ float g_mod[Bx * 6 * Dx];
__device__ float g_x1[ROWS * Dx];
__device__ float g_x2[ROWS * Dx];
// half scratch
__device__ __half g_h[ROWS * Dx];
__device__ __half g_qkv[ROWS * 3 * Dx];
__device__ __half g_attn_h[ROWS * Dx];
__device__ __half g_q2[ROWS * Dx];
__device__ __half g_k2v2[CTXROWS * 2 * Dx];
__device__ __half g_ctx_h[CTXROWS * Dx];
__device__ __half g_text_h[CTXROWS * TDx];
__device__ __half g_hid_h[ROWS * 4 * Dx];
// transposed (K-major [N,K]) fp16 weights
__device__ __half g_Wqkv_t[3 * Dx * Dx];
__device__ __half g_Wproj_t[Dx * Dx];
__device__ __half g_Wctx_t[Dx * TDx];
__device__ __half g_Wq_t[Dx * Dx];
__device__ __half g_Wkv_t[2 * Dx * Dx];
__device__ __half g_Wout_t[Dx * Dx];
__device__ __half g_Wfc1_t[4 * Dx * Dx];
__device__ __half g_Wfc2_t[4 * Dx * Dx];

// ----------------------------------------------------------------------------
// helpers
// ----------------------------------------------------------------------------
__device__ __forceinline__ uint32_t smem_u32(const void* p) {
    uint32_t a;
    asm("{ .reg .u64 t; cvta.to.shared.u64 t, %1; cvt.u32.u64 %0, t; }"
        : "=r"(a) : "l"(p));
    return a;
}
__device__ __forceinline__ void cp_async16(uint32_t saddr, const void* gaddr, int szbytes) {
    asm volatile("cp.async.cg.shared.global [%0], [%1], 16, %2;"
                 :: "r"(saddr), "l"(gaddr), "r"(szbytes) : "memory");
}
#define CP_COMMIT() asm volatile("cp.async.commit_group;" ::: "memory")
#define CP_WAIT(n)  asm volatile("cp.async.wait_group %0;" :: "n"(n) : "memory")

#define LDMATRIX_X4(r0, r1, r2, r3, addr) \
    asm volatile("ldmatrix.sync.aligned.m8n8.x4.shared.b16 {%0,%1,%2,%3}, [%4];" \
                 : "=r"(r0), "=r"(r1), "=r"(r2), "=r"(r3) : "r"(addr))
#define LDMATRIX_X4_T(r0, r1, r2, r3, addr) \
    asm volatile("ldmatrix.sync.aligned.m8n8.x4.trans.shared.b16 {%0,%1,%2,%3}, [%4];" \
                 : "=r"(r0), "=r"(r1), "=r"(r2), "=r"(r3) : "r"(addr))

__device__ __forceinline__ void mma_f16(float& c0, float& c1, float& c2, float& c3,
                                        uint32_t a0, uint32_t a1, uint32_t a2, uint32_t a3,
                                        uint32_t b0, uint32_t b1) {
    asm volatile(
        "mma.sync.aligned.m16n8k16.row.col.f32.f16.f16.f32 "
        "{%0,%1,%2,%3}, {%4,%5,%6,%7}, {%8,%9}, {%0,%1,%2,%3};"
        : "+f"(c0), "+f"(c1), "+f"(c2), "+f"(c3)
        : "r"(a0), "r"(a1), "r"(a2), "r"(a3), "r"(b0), "r"(b1));
}
__device__ __forceinline__ uint32_t pack_h2(float lo, float hi) {
    __half2 h = __floats2half2_rn(lo, hi);
    return *(uint32_t*)&h;
}

// ----------------------------------------------------------------------------
// batched weight transpose: all 9 weights in one launch.
// Each 32x32 tile is one block; job lookup by tile base.
// ----------------------------------------------------------------------------
#define NTJOBS 9
struct TransJobs {
    const float* in[NTJOBS];
    __half* out[NTJOBS];
    int K[NTJOBS];
    int N[NTJOBS];
    int base[NTJOBS];   // first global tile index of this job
};

__global__ void transpose_batch_kernel(TransJobs jobs) {
    __shared__ float t[32][33];
    int bid = blockIdx.x;
    int j = 0;
    #pragma unroll
    for (int i = 1; i < NTJOBS; i++)
        if (bid >= jobs.base[i]) j = i;
    int tloc = bid - jobs.base[j];
    int K = jobs.K[j], N = jobs.N[j];
    int tiles_x = N >> 5;
    int n0 = (tloc % tiles_x) << 5;
    int k0 = (tloc / tiles_x) << 5;
    const float* in = jobs.in[j];
    __half* out = jobs.out[j];
    int tx = threadIdx.x, ty = threadIdx.y;
    #pragma unroll
    for (int i = 0; i < 32; i += 8)
        t[ty + i][tx] = in[(size_t)(k0 + ty + i) * N + n0 + tx];
    __syncthreads();
    #pragma unroll
    for (int i = 0; i < 32; i += 8)
        out[(size_t)(n0 + ty + i) * K + k0 + tx] = __float2half(t[tx][ty + i]);
}

__global__ void f2h_kernel(const float* __restrict__ in, __half* __restrict__ out, int n) {
    int i = blockIdx.x * 256 + threadIdx.x;
    if (i < n) out[i] = __float2half(in[i]);
}

// ----------------------------------------------------------------------------
// adaLN modulation
// ----------------------------------------------------------------------------
__global__ void ada_mod_kernel(const float* __restrict__ c,
                               const float* __restrict__ Wada,
                               const float* __restrict__ bada,
                               float* __restrict__ mod) {
    __shared__ float sc[Dx];
    int b = blockIdx.y;
    for (int i = threadIdx.x; i < Dx; i += 256) {
        float v = c[b * Dx + i];
        sc[i] = v / (1.f + __expf(-v));
    }
    __syncthreads();
    int n = blockIdx.x * 256 + threadIdx.x;
    float acc = 0.f;
    for (int k = 0; k < Dx; k++)
        acc += sc[k] * Wada[(size_t)k * (6 * Dx) + n];
    mod[b * 6 * Dx + n] = acc + bada[n];
}

// ----------------------------------------------------------------------------
// LayerNorm + modulate -> fp16
// ----------------------------------------------------------------------------
__global__ void ln_mod_kernel(const float* __restrict__ x,
                              const float* __restrict__ mod,
                              __half* __restrict__ out, int chunk) {
    int row = blockIdx.x;
    int b = row >> 10;
    int tid = threadIdx.x;
    const float* xr = x + (size_t)row * Dx;
    float4 v = *(const float4*)(xr + tid * 4);
    float s = v.x + v.y + v.z + v.w;
    float ss = v.x * v.x + v.y * v.y + v.z * v.z + v.w * v.w;
    #pragma unroll
    for (int off = 16; off; off >>= 1) {
        s  += __shfl_xor_sync(0xffffffffu, s, off);
        ss += __shfl_xor_sync(0xffffffffu, ss, off);
    }
    __shared__ float rs[8], rss[8];
    int wid = tid >> 5, lane = tid & 31;
    if (!lane) { rs[wid] = s; rss[wid] = ss; }
    __syncthreads();
    s = 0.f; ss = 0.f;
    #pragma unroll
    for (int w = 0; w < 8; w++) { s += rs[w]; ss += rss[w]; }
    float mean = s * (1.f / Dx);
    float var = ss * (1.f / Dx) - mean * mean;
    float inv = rsqrtf(var + 1e-6f);
    const float* sh = mod + (size_t)b * 6 * Dx + (size_t)chunk * Dx;
    const float* scl = sh + Dx;
    int d = tid * 4;
    float o0 = (v.x - mean) * inv * (1.f + scl[d + 0]) + sh[d + 0];
    float o1 = (v.y - mean) * inv * (1.f + scl[d + 1]) + sh[d + 1];
    float o2 = (v.z - mean) * inv * (1.f + scl[d + 2]) + sh[d + 2];
    float o3 = (v.w - mean) * inv * (1.f + scl[d + 3]) + sh[d + 3];
    __half2* op = (__half2*)(out + (size_t)row * Dx + d);
    op[0] = __floats2half2_rn(o0, o1);
    op[1] = __floats2half2_rn(o2, o3);
}

// ----------------------------------------------------------------------------
// fp16 mma.sync GEMM, cp.async 3-stage, templated M-tile (BM = 128 or 64).
// BMx128 tile, BK=64, 256 threads (8 warps, 2x4), warp tile (BM/2)x32.
// ----------------------------------------------------------------------------
#define ACT_NONE 0
#define ACT_GELU 1
#define STAGES 3

__device__ __forceinline__ float gelu_tanh(float x) {
    float x3 = x * x * x;
    return 0.5f * x * (1.f + tanhf(0.7978845608028654f * (x + 0.044715f * x3)));
}

template <int BM>
__global__ __launch_bounds__(256, 2)
void h_mma_gemm(const __half* __restrict__ A, const __half* __restrict__ BT,
                const float* __restrict__ bias, const float* __restrict__ res,
                float* __restrict__ Cf, __half* __restrict__ Ch,
                int M, int N, int K, int act) {
    constexpr int STAGE_BYTES = (BM + 128) * 128;
    constexpr int ACH = BM / 32;     // A 16B-chunks per thread (4 or 2)
    constexpr int IM = BM / 32;      // m16 fragments per warp (4 or 2)
    extern __shared__ char smem[];
    uint32_t sbase = smem_u32(smem);
    int tid = threadIdx.x, lane = tid & 31, wid = tid >> 5;
    int wm = wid >> 2, wn = wid & 3;
    int row0 = blockIdx.y * BM, col0 = blockIdx.x * 128;

    uint32_t offA[4], offB[4];
    const __half* gA[4];
    const __half* gB[4];
    int szA[4];
    #pragma unroll
    for (int i = 0; i < ACH; i++) {
        int idx = tid + i * 256;             // 0..BM*8-1
        int r = idx >> 3, c8 = idx & 7;
        offA[i] = (uint32_t)(r * 128 + ((c8 ^ (r & 7)) << 4));
        szA[i] = (row0 + r) < M ? 16 : 0;
        gA[i] = A + (size_t)(row0 + r) * K + c8 * 8;
    }
    #pragma unroll
    for (int i = 0; i < 4; i++) {
        int idx = tid + i * 256;             // 0..1023
        int r = idx >> 3, c8 = idx & 7;
        offB[i] = (uint32_t)(BM * 128 + r * 128 + ((c8 ^ (r & 7)) << 4));
        gB[i] = BT + (size_t)(col0 + r) * K + c8 * 8;
    }

    float acc[IM][4][4];
    #pragma unroll
    for (int im = 0; im < IM; im++)
        #pragma unroll
        for (int jn = 0; jn < 4; jn++)
            #pragma unroll
            for (int e = 0; e < 4; e++) acc[im][jn][e] = 0.f;

    int K64 = K >> 6;

    #pragma unroll
    for (int s = 0; s < STAGES - 1; s++) {
        uint32_t sa = sbase + (uint32_t)(s * STAGE_BYTES);
        #pragma unroll
        for (int i = 0; i < ACH; i++)
            cp_async16(sa + offA[i], gA[i] + (size_t)s * 64, szA[i]);
        #pragma unroll
        for (int i = 0; i < 4; i++)
            cp_async16(sa + offB[i], gB[i] + (size_t)s * 64, 16);
        CP_COMMIT();
    }

    int lrA = (lane & 7) | (lane & 8);
    int lkA8 = (lane >> 4) << 3;
    int lrB = (lane & 7) | ((lane & 16) >> 1);
    int lkB8 = lane & 8;

    for (int s = 0; s < K64; s++) {
        CP_WAIT(STAGES - 2);
        __syncthreads();
        uint32_t sa = sbase + (uint32_t)((s % STAGES) * STAGE_BYTES);
        uint32_t sb = sa + (uint32_t)(BM * 128);

        #pragma unroll
        for (int kg = 0; kg < 4; kg++) {
            int lkA = kg * 16 + lkA8;
            int lkB = kg * 16 + lkB8;
            uint32_t areg[IM][4];
            #pragma unroll
            for (int im = 0; im < IM; im++) {
                int r = wm * (BM / 2) + im * 16 + lrA;
                uint32_t addr = sa + (uint32_t)(r * 128 + (((lkA >> 3) ^ (r & 7)) << 4));
                LDMATRIX_X4(areg[im][0], areg[im][1], areg[im][2], areg[im][3], addr);
            }
            uint32_t breg[2][4];
            #pragma unroll
            for (int p = 0; p < 2; p++) {
                int r = wn * 32 + p * 16 + lrB;
                uint32_t addr = sb + (uint32_t)(r * 128 + (((lkB >> 3) ^ (r & 7)) << 4));
                LDMATRIX_X4(breg[p][0], breg[p][1], breg[p][2], breg[p][3], addr);
            }
            #pragma unroll
            for (int im = 0; im < IM; im++)
                #pragma unroll
                for (int jn = 0; jn < 4; jn++) {
                    int p = jn >> 1, q = (jn & 1) * 2;
                    mma_f16(acc[im][jn][0], acc[im][jn][1],
                            acc[im][jn][2], acc[im][jn][3],
                            areg[im][0], areg[im][1], areg[im][2], areg[im][3],
                            breg[p][q], breg[p][q + 1]);
                }
        }

        int sn = s + STAGES - 1;
        if (sn < K64) {
            uint32_t sa2 = sbase + (uint32_t)((sn % STAGES) * STAGE_BYTES);
            #pragma unroll
            for (int i = 0; i < ACH; i++)
                cp_async16(sa2 + offA[i], gA[i] + (size_t)sn * 64, szA[i]);
            #pragma unroll
            for (int i = 0; i < 4; i++)
                cp_async16(sa2 + offB[i], gB[i] + (size_t)sn * 64, 16);
        }
        CP_COMMIT();
    }

    int egr = lane >> 2, egc = (lane & 3) * 2;
    #pragma unroll
    for (int im = 0; im < IM; im++) {
        #pragma unroll
        for (int half = 0; half < 2; half++) {
            int rg = row0 + wm * (BM / 2) + im * 16 + egr + half * 8;
            if (rg >= M) continue;
            #pragma unroll
            for (int jn = 0; jn < 4; jn++) {
                int cg = col0 + wn * 32 + jn * 8 + egc;
                float t0 = acc[im][jn][half * 2 + 0];
                float t1 = acc[im][jn][half * 2 + 1];
                if (bias) { t0 += bias[cg]; t1 += bias[cg + 1]; }
                if (act == ACT_GELU) { t0 = gelu_tanh(t0); t1 = gelu_tanh(t1); }
                if (res) {
                    t0 += res[(size_t)rg * N + cg];
                    t1 += res[(size_t)rg * N + cg + 1];
                }
                if (Ch) {
                    *(__half2*)(Ch + (size_t)rg * N + cg) = __floats2half2_rn(t0, t1);
                } else {
                    *(float2*)(Cf + (size_t)rg * N + cg) = make_float2(t0, t1);
                }
            }
        }
    }
}

#define GEMM_SMEM_128 (STAGES * (128 + 128) * 128)
#define GEMM_SMEM_64  (STAGES * (64 + 128) * 128)

// ----------------------------------------------------------------------------
// fp16 ldmatrix/mma flash attention, double-buffered K/V.
// smem: sQ 8KB | stage0 (K 8K, V 8K) | stage1 (K 8K, V 8K) = 40KB.
// ----------------------------------------------------------------------------
#define ATTN_SMEM (8192 + 2 * 16384)

__global__ __launch_bounds__(128, 3)
void attn_h_kernel(const __half* __restrict__ Q, int qStride,
                   const __half* __restrict__ K, const __half* __restrict__ V,
                   int kStride, __half* __restrict__ O, int Lq, int Lk) {
    extern __shared__ char smc[];
    uint32_t sQ = smem_u32(smc);

    int tid = threadIdx.x, lane = tid & 31, w = tid >> 5;
    int gr = lane >> 2, lc = lane & 3;
    int qt = blockIdx.x, h = blockIdx.y, b = blockIdx.z;
    int wr = w * 16;
    const float scale = 0.125f;

    const __half* Kbase = K + (size_t)(b * Lk) * kStride + h * 64;
    const __half* Vbase = V + (size_t)(b * Lk) * kStride + h * 64;
    int nkt = (Lk + 63) >> 6;

    // prologue: Q tile + K/V tile 0, one commit group
    const __half* Qbase = Q + (size_t)(b * Lq + qt * 64) * qStride + h * 64;
    #pragma unroll
    for (int i = 0; i < 4; i++) {
        int idx = tid + i * 128;
        int r = idx >> 3, c8 = idx & 7;
        cp_async16(sQ + r * 128 + ((c8 ^ (r & 7)) << 4),
                   Qbase + (size_t)r * qStride + c8 * 8, 16);
    }
    {
        uint32_t sK0 = sQ + 8192;
        uint32_t sV0 = sK0 + 8192;
        #pragma unroll
        for (int i = 0; i < 4; i++) {
            int idx = tid + i * 128;
            int r = idx >> 3, c8 = idx & 7;
            int jg = r;                     // kt = 0
            int sz = (jg < Lk) ? 16 : 0;
            uint32_t so = (uint32_t)(r * 128 + ((c8 ^ (r & 7)) << 4));
            cp_async16(sK0 + so, Kbase + (size_t)jg * kStride + c8 * 8, sz);
            cp_async16(sV0 + so, Vbase + (size_t)jg * kStride + c8 * 8, sz);
        }
    }
    CP_COMMIT();

    int lrA = (lane & 7) | (lane & 8);
    int lkA8 = (lane >> 4) << 3;
    int lrB = (lane & 7) | ((lane & 16) >> 1);
    int lkB8 = lane & 8;
    int mV = lane >> 3;

    uint32_t qf[4][4];
    float oacc[8][4];
    #pragma unroll
    for (int fn = 0; fn < 8; fn++)
        #pragma unroll
        for (int e = 0; e < 4; e++) oacc[fn][e] = 0.f;
    float mrow[2] = { -1e30f, -1e30f };
    float lrow[2] = { 0.f, 0.f };

    for (int kt = 0; kt < nkt; kt++) {
        CP_WAIT(0);
        __syncthreads();
        int st = kt & 1;
        uint32_t sK = sQ + 8192 + (uint32_t)(st * 16384);
        uint32_t sV = sK + 8192;

        // issue next tile into the other buffer (overlaps with compute below)
        if (kt + 1 < nkt) {
            uint32_t sK1 = sQ + 8192 + (uint32_t)((1 - st) * 16384);
            uint32_t sV1 = sK1 + 8192;
            #pragma unroll
            for (int i = 0; i < 4; i++) {
                int idx = tid + i * 128;
                int r = idx >> 3, c8 = idx & 7;
                int jg = (kt + 1) * 64 + r;
                int sz = (jg < Lk) ? 16 : 0;
                uint32_t so = (uint32_t)(r * 128 + ((c8 ^ (r & 7)) << 4));
                cp_async16(sK1 + so, Kbase + (size_t)jg * kStride + c8 * 8, sz);
                cp_async16(sV1 + so, Vbase + (size_t)jg * kStride + c8 * 8, sz);
            }
        }
        CP_COMMIT();

        if (kt == 0) {
            // build Q fragments once (sQ is ready after first wait)
            #pragma unroll
            for (int kg = 0; kg < 4; kg++) {
                int r = wr + lrA;
                int c = kg * 16 + lkA8;
                uint32_t addr = sQ + (uint32_t)(r * 128 + (((c >> 3) ^ (r & 7)) << 4));
                LDMATRIX_X4(qf[kg][0], qf[kg][1], qf[kg][2], qf[kg][3], addr);
            }
        }

        // ---- S = Q @ K^T ----
        float sacc[8][4];
        #pragma unroll
        for (int fn = 0; fn < 8; fn++)
            #pragma unroll
            for (int e = 0; e < 4; e++) sacc[fn][e] = 0.f;
        #pragma unroll
        for (int kg = 0; kg < 4; kg++) {
            #pragma unroll
            for (int pp = 0; pp < 4; pp++) {
                int r = pp * 16 + lrB;
                int c = kg * 16 + lkB8;
                uint32_t addr = sK + (uint32_t)(r * 128 + (((c >> 3) ^ (r & 7)) << 4));
                uint32_t kb0, kb1, kb2, kb3;
                LDMATRIX_X4(kb0, kb1, kb2, kb3, addr);
                mma_f16(sacc[2 * pp][0], sacc[2 * pp][1], sacc[2 * pp][2], sacc[2 * pp][3],
                        qf[kg][0], qf[kg][1], qf[kg][2], qf[kg][3], kb0, kb1);
                mma_f16(sacc[2 * pp + 1][0], sacc[2 * pp + 1][1],
                        sacc[2 * pp + 1][2], sacc[2 * pp + 1][3],
                        qf[kg][0], qf[kg][1], qf[kg][2], qf[kg][3], kb2, kb3);
            }
        }
        #pragma unroll
        for (int fn = 0; fn < 8; fn++)
            #pragma unroll
            for (int e = 0; e < 4; e++) sacc[fn][e] *= scale;

        if (kt * 64 + 64 > Lk) {
            #pragma unroll
            for (int fn = 0; fn < 8; fn++) {
                int key0 = kt * 64 + fn * 8 + 2 * lc;
                if (key0 >= Lk)     { sacc[fn][0] = -1e30f; sacc[fn][2] = -1e30f; }
                if (key0 + 1 >= Lk) { sacc[fn][1] = -1e30f; sacc[fn][3] = -1e30f; }
            }
        }

        // ---- online softmax ----
        #pragma unroll
        for (int hr = 0; hr < 2; hr++) {
            float rm = -1e30f;
            #pragma unroll
            for (int fn = 0; fn < 8; fn++)
                rm = fmaxf(rm, fmaxf(sacc[fn][hr * 2], sacc[fn][hr * 2 + 1]));
            rm = fmaxf(rm, __shfl_xor_sync(0xffffffffu, rm, 1));
            rm = fmaxf(rm, __shfl_xor_sync(0xffffffffu, rm, 2));
            float mn = fmaxf(mrow[hr], rm);
            float rsum = 0.f;
            #pragma unroll
            for (int fn = 0; fn < 8; fn++) {
                float p0 = __expf(sacc[fn][hr * 2]     - mn);
                float p1 = __expf(sacc[fn][hr * 2 + 1] - mn);
                sacc[fn][hr * 2] = p0; sacc[fn][hr * 2 + 1] = p1;
                rsum += p0 + p1;
            }
            rsum += __shfl_xor_sync(0xffffffffu, rsum, 1);
            rsum += __shfl_xor_sync(0xffffffffu, rsum, 2);
            float alpha = __expf(mrow[hr] - mn);
            lrow[hr] = lrow[hr] * alpha + rsum;
            mrow[hr] = mn;
            #pragma unroll
            for (int fn = 0; fn < 8; fn++) {
                oacc[fn][hr * 2]     *= alpha;
                oacc[fn][hr * 2 + 1] *= alpha;
            }
        }

        // ---- P fragments (register repack) ----
        uint32_t pf[4][4];
        #pragma unroll
        for (int kg = 0; kg < 4; kg++) {
            pf[kg][0] = pack_h2(sacc[2 * kg][0],     sacc[2 * kg][1]);
            pf[kg][1] = pack_h2(sacc[2 * kg][2],     sacc[2 * kg][3]);
            pf[kg][2] = pack_h2(sacc[2 * kg + 1][0], sacc[2 * kg + 1][1]);
            pf[kg][3] = pack_h2(sacc[2 * kg + 1][2], sacc[2 * kg + 1][3]);
        }

        // ---- O += P @ V ----
        #pragma unroll
        for (int kg = 0; kg < 4; kg++) {
            #pragma unroll
            for (int dn = 0; dn < 4; dn++) {
                int r = kg * 16 + (mV & 1) * 8 + (lane & 7);
                int c8 = dn * 2 + (mV >> 1);
                uint32_t addr = sV + (uint32_t)(r * 128 + ((c8 ^ (r & 7)) << 4));
                uint32_t vb0, vb1, vb2, vb3;
                LDMATRIX_X4_T(vb0, vb1, vb2, vb3, addr);
                mma_f16(oacc[2 * dn][0], oacc[2 * dn][1],
                        oacc[2 * dn][2], oacc[2 * dn][3],
                        pf[kg][0], pf[kg][1], pf[kg][2], pf[kg][3], vb0, vb1);
                mma_f16(oacc[2 * dn + 1][0], oacc[2 * dn + 1][1],
                        oacc[2 * dn + 1][2], oacc[2 * dn + 1][3],
                        pf[kg][0], pf[kg][1], pf[kg][2], pf[kg][3], vb2, vb3);
            }
        }
        __syncthreads();   // all warps done with this stage before it is reloaded
    }

    __half* Obase = O + (size_t)(b * Lq + qt * 64) * Dx + h * 64;
    #pragma unroll
    for (int hr = 0; hr < 2; hr++) {
        float inv = 1.f / lrow[hr];
        int row = wr + gr + hr * 8;
        #pragma unroll
        for (int fn = 0; fn < 8; fn++) {
            *(__half2*)(Obase + (size_t)row * Dx + fn * 8 + 2 * lc) =
                __floats2half2_rn(oacc[fn][hr * 2] * inv, oacc[fn][hr * 2 + 1] * inv);
        }
    }
}

// ----------------------------------------------------------------------------
// launch
// ----------------------------------------------------------------------------
template <typename T>
static inline T* sym(const void* s) {
    void* p = nullptr;
    cudaGetSymbolAddress(&p, s);
    return (T*)p;
}

static inline void hgemm(const __half* A, const __half* BT, const float* bias,
                         const float* res, float* Cf, __half* Ch,
                         int M, int N, int K, int act) {
    int ctas128 = (N / 128) * ((M + 127) / 128);
    if (ctas128 >= 148) {
        dim3 grid(N / 128, (M + 127) / 128);
        h_mma_gemm<128><<<grid, 256, GEMM_SMEM_128>>>(A, BT, bias, res, Cf, Ch, M, N, K, act);
    } else {
        dim3 grid(N / 128, (M + 63) / 64);
        h_mma_gemm<64><<<grid, 256, GEMM_SMEM_64>>>(A, BT, bias, res, Cf, Ch, M, N, K, act);
    }
}

extern "C" void kernel_launch(void* const* d_in, const int* in_sizes, int n_in,
                              void* d_out, int out_size) {
    const float* x     = (const float*)d_in[0];
    const float* c     = (const float*)d_in[1];
    const float* text  = (const float*)d_in[2];
    const float* W_ada = (const float*)d_in[3];
    const float* b_ada = (const float*)d_in[4];
    const float* W_qkv = (const float*)d_in[5];
    const float* b_qkv = (const float*)d_in[6];
    const float* W_proj= (const float*)d_in[7];
    const float* b_proj= (const float*)d_in[8];
    const float* W_ctx = (const float*)d_in[9];
    const float* b_ctx = (const float*)d_in[10];
    const float* W_q   = (const float*)d_in[11];
    const float* W_k   = (const float*)d_in[12];
    const float* W_v   = (const float*)d_in[13];
    const float* W_out = (const float*)d_in[14];
    const float* b_out = (const float*)d_in[15];
    const float* W_fc1 = (const float*)d_in[16];
    const float* b_fc1 = (const float*)d_in[17];
    const float* W_fc2 = (const float*)d_in[18];
    const float* b_fc2 = (const float*)d_in[19];
    float* out = (float*)d_out;

    float*  mod   = sym<float>(g_mod);
    float*  x1    = sym<float>(g_x1);
    float*  x2    = sym<float>(g_x2);
    __half* h     = sym<__half>(g_h);
    __half* qkvh  = sym<__half>(g_qkv);
    __half* attnh = sym<__half>(g_attn_h);
    __half* q2h   = sym<__half>(g_q2);
    __half* k2v2h = sym<__half>(g_k2v2);
    __half* ctxh  = sym<__half>(g_ctx_h);
    __half* texth = sym<__half>(g_text_h);
    __half* hidh  = sym<__half>(g_hid_h);

    __half* Wqkv_t = sym<__half>(g_Wqkv_t);
    __half* Wproj_t= sym<__half>(g_Wproj_t);
    __half* Wctx_t = sym<__half>(g_Wctx_t);
    __half* Wq_t   = sym<__half>(g_Wq_t);
    __half* Wkv_t  = sym<__half>(g_Wkv_t);
    __half* Wout_t = sym<__half>(g_Wout_t);
    __half* Wfc1_t = sym<__half>(g_Wfc1_t);
    __half* Wfc2_t = sym<__half>(g_Wfc2_t);

    cudaFuncSetAttribute(attn_h_kernel, cudaFuncAttributeMaxDynamicSharedMemorySize,
                         ATTN_SMEM);
    cudaFuncSetAttribute(h_mma_gemm<128>, cudaFuncAttributeMaxDynamicSharedMemorySize,
                         GEMM_SMEM_128);
    cudaFuncSetAttribute(h_mma_gemm<64>, cudaFuncAttributeMaxDynamicSharedMemorySize,
                         GEMM_SMEM_64);

    // ---- batched weight transpose (one launch) ----
    TransJobs tj;
    const float* tin[NTJOBS] = { W_qkv, W_proj, W_fc1, W_ctx, W_q, W_k, W_v, W_out, W_fc2 };
    __half* tout[NTJOBS] = { Wqkv_t, Wproj_t, Wfc1_t, Wctx_t, Wq_t, Wkv_t,
                             Wkv_t + Dx * Dx, Wout_t, Wfc2_t };
    int tK[NTJOBS] = { Dx, Dx, Dx, TDx, Dx, Dx, Dx, Dx, 4 * Dx };
    int tN[NTJOBS] = { 3 * Dx, Dx, 4 * Dx, Dx, Dx, Dx, Dx, Dx, Dx };
    int total = 0;
    for (int j = 0; j < NTJOBS; j++) {
        tj.in[j] = tin[j]; tj.out[j] = tout[j];
        tj.K[j] = tK[j]; tj.N[j] = tN[j];
        tj.base[j] = total;
        total += (tN[j] >> 5) * (tK[j] >> 5);
    }

    dim3 tb(32, 8);
    transpose_batch_kernel<<<total, tb>>>(tj);                                   // 0
    ada_mod_kernel<<<dim3(24, 4), 256>>>(c, W_ada, b_ada, mod);                  // 1
    ln_mod_kernel<<<ROWS, 256>>>(x, mod, h, 0);                                  // 2
    f2h_kernel<<<(CTXROWS * TDx + 255) / 256, 256>>>(text, texth, CTXROWS * TDx);// 3
    hgemm(h, Wqkv_t, b_qkv, nullptr, nullptr, qkvh, ROWS, 3 * Dx, Dx, ACT_NONE); // 4
    attn_h_kernel<<<dim3(Nx / 64, Hx, Bx), 128, ATTN_SMEM>>>(                    // 5 (ncu)
        qkvh, 3 * Dx, qkvh + Dx, qkvh + 2 * Dx, 3 * Dx, attnh, Nx, Nx);
    hgemm(attnh, Wproj_t, b_proj, x, x1, nullptr, ROWS, Dx, Dx, ACT_NONE);

    // --- cross attention ---
    ln_mod_kernel<<<ROWS, 256>>>(x1, mod, h, 2);
    hgemm(texth, Wctx_t, b_ctx, nullptr, nullptr, ctxh, CTXROWS, Dx, TDx, ACT_NONE);
    hgemm(h, Wq_t, nullptr, nullptr, nullptr, q2h, ROWS, Dx, Dx, ACT_NONE);
    hgemm(ctxh, Wkv_t, nullptr, nullptr, nullptr, k2v2h, CTXROWS, 2 * Dx, Dx, ACT_NONE);
    attn_h_kernel<<<dim3(Nx / 64, Hx, Bx), 128, ATTN_SMEM>>>(
        q2h, Dx, k2v2h, k2v2h + Dx, 2 * Dx, attnh, Nx, TLx);
    hgemm(attnh, Wout_t, b_out, x1, x2, nullptr, ROWS, Dx, Dx, ACT_NONE);

    // --- MLP ---
    ln_mod_kernel<<<ROWS, 256>>>(x2, mod, h, 4);
    hgemm(h, Wfc1_t, b_fc1, nullptr, nullptr, hidh, ROWS, 4 * Dx, Dx, ACT_GELU);
    hgemm(hidh, Wfc2_t, b_fc2, x2, out, nullptr, ROWS, Dx, 4 * Dx, ACT_NONE);
}